// round 3
// baseline (speedup 1.0000x reference)
#include <cuda_runtime.h>
#include <cuda_bf16.h>
#include <cstdint>

#define BATCH 2
#define SEQ   2048
#define HID   512
#define HEADS 8
#define HDIM  64
#define MAN   256
#define DM    512            // 2*MAN  (re || im)
#define NROWS (BATCH*SEQ)    // 4096
#define BH    (BATCH*HEADS)  // 16
#define SCALE 0.125f         // 64^-0.5

// ---------------- scratch (device globals; no allocations) ----------------
__device__ float g_xn[NROWS * HID];
__device__ float g_q_re[NROWS * HID];
__device__ float g_q_im[NROWS * HID];
__device__ float g_k_re[NROWS * HID];
__device__ float g_k_im[NROWS * HID];
__device__ float g_v_re[NROWS * HID];
__device__ float g_v_im[NROWS * HID];
__device__ float g_Qp[(size_t)BH * SEQ * DM];
__device__ float g_Kp[(size_t)BH * SEQ * DM];
__device__ float g_Vp[(size_t)BH * SEQ * DM];
__device__ float g_Op[(size_t)BH * SEQ * DM];
__device__ float g_oh_re[NROWS * HID];
__device__ float g_oh_im[NROWS * HID];
__device__ float g_S[(size_t)BH * SEQ * SEQ];   // 268 MB score/prob scratch

#define MAXB 16
struct PtrBatch {
    const float* A[MAXB];
    const float* B[MAXB];
    float*       C[MAXB];
};

// ---------------- helpers ----------------
__device__ __forceinline__ float to_tf32(float x) {
    asm("cvt.rna.tf32.f32 %0, %1;" : "=f"(x) : "f"(x));
    return x;
}
__device__ __forceinline__ uint32_t f2u(float x) { return __float_as_uint(x); }

__device__ __forceinline__ void mma_tf32(float c[4], const uint32_t a[4], const uint32_t b[2]) {
    asm volatile(
        "mma.sync.aligned.m16n8k8.row.col.f32.tf32.tf32.f32 "
        "{%0,%1,%2,%3},{%4,%5,%6,%7},{%8,%9},{%0,%1,%2,%3};"
        : "+f"(c[0]), "+f"(c[1]), "+f"(c[2]), "+f"(c[3])
        : "r"(a[0]), "r"(a[1]), "r"(a[2]), "r"(a[3]), "r"(b[0]), "r"(b[1]));
}

// ---------------- row L2-normalize ----------------
__global__ void norm_kernel(const float* __restrict__ x, float* __restrict__ xn) {
    int row = blockIdx.x;
    int t = threadIdx.x;
    const float4* xr = (const float4*)(x + (size_t)row * HID);
    float4 v = xr[t];
    float ss = v.x*v.x + v.y*v.y + v.z*v.z + v.w*v.w;
    #pragma unroll
    for (int o = 16; o > 0; o >>= 1) ss += __shfl_xor_sync(0xffffffffu, ss, o);
    __shared__ float ws[4];
    if ((t & 31) == 0) ws[t >> 5] = ss;
    __syncthreads();
    float tot = ws[0] + ws[1] + ws[2] + ws[3];
    float inv = 1.0f / sqrtf(tot);
    v.x *= inv; v.y *= inv; v.z *= inv; v.w *= inv;
    ((float4*)(xn + (size_t)row * HID))[t] = v;
}

// ---------------- tf32 tensor-core GEMM v2 ----------------
// 128x128 tile, BK=16, 256 threads (8 warps, 2x4, 64x32 warp tiles).
// k-permuted + XOR-swizzled smem: frag loads are LDS.128, conflict-free.
// Double-buffered smem: one __syncthreads per k-tile.
// TWO=1: C = A1@B1 + s2*A2@B2 (pb.A/B[2z],[2z+1]), K each.
template<int TRANSB, int TWO>
__global__ __launch_bounds__(256)
void gemm_tf32(PtrBatch pb, int M, int N, int K,
               int ldc, int cstride, float sign, float s2a, float s2b) {
    __shared__ alignas(16) float As[2][128 * 16];
    __shared__ alignas(16) float Bs[2][128 * 16];

    const int tid = threadIdx.x;
    const int bz = blockIdx.z;
    const float *A1, *B1, *A2 = nullptr, *B2 = nullptr;
    float* C;
    float s2 = 1.f;
    if (TWO) {
        A1 = pb.A[2*bz]; B1 = pb.B[2*bz];
        A2 = pb.A[2*bz+1]; B2 = pb.B[2*bz+1];
        C = pb.C[bz];
        s2 = bz ? s2b : s2a;
    } else {
        A1 = pb.A[bz]; B1 = pb.B[bz]; C = pb.C[bz];
    }
    const int row0 = blockIdx.y * 128;
    const int col0 = blockIdx.x * 128;
    const int warp = tid >> 5, lane = tid & 31;
    const int wm = (warp & 1) * 64;
    const int wn = (warp >> 1) * 32;
    const int g = lane >> 2, tig = lane & 3;

    float c[4][4][4] = {};
    float4 ra[2], rb[2];
    float stage_sc = 1.f;

    const int nk = TWO ? 2 * K : K;

    auto load_stage = [&](int kt) {
        int p = TWO && (kt >= K);
        const float* Ap = p ? A2 : A1;
        const float* Bp = p ? B2 : B1;
        int kk = kt - (p ? K : 0);
        stage_sc = p ? s2 : 1.f;
        #pragma unroll
        for (int i = 0; i < 2; i++) {
            int idx = tid + i * 256;
            int r = idx >> 2, kq = idx & 3;
            ra[i] = *(const float4*)(Ap + (size_t)(row0 + r) * K + kk + kq * 4);
        }
        if (TRANSB) {
            #pragma unroll
            for (int i = 0; i < 2; i++) {
                int idx = tid + i * 256;
                int n = idx >> 2, kq = idx & 3;
                rb[i] = *(const float4*)(Bp + (size_t)(col0 + n) * K + kk + kq * 4);
            }
        } else {
            #pragma unroll
            for (int i = 0; i < 2; i++) {
                int idx = tid + i * 256;
                int q = idx & 3, r = (idx >> 2) & 15, nqh = idx >> 6;
                rb[i] = *(const float4*)(Bp + (size_t)(kk + r) * N + col0 + (nqh * 4 + q) * 4);
            }
        }
    };

    auto commit = [&](int s) {
        float sc = stage_sc;
        // A: element (r, k_local = kq*4+d) -> k' chunk d, word kq; chunk XOR (r&3)
        #pragma unroll
        for (int i = 0; i < 2; i++) {
            int idx = tid + i * 256;
            int r = idx >> 2, kq = idx & 3;
            float* dst = &As[s][r * 16];
            int sw = r & 3;
            dst[((0 ^ sw) << 2) | kq] = to_tf32(ra[i].x);
            dst[((1 ^ sw) << 2) | kq] = to_tf32(ra[i].y);
            dst[((2 ^ sw) << 2) | kq] = to_tf32(ra[i].z);
            dst[((3 ^ sw) << 2) | kq] = to_tf32(ra[i].w);
        }
        if (TRANSB) {
            #pragma unroll
            for (int i = 0; i < 2; i++) {
                int idx = tid + i * 256;
                int n = idx >> 2, kq = idx & 3;
                float* dst = &Bs[s][n * 16];
                int sw = n & 3;
                dst[((0 ^ sw) << 2) | kq] = to_tf32(rb[i].x * sc);
                dst[((1 ^ sw) << 2) | kq] = to_tf32(rb[i].y * sc);
                dst[((2 ^ sw) << 2) | kq] = to_tf32(rb[i].z * sc);
                dst[((3 ^ sw) << 2) | kq] = to_tf32(rb[i].w * sc);
            }
        } else {
            #pragma unroll
            for (int i = 0; i < 2; i++) {
                int idx = tid + i * 256;
                int q = idx & 3, r = (idx >> 2) & 15, nqh = idx >> 6;
                int cch = r & 3, w = r >> 2;     // k' = cch*4 + w
                float v[4] = {rb[i].x, rb[i].y, rb[i].z, rb[i].w};
                #pragma unroll
                for (int d = 0; d < 4; d++) {
                    int n = (nqh * 4 + q) * 4 + d;
                    Bs[s][n * 16 + (((cch ^ (n & 3)) << 2) | w)] = to_tf32(v[d] * sc);
                }
            }
        }
    };

    load_stage(0);
    int s = 0;
    for (int kt = 0; kt < nk; kt += 16) {
        commit(s);
        __syncthreads();
        if (kt + 16 < nk) load_stage(kt + 16);

        const float* AsS = As[s];
        const float* BsS = Bs[s];
        float4 bfr[4];
        #pragma unroll
        for (int ni = 0; ni < 4; ni++) {
            int n = wn + ni * 8 + g;
            bfr[ni] = *(const float4*)(BsS + n * 16 + ((tig ^ (n & 3)) << 2));
        }
        #pragma unroll
        for (int mi = 0; mi < 4; mi++) {
            int m = wm + mi * 16 + g;
            float4 alo = *(const float4*)(AsS + m * 16 + ((tig ^ (m & 3)) << 2));
            float4 ahi = *(const float4*)(AsS + (m + 8) * 16 + ((tig ^ (m & 3)) << 2));
            uint32_t a0[4] = {f2u(alo.x), f2u(ahi.x), f2u(alo.y), f2u(ahi.y)};
            uint32_t a1[4] = {f2u(alo.z), f2u(ahi.z), f2u(alo.w), f2u(ahi.w)};
            #pragma unroll
            for (int ni = 0; ni < 4; ni++) {
                uint32_t b0[2] = {f2u(bfr[ni].x), f2u(bfr[ni].y)};
                uint32_t b1[2] = {f2u(bfr[ni].z), f2u(bfr[ni].w)};
                mma_tf32(c[mi][ni], a0, b0);
                mma_tf32(c[mi][ni], a1, b1);
            }
        }
        s ^= 1;
    }

    #pragma unroll
    for (int mi = 0; mi < 4; mi++) {
        int m0 = row0 + wm + mi * 16 + g;
        #pragma unroll
        for (int ni = 0; ni < 4; ni++) {
            int n0 = col0 + wn + ni * 8 + tig * 2;
            #pragma unroll
            for (int jj = 0; jj < 4; jj++) {
                int m = m0 + (jj >> 1) * 8;
                int n = n0 + (jj & 1);
                C[(size_t)m * ldc + (size_t)n * cstride] = sign * c[mi][ni][jj];
            }
        }
    }
}

// ---------------- row softmax (scores pre-scaled), in-place on S ----------------
__global__ void softmax_kernel(float* __restrict__ S) {
    size_t base = ((size_t)blockIdx.y * SEQ + blockIdx.x) * SEQ;
    float4* row = (float4*)(S + base);
    int t = threadIdx.x;
    float4 v0 = row[t], v1 = row[t + 256];
    float m = fmaxf(fmaxf(fmaxf(v0.x, v0.y), fmaxf(v0.z, v0.w)),
                    fmaxf(fmaxf(v1.x, v1.y), fmaxf(v1.z, v1.w)));
    #pragma unroll
    for (int o = 16; o > 0; o >>= 1) m = fmaxf(m, __shfl_xor_sync(0xffffffffu, m, o));
    __shared__ float red[8];
    if ((t & 31) == 0) red[t >> 5] = m;
    __syncthreads();
    m = red[0];
    #pragma unroll
    for (int i = 1; i < 8; i++) m = fmaxf(m, red[i]);

    v0.x = expf(v0.x - m); v0.y = expf(v0.y - m); v0.z = expf(v0.z - m); v0.w = expf(v0.w - m);
    v1.x = expf(v1.x - m); v1.y = expf(v1.y - m); v1.z = expf(v1.z - m); v1.w = expf(v1.w - m);
    float s = v0.x + v0.y + v0.z + v0.w + v1.x + v1.y + v1.z + v1.w;
    #pragma unroll
    for (int o = 16; o > 0; o >>= 1) s += __shfl_xor_sync(0xffffffffu, s, o);
    __syncthreads();
    if ((t & 31) == 0) red[t >> 5] = s;
    __syncthreads();
    s = red[0];
    #pragma unroll
    for (int i = 1; i < 8; i++) s += red[i];
    float inv = 1.0f / s;
    v0.x *= inv; v0.y *= inv; v0.z *= inv; v0.w *= inv;
    v1.x *= inv; v1.y *= inv; v1.z *= inv; v1.w *= inv;
    row[t] = v0; row[t + 256] = v1;
}

// ---------------- manifold projection (complex, K=64) ----------------
__global__ void manifold_kernel(const float* __restrict__ t_re, const float* __restrict__ t_im,
                                const float* __restrict__ Wre, const float* __restrict__ Wim,
                                float* __restrict__ Tp) {
    __shared__ float sAr[16][64], sAi[16][64];
    __shared__ float4 sWr[64][16], sWi[64][16];
    int bh = blockIdx.z; int b = bh >> 3, h = bh & 7;
    int s0 = blockIdx.y * 16;
    int qbase = blockIdx.x * 16;
    int tx = threadIdx.x, ty = threadIdx.y;
    int tid = ty * 16 + tx;
    const float4* Wre4 = (const float4*)Wre;
    const float4* Wim4 = (const float4*)Wim;
    #pragma unroll
    for (int i = 0; i < 4; i++) {
        int idx = tid + i * 256;
        int ss = idx >> 6, kk = idx & 63;
        size_t gg = ((size_t)(b * SEQ + s0 + ss)) * HID + h * HDIM + kk;
        sAr[ss][kk] = t_re[gg];
        sAi[ss][kk] = t_im[gg];
        int wk = idx >> 4, mq = idx & 15;
        sWr[wk][mq] = Wre4[wk * 64 + qbase + mq];
        sWi[wk][mq] = Wim4[wk * 64 + qbase + mq];
    }
    __syncthreads();
    float4 ar = make_float4(0,0,0,0), ai = make_float4(0,0,0,0);
    #pragma unroll
    for (int k = 0; k < 64; k++) {
        float xr = sAr[ty][k], xi = sAi[ty][k];
        float4 wr = sWr[k][tx], wi = sWi[k][tx];
        ar.x += xr*wr.x - xi*wi.x;  ai.x += xr*wi.x + xi*wr.x;
        ar.y += xr*wr.y - xi*wi.y;  ai.y += xr*wi.y + xi*wr.y;
        ar.z += xr*wr.z - xi*wi.z;  ai.z += xr*wi.z + xi*wr.z;
        ar.w += xr*wr.w - xi*wi.w;  ai.w += xr*wi.w + xi*wr.w;
    }
    size_t o = ((size_t)bh * SEQ + s0 + ty) * DM + qbase * 4;
    ((float4*)(Tp + o))[tx] = ar;
    ((float4*)(Tp + o + MAN))[tx] = ai;
}

// ---------------- Wmi back-projection (complex, K=256) + head merge ----------------
__global__ void wmi_kernel(const float* __restrict__ Op,
                           const float* __restrict__ Wre, const float* __restrict__ Wim,
                           float* __restrict__ o_re, float* __restrict__ o_im) {
    __shared__ float sAr[16][64], sAi[16][64];
    __shared__ float4 sWr[64][16], sWi[64][16];
    int bh = blockIdx.y; int b = bh >> 3, h = bh & 7;
    int s0 = blockIdx.x * 16;
    int tx = threadIdx.x, ty = threadIdx.y;
    int tid = ty * 16 + tx;
    const float4* Wre4 = (const float4*)Wre;
    const float4* Wim4 = (const float4*)Wim;
    float4 ar = make_float4(0,0,0,0), ai = make_float4(0,0,0,0);
    for (int kt = 0; kt < MAN; kt += 64) {
        #pragma unroll
        for (int i = 0; i < 4; i++) {
            int idx = tid + i * 256;
            int ss = idx >> 6, kk = idx & 63;
            size_t gg = ((size_t)bh * SEQ + s0 + ss) * DM;
            sAr[ss][kk] = Op[gg + kt + kk];
            sAi[ss][kk] = Op[gg + MAN + kt + kk];
            int wk = idx >> 4, dq = idx & 15;
            sWr[wk][dq] = Wre4[(size_t)(kt + wk) * 16 + dq];
            sWi[wk][dq] = Wim4[(size_t)(kt + wk) * 16 + dq];
        }
        __syncthreads();
        #pragma unroll
        for (int k = 0; k < 64; k++) {
            float xr = sAr[ty][k], xi = sAi[ty][k];
            float4 wr = sWr[k][tx], wi = sWi[k][tx];
            ar.x += xr*wr.x - xi*wi.x;  ai.x += xr*wi.x + xi*wr.x;
            ar.y += xr*wr.y - xi*wi.y;  ai.y += xr*wi.y + xi*wr.y;
            ar.z += xr*wr.z - xi*wi.z;  ai.z += xr*wi.z + xi*wr.z;
            ar.w += xr*wr.w - xi*wi.w;  ai.w += xr*wi.w + xi*wr.w;
        }
        __syncthreads();
    }
    size_t o = ((size_t)(b * SEQ + s0 + ty)) * HID + h * HDIM;
    ((float4*)(o_re + o))[tx] = ar;
    ((float4*)(o_im + o))[tx] = ai;
}

// ---------------- launcher ----------------
extern "C" void kernel_launch(void* const* d_in, const int* in_sizes, int n_in,
                              void* d_out, int out_size) {
    const float* x      = (const float*)d_in[0];
    const float* Wq_re  = (const float*)d_in[1];
    const float* Wq_im  = (const float*)d_in[2];
    const float* Wk_re  = (const float*)d_in[3];
    const float* Wk_im  = (const float*)d_in[4];
    const float* Wv_re  = (const float*)d_in[5];
    const float* Wv_im  = (const float*)d_in[6];
    const float* Wm_re  = (const float*)d_in[7];
    const float* Wm_im  = (const float*)d_in[8];
    const float* Wmi_re = (const float*)d_in[9];
    const float* Wmi_im = (const float*)d_in[10];
    const float* Wo_re  = (const float*)d_in[11];
    const float* Wo_im  = (const float*)d_in[12];
    float* out = (float*)d_out;

    float *xn, *q_re, *q_im, *k_re, *k_im, *v_re, *v_im, *Qp, *Kp, *Vp, *Opp, *oh_re, *oh_im, *S;
    cudaGetSymbolAddress((void**)&xn,    g_xn);
    cudaGetSymbolAddress((void**)&q_re,  g_q_re);
    cudaGetSymbolAddress((void**)&q_im,  g_q_im);
    cudaGetSymbolAddress((void**)&k_re,  g_k_re);
    cudaGetSymbolAddress((void**)&k_im,  g_k_im);
    cudaGetSymbolAddress((void**)&v_re,  g_v_re);
    cudaGetSymbolAddress((void**)&v_im,  g_v_im);
    cudaGetSymbolAddress((void**)&Qp,    g_Qp);
    cudaGetSymbolAddress((void**)&Kp,    g_Kp);
    cudaGetSymbolAddress((void**)&Vp,    g_Vp);
    cudaGetSymbolAddress((void**)&Opp,   g_Op);
    cudaGetSymbolAddress((void**)&oh_re, g_oh_re);
    cudaGetSymbolAddress((void**)&oh_im, g_oh_im);
    cudaGetSymbolAddress((void**)&S,     g_S);

    norm_kernel<<<NROWS, 128>>>(x, xn);

    dim3 tb(256);

    // QKV: one launch, z=6
    {
        PtrBatch pb{};
        const float* Bs6[6] = {Wq_re, Wq_im, Wk_re, Wk_im, Wv_re, Wv_im};
        float* Cs6[6] = {q_re, q_im, k_re, k_im, v_re, v_im};
        for (int i = 0; i < 6; i++) { pb.A[i] = xn; pb.B[i] = Bs6[i]; pb.C[i] = Cs6[i]; }
        gemm_tf32<0,0><<<dim3(HID/128, NROWS/128, 6), tb>>>(pb, NROWS, HID, HID, HID, 1, 1.f, 0, 0);
    }

    // manifold projections -> Q',K',V'  [BH, SEQ, 512]
    dim3 tb2(16, 16);
    dim3 gm(4, SEQ / 16, BH);
    manifold_kernel<<<gm, tb2>>>(q_re, q_im, Wm_re, Wm_im, Qp);
    manifold_kernel<<<gm, tb2>>>(k_re, k_im, Wm_re, Wm_im, Kp);
    manifold_kernel<<<gm, tb2>>>(v_re, v_im, Wm_re, Wm_im, Vp);

    // scores: S = SCALE * Q' K'^T   (batched over BH, NT)
    {
        PtrBatch pb{};
        for (int z = 0; z < BH; z++) {
            pb.A[z] = Qp + (size_t)z * SEQ * DM;
            pb.B[z] = Kp + (size_t)z * SEQ * DM;
            pb.C[z] = S + (size_t)z * SEQ * SEQ;
        }
        gemm_tf32<1,0><<<dim3(SEQ/128, SEQ/128, BH), tb>>>(pb, SEQ, SEQ, DM, SEQ, 1, SCALE, 0, 0);
    }

    softmax_kernel<<<dim3(SEQ, BH), 256>>>(S);

    // O' = P V'   (batched, NN)
    {
        PtrBatch pb{};
        for (int z = 0; z < BH; z++) {
            pb.A[z] = S + (size_t)z * SEQ * SEQ;
            pb.B[z] = Vp + (size_t)z * SEQ * DM;
            pb.C[z] = Opp + (size_t)z * SEQ * DM;
        }
        gemm_tf32<0,0><<<dim3(DM/128, SEQ/128, BH), tb>>>(pb, SEQ, DM, SEQ, DM, 1, 1.f, 0, 0);
    }

    // Wmi back-projection + head merge
    wmi_kernel<<<dim3(SEQ / 16, BH), tb2>>>(Opp, Wmi_re, Wmi_im, oh_re, oh_im);

    // out = (oh_re + i*oh_im) @ (Wo_re + i*Wo_im), interleaved [.,512,2]
    // z=0: out_re = oh_re@Wo_re - oh_im@Wo_im ; z=1: out_im = oh_re@Wo_im + oh_im@Wo_re
    {
        PtrBatch pb{};
        pb.A[0] = oh_re; pb.B[0] = Wo_re; pb.A[1] = oh_im; pb.B[1] = Wo_im;
        pb.A[2] = oh_re; pb.B[2] = Wo_im; pb.A[3] = oh_im; pb.B[3] = Wo_re;
        pb.C[0] = out;   pb.C[1] = out + 1;
        gemm_tf32<0,1><<<dim3(HID/128, NROWS/128, 2), tb>>>(pb, NROWS, HID, HID, 2*HID, 2, 1.f, -1.f, 1.f);
    }
}

// round 4
// speedup vs baseline: 1.6870x; 1.6870x over previous
#include <cuda_runtime.h>
#include <cuda_bf16.h>
#include <cstdint>

#define BATCH 2
#define SEQ   2048
#define HID   512
#define HEADS 8
#define HDIM  64
#define MAN   256
#define DM2   2048           // HEADS*MAN
#define NROWS (BATCH*SEQ)    // 4096
#define BH    (BATCH*HEADS)  // 16
#define SCALE 0.125f         // 64^-0.5

// ---------------- scratch (device globals; no allocations) ----------------
__device__ float g_xn[NROWS * HID];
__device__ float g_fq_re[HID * DM2];
__device__ float g_fq_im[HID * DM2];
__device__ float g_fk_re[HID * DM2];
__device__ float g_fk_im[HID * DM2];
__device__ float g_fv_re[HID * DM2];
__device__ float g_fv_im[HID * DM2];
__device__ float g_Wmio_re[DM2 * HID];
__device__ float g_Wmio_im[DM2 * HID];   // (unused in final path; kept for option)
__device__ float g_Qre[(size_t)NROWS * DM2];
__device__ float g_Qim[(size_t)NROWS * DM2];
__device__ float g_Kre[(size_t)NROWS * DM2];
__device__ float g_Kim[(size_t)NROWS * DM2];
__device__ float g_Vre[(size_t)NROWS * DM2];
__device__ float g_Vim[(size_t)NROWS * DM2];
__device__ float g_S[(size_t)BH * SEQ * SEQ];   // 268 MB
__device__ float g_Om_re[(size_t)NROWS * DM2];
__device__ float g_Om_im[(size_t)NROWS * DM2];
__device__ float g_oh_re[NROWS * HID];
__device__ float g_oh_im[NROWS * HID];

#define MAXB 48
struct GemmBatch {
    const float* A1[MAXB];
    const float* B1[MAXB];
    const float* A2[MAXB];
    const float* B2[MAXB];
    float*       C[MAXB];
    float        s2[MAXB];
};

// ---------------- helpers ----------------
__device__ __forceinline__ float to_tf32(float x) {
    asm("cvt.rna.tf32.f32 %0, %1;" : "=f"(x) : "f"(x));
    return x;
}
__device__ __forceinline__ void mma_tf32(float c[4], const uint32_t a[4], const uint32_t b[2]) {
    asm volatile(
        "mma.sync.aligned.m16n8k8.row.col.f32.tf32.tf32.f32 "
        "{%0,%1,%2,%3},{%4,%5,%6,%7},{%8,%9},{%0,%1,%2,%3};"
        : "+f"(c[0]), "+f"(c[1]), "+f"(c[2]), "+f"(c[3])
        : "r"(a[0]), "r"(a[1]), "r"(a[2]), "r"(a[3]), "r"(b[0]), "r"(b[1]));
}

// ---------------- row L2-normalize ----------------
__global__ void norm_kernel(const float* __restrict__ x, float* __restrict__ xn) {
    int row = blockIdx.x;
    int t = threadIdx.x;
    const float4* xr = (const float4*)(x + (size_t)row * HID);
    float4 v = xr[t];
    float ss = v.x*v.x + v.y*v.y + v.z*v.z + v.w*v.w;
    #pragma unroll
    for (int o = 16; o > 0; o >>= 1) ss += __shfl_xor_sync(0xffffffffu, ss, o);
    __shared__ float ws[4];
    if ((t & 31) == 0) ws[t >> 5] = ss;
    __syncthreads();
    float tot = ws[0] + ws[1] + ws[2] + ws[3];
    float inv = 1.0f / sqrtf(tot);
    v.x *= inv; v.y *= inv; v.z *= inv; v.w *= inv;
    ((float4*)(xn + (size_t)row * HID))[t] = v;
}

// ---------------- tf32 tensor-core GEMM (round-2 mechanics + lda/ldb/TWO) ----------------
// 128x128 tile, BK=16, 256 threads (8 warps, 2x4, 64x32 warp tiles).
// TRANSB=0: B[k*ldb + n].  TRANSB=1: B[n*ldb + k].
// TWO=1: C = sign * (A1@B1 + s2[z] * A2@B2), each product depth K.
template<int TRANSB, int TWO>
__global__ __launch_bounds__(256)
void gemm_tf32(GemmBatch gb, int K, int lda, int ldb, int ldc, int cstride, float sign) {
    __shared__ float As[16][136];
    __shared__ float Bs[16][136];

    const int tid = threadIdx.x;
    const int bz = blockIdx.z;
    const float* A1 = gb.A1[bz];
    const float* B1 = gb.B1[bz];
    const float* A2 = TWO ? gb.A2[bz] : nullptr;
    const float* B2 = TWO ? gb.B2[bz] : nullptr;
    const float  s2 = TWO ? gb.s2[bz] : 1.f;
    float* C = gb.C[bz];

    const int row0 = blockIdx.y * 128;
    const int col0 = blockIdx.x * 128;
    const int warp = tid >> 5, lane = tid & 31;
    const int wm = (warp & 1) * 64;
    const int wn = (warp >> 1) * 32;
    const int g = lane >> 2, tig = lane & 3;

    float c[4][4][4] = {};
    float4 ra[2], rb[2];
    float stage_sc = 1.f;
    const int nk = TWO ? 2 * K : K;

    auto load_stage = [&](int kt) {
        int p = TWO && (kt >= K);
        const float* Ap = p ? A2 : A1;
        const float* Bp = p ? B2 : B1;
        int kk = kt - (p ? K : 0);
        stage_sc = p ? s2 : 1.f;
        #pragma unroll
        for (int i = 0; i < 2; i++) {
            int idx = tid + i * 256;
            int r = idx >> 2, kq = (idx & 3) * 4;
            ra[i] = *(const float4*)(Ap + (size_t)(row0 + r) * lda + kk + kq);
        }
        if (TRANSB) {
            #pragma unroll
            for (int i = 0; i < 2; i++) {
                int idx = tid + i * 256;
                int n = idx >> 2, kq = (idx & 3) * 4;
                rb[i] = *(const float4*)(Bp + (size_t)(col0 + n) * ldb + kk + kq);
            }
        } else {
            #pragma unroll
            for (int i = 0; i < 2; i++) {
                int idx = tid + i * 256;
                int r = idx >> 5, nq = (idx & 31) * 4;
                rb[i] = *(const float4*)(Bp + (size_t)(kk + r) * ldb + col0 + nq);
            }
        }
    };

    load_stage(0);

    for (int kt = 0; kt < nk; kt += 16) {
        float sc = stage_sc;
        #pragma unroll
        for (int i = 0; i < 2; i++) {
            int idx = tid + i * 256;
            int r = idx >> 2, kq = (idx & 3) * 4;
            As[kq + 0][r] = to_tf32(ra[i].x);
            As[kq + 1][r] = to_tf32(ra[i].y);
            As[kq + 2][r] = to_tf32(ra[i].z);
            As[kq + 3][r] = to_tf32(ra[i].w);
        }
        if (TRANSB) {
            #pragma unroll
            for (int i = 0; i < 2; i++) {
                int idx = tid + i * 256;
                int n = idx >> 2, kq = (idx & 3) * 4;
                Bs[kq + 0][n] = to_tf32(rb[i].x * sc);
                Bs[kq + 1][n] = to_tf32(rb[i].y * sc);
                Bs[kq + 2][n] = to_tf32(rb[i].z * sc);
                Bs[kq + 3][n] = to_tf32(rb[i].w * sc);
            }
        } else {
            #pragma unroll
            for (int i = 0; i < 2; i++) {
                int idx = tid + i * 256;
                int r = idx >> 5, nq = (idx & 31) * 4;
                float4 cv;
                cv.x = to_tf32(rb[i].x * sc); cv.y = to_tf32(rb[i].y * sc);
                cv.z = to_tf32(rb[i].z * sc); cv.w = to_tf32(rb[i].w * sc);
                *(float4*)&Bs[r][nq] = cv;
            }
        }
        __syncthreads();

        if (kt + 16 < nk) load_stage(kt + 16);

        #pragma unroll
        for (int kc = 0; kc < 2; kc++) {
            const int kb = kc * 8;
            uint32_t a[4][4], b[4][2];
            #pragma unroll
            for (int mi = 0; mi < 4; mi++) {
                int m = wm + mi * 16 + g;
                a[mi][0] = __float_as_uint(As[kb + tig][m]);
                a[mi][1] = __float_as_uint(As[kb + tig][m + 8]);
                a[mi][2] = __float_as_uint(As[kb + tig + 4][m]);
                a[mi][3] = __float_as_uint(As[kb + tig + 4][m + 8]);
            }
            #pragma unroll
            for (int ni = 0; ni < 4; ni++) {
                int n = wn + ni * 8 + g;
                b[ni][0] = __float_as_uint(Bs[kb + tig][n]);
                b[ni][1] = __float_as_uint(Bs[kb + tig + 4][n]);
            }
            #pragma unroll
            for (int mi = 0; mi < 4; mi++)
                #pragma unroll
                for (int ni = 0; ni < 4; ni++)
                    mma_tf32(c[mi][ni], a[mi], b[ni]);
        }
        __syncthreads();
    }

    #pragma unroll
    for (int mi = 0; mi < 4; mi++) {
        int m0 = row0 + wm + mi * 16 + g;
        #pragma unroll
        for (int ni = 0; ni < 4; ni++) {
            int n0 = col0 + wn + ni * 8 + tig * 2;
            #pragma unroll
            for (int jj = 0; jj < 4; jj++) {
                int m = m0 + (jj >> 1) * 8;
                int n = n0 + (jj & 1);
                C[(size_t)m * ldc + (size_t)n * cstride] = sign * c[mi][ni][jj];
            }
        }
    }
}

// ---------------- row softmax (scores pre-scaled), in-place on S ----------------
__global__ void softmax_kernel(float* __restrict__ S) {
    size_t base = ((size_t)blockIdx.y * SEQ + blockIdx.x) * SEQ;
    float4* row = (float4*)(S + base);
    int t = threadIdx.x;
    float4 v0 = row[t], v1 = row[t + 256];
    float m = fmaxf(fmaxf(fmaxf(v0.x, v0.y), fmaxf(v0.z, v0.w)),
                    fmaxf(fmaxf(v1.x, v1.y), fmaxf(v1.z, v1.w)));
    #pragma unroll
    for (int o = 16; o > 0; o >>= 1) m = fmaxf(m, __shfl_xor_sync(0xffffffffu, m, o));
    __shared__ float red[8];
    if ((t & 31) == 0) red[t >> 5] = m;
    __syncthreads();
    m = red[0];
    #pragma unroll
    for (int i = 1; i < 8; i++) m = fmaxf(m, red[i]);

    v0.x = expf(v0.x - m); v0.y = expf(v0.y - m); v0.z = expf(v0.z - m); v0.w = expf(v0.w - m);
    v1.x = expf(v1.x - m); v1.y = expf(v1.y - m); v1.z = expf(v1.z - m); v1.w = expf(v1.w - m);
    float s = v0.x + v0.y + v0.z + v0.w + v1.x + v1.y + v1.z + v1.w;
    #pragma unroll
    for (int o = 16; o > 0; o >>= 1) s += __shfl_xor_sync(0xffffffffu, s, o);
    __syncthreads();
    if ((t & 31) == 0) red[t >> 5] = s;
    __syncthreads();
    s = red[0];
    #pragma unroll
    for (int i = 1; i < 8; i++) s += red[i];
    float inv = 1.0f / s;
    v0.x *= inv; v0.y *= inv; v0.z *= inv; v0.w *= inv;
    v1.x *= inv; v1.y *= inv; v1.z *= inv; v1.w *= inv;
    row[t] = v0; row[t + 256] = v1;
}

// ---------------- Wmi back-projection (complex, K=256) + head merge ----------------
// Om_re/Om_im [NROWS, 2048] ([b,s][h*256+m]); Wmi [256,64] -> o_re/o_im [NROWS,512]
__global__ void wmi_kernel(const float* __restrict__ Om_re, const float* __restrict__ Om_im,
                           const float* __restrict__ Wre, const float* __restrict__ Wim,
                           float* __restrict__ o_re, float* __restrict__ o_im) {
    // grid (NROWS/16, HEADS), block (16,16)
    __shared__ float sAr[16][64], sAi[16][64];
    __shared__ float4 sWr[64][16], sWi[64][16];
    int h = blockIdx.y;
    int s0 = blockIdx.x * 16;
    int tx = threadIdx.x, ty = threadIdx.y;
    int tid = ty * 16 + tx;
    const float4* Wre4 = (const float4*)Wre;
    const float4* Wim4 = (const float4*)Wim;
    float4 ar = make_float4(0,0,0,0), ai = make_float4(0,0,0,0);
    for (int kt = 0; kt < MAN; kt += 64) {
        #pragma unroll
        for (int i = 0; i < 4; i++) {
            int idx = tid + i * 256;
            int ss = idx >> 6, kk = idx & 63;
            size_t gg = (size_t)(s0 + ss) * DM2 + h * MAN + kt + kk;
            sAr[ss][kk] = Om_re[gg];
            sAi[ss][kk] = Om_im[gg];
            int wk = idx >> 4, dq = idx & 15;
            sWr[wk][dq] = Wre4[(size_t)(kt + wk) * 16 + dq];
            sWi[wk][dq] = Wim4[(size_t)(kt + wk) * 16 + dq];
        }
        __syncthreads();
        #pragma unroll
        for (int k = 0; k < 64; k++) {
            float xr = sAr[ty][k], xi = sAi[ty][k];
            float4 wr = sWr[k][tx], wi = sWi[k][tx];
            ar.x += xr*wr.x - xi*wi.x;  ai.x += xr*wi.x + xi*wr.x;
            ar.y += xr*wr.y - xi*wi.y;  ai.y += xr*wi.y + xi*wr.y;
            ar.z += xr*wr.z - xi*wi.z;  ai.z += xr*wi.z + xi*wr.z;
            ar.w += xr*wr.w - xi*wi.w;  ai.w += xr*wi.w + xi*wr.w;
        }
        __syncthreads();
    }
    size_t o = (size_t)(s0 + ty) * HID + h * HDIM;
    ((float4*)(o_re + o))[tx] = ar;
    ((float4*)(o_im + o))[tx] = ai;
}

// ---------------- launcher ----------------
extern "C" void kernel_launch(void* const* d_in, const int* in_sizes, int n_in,
                              void* d_out, int out_size) {
    const float* x      = (const float*)d_in[0];
    const float* Wq_re  = (const float*)d_in[1];
    const float* Wq_im  = (const float*)d_in[2];
    const float* Wk_re  = (const float*)d_in[3];
    const float* Wk_im  = (const float*)d_in[4];
    const float* Wv_re  = (const float*)d_in[5];
    const float* Wv_im  = (const float*)d_in[6];
    const float* Wm_re  = (const float*)d_in[7];
    const float* Wm_im  = (const float*)d_in[8];
    const float* Wmi_re = (const float*)d_in[9];
    const float* Wmi_im = (const float*)d_in[10];
    const float* Wo_re  = (const float*)d_in[11];
    const float* Wo_im  = (const float*)d_in[12];
    float* out = (float*)d_out;

    float *xn, *fq_re, *fq_im, *fk_re, *fk_im, *fv_re, *fv_im;
    float *Qre, *Qim, *Kre, *Kim, *Vre, *Vim, *S, *Om_re, *Om_im, *oh_re, *oh_im;
    cudaGetSymbolAddress((void**)&xn,    g_xn);
    cudaGetSymbolAddress((void**)&fq_re, g_fq_re);
    cudaGetSymbolAddress((void**)&fq_im, g_fq_im);
    cudaGetSymbolAddress((void**)&fk_re, g_fk_re);
    cudaGetSymbolAddress((void**)&fk_im, g_fk_im);
    cudaGetSymbolAddress((void**)&fv_re, g_fv_re);
    cudaGetSymbolAddress((void**)&fv_im, g_fv_im);
    cudaGetSymbolAddress((void**)&Qre,   g_Qre);
    cudaGetSymbolAddress((void**)&Qim,   g_Qim);
    cudaGetSymbolAddress((void**)&Kre,   g_Kre);
    cudaGetSymbolAddress((void**)&Kim,   g_Kim);
    cudaGetSymbolAddress((void**)&Vre,   g_Vre);
    cudaGetSymbolAddress((void**)&Vim,   g_Vim);
    cudaGetSymbolAddress((void**)&S,     g_S);
    cudaGetSymbolAddress((void**)&Om_re, g_Om_re);
    cudaGetSymbolAddress((void**)&Om_im, g_Om_im);
    cudaGetSymbolAddress((void**)&oh_re, g_oh_re);
    cudaGetSymbolAddress((void**)&oh_im, g_oh_im);

    norm_kernel<<<NROWS, 128>>>(x, xn);

    dim3 tb(256);

    // --- precompute fused QKV+manifold weights: Wxm = Wx_head @ Wm (complex), z=48 ---
    {
        GemmBatch gb{};
        const float* Wre_[3] = {Wq_re, Wk_re, Wv_re};
        const float* Wim_[3] = {Wq_im, Wk_im, Wv_im};
        float* Fre[3] = {fq_re, fk_re, fv_re};
        float* Fim[3] = {fq_im, fk_im, fv_im};
        int z = 0;
        for (int w = 0; w < 3; w++) {
            for (int h = 0; h < HEADS; h++) {
                gb.A1[z] = Wre_[w] + h * HDIM; gb.B1[z] = Wm_re;
                gb.A2[z] = Wim_[w] + h * HDIM; gb.B2[z] = Wm_im;
                gb.s2[z] = -1.f; gb.C[z] = Fre[w] + h * MAN; z++;
                gb.A1[z] = Wre_[w] + h * HDIM; gb.B1[z] = Wm_im;
                gb.A2[z] = Wim_[w] + h * HDIM; gb.B2[z] = Wm_re;
                gb.s2[z] = 1.f; gb.C[z] = Fim[w] + h * MAN; z++;
            }
        }
        gemm_tf32<0,1><<<dim3(MAN/128, HID/128, 48), tb>>>(gb, HDIM, HID, MAN, DM2, 1, 1.f);
    }

    // --- fused QKV+manifold: [4096,512] @ [512,2048], z=6 ---
    {
        GemmBatch gb{};
        const float* Bp[6] = {fq_re, fq_im, fk_re, fk_im, fv_re, fv_im};
        float* Cp[6] = {Qre, Qim, Kre, Kim, Vre, Vim};
        for (int i = 0; i < 6; i++) { gb.A1[i] = xn; gb.B1[i] = Bp[i]; gb.C[i] = Cp[i]; }
        gemm_tf32<0,0><<<dim3(DM2/128, NROWS/128, 6), tb>>>(gb, HID, HID, DM2, DM2, 1, 1.f);
    }

    // --- scores: S = SCALE * (Qre Kre^T + Qim Kim^T), z=16 ---
    {
        GemmBatch gb{};
        for (int z = 0; z < BH; z++) {
            int b = z >> 3, h = z & 7;
            size_t off = (size_t)b * SEQ * DM2 + (size_t)h * MAN;
            gb.A1[z] = Qre + off; gb.B1[z] = Kre + off;
            gb.A2[z] = Qim + off; gb.B2[z] = Kim + off;
            gb.s2[z] = 1.f;
            gb.C[z] = S + (size_t)z * SEQ * SEQ;
        }
        gemm_tf32<1,1><<<dim3(SEQ/128, SEQ/128, BH), tb>>>(gb, MAN, DM2, DM2, SEQ, 1, SCALE);
    }

    softmax_kernel<<<dim3(SEQ, BH), 256>>>(S);

    // --- PV: Om_re = P Vre, Om_im = P Vim, z=32 ---
    {
        GemmBatch gb{};
        for (int z = 0; z < BH; z++) {
            int b = z >> 3, h = z & 7;
            size_t off = (size_t)b * SEQ * DM2 + (size_t)h * MAN;
            gb.A1[z]      = S + (size_t)z * SEQ * SEQ;
            gb.B1[z]      = Vre + off;
            gb.C[z]       = Om_re + off;
            gb.A1[z + BH] = S + (size_t)z * SEQ * SEQ;
            gb.B1[z + BH] = Vim + off;
            gb.C[z + BH]  = Om_im + off;
        }
        gemm_tf32<0,0><<<dim3(MAN/128, SEQ/128, 2*BH), tb>>>(gb, SEQ, SEQ, DM2, DM2, 1, 1.f);
    }

    // --- Wmi back-projection + head merge ---
    wmi_kernel<<<dim3(NROWS/16, HEADS), dim3(16,16)>>>(Om_re, Om_im, Wmi_re, Wmi_im, oh_re, oh_im);

    // --- output projection: complex Wo, interleaved [.,512,2], z=2 ---
    {
        GemmBatch gb{};
        gb.A1[0] = oh_re; gb.B1[0] = Wo_re; gb.A2[0] = oh_im; gb.B2[0] = Wo_im;
        gb.s2[0] = -1.f;  gb.C[0] = out;
        gb.A1[1] = oh_re; gb.B1[1] = Wo_im; gb.A2[1] = oh_im; gb.B2[1] = Wo_re;
        gb.s2[1] = 1.f;   gb.C[1] = out + 1;
        gemm_tf32<0,1><<<dim3(HID/128, NROWS/128, 2), tb>>>(gb, HID, HID, HID, 2*HID, 2, 1.f);
    }
}

// round 6
// speedup vs baseline: 1.9531x; 1.1578x over previous
#include <cuda_runtime.h>
#include <cuda_bf16.h>
#include <cstdint>

#define BATCH 2
#define SEQ   2048
#define HID   512
#define HEADS 8
#define HDIM  64
#define MAN   256
#define DM2   2048           // HEADS*MAN
#define NROWS (BATCH*SEQ)    // 4096
#define BH    (BATCH*HEADS)  // 16
#define SCALE 0.125f         // 64^-0.5

#define AROW 20              // padded smem row (floats): conflict-free ldmatrix

// ---------------- scratch (device globals; no allocations) ----------------
__device__ float g_xn[NROWS * HID];
__device__ float g_fq_re[HID * DM2];
__device__ float g_fq_im[HID * DM2];
__device__ float g_fk_re[HID * DM2];
__device__ float g_fk_im[HID * DM2];
__device__ float g_fv_re[HID * DM2];
__device__ float g_fv_im[HID * DM2];
__device__ float g_Qre[(size_t)NROWS * DM2];
__device__ float g_Qim[(size_t)NROWS * DM2];
__device__ float g_Kre[(size_t)NROWS * DM2];
__device__ float g_Kim[(size_t)NROWS * DM2];
__device__ float g_Vre[(size_t)NROWS * DM2];
__device__ float g_Vim[(size_t)NROWS * DM2];
__device__ float g_S[(size_t)BH * SEQ * SEQ];   // 268 MB
__device__ float g_Om_re[(size_t)NROWS * DM2];
__device__ float g_Om_im[(size_t)NROWS * DM2];
__device__ float g_oh_re[NROWS * HID];
__device__ float g_oh_im[NROWS * HID];

#define MAXB 48
struct GemmBatch {
    const float* A1[MAXB];
    const float* B1[MAXB];
    const float* A2[MAXB];
    const float* B2[MAXB];
    float*       C[MAXB];
    float        s2[MAXB];
};

// ---------------- helpers ----------------
__device__ __forceinline__ float to_tf32(float x) {
    asm("cvt.rna.tf32.f32 %0, %1;" : "=f"(x) : "f"(x));
    return x;
}
__device__ __forceinline__ void mma_tf32(float c[4], const uint32_t a[4], const uint32_t b[2]) {
    asm volatile(
        "mma.sync.aligned.m16n8k8.row.col.f32.tf32.tf32.f32 "
        "{%0,%1,%2,%3},{%4,%5,%6,%7},{%8,%9},{%0,%1,%2,%3};"
        : "+f"(c[0]), "+f"(c[1]), "+f"(c[2]), "+f"(c[3])
        : "r"(a[0]), "r"(a[1]), "r"(a[2]), "r"(a[3]), "r"(b[0]), "r"(b[1]));
}
__device__ __forceinline__ void ldsm_x4(uint32_t r[4], uint32_t addr) {
    asm volatile("ldmatrix.sync.aligned.m8n8.x4.shared.b16 {%0,%1,%2,%3}, [%4];"
        : "=r"(r[0]), "=r"(r[1]), "=r"(r[2]), "=r"(r[3]) : "r"(addr));
}
__device__ __forceinline__ void ldsm_x2(uint32_t r[2], uint32_t addr) {
    asm volatile("ldmatrix.sync.aligned.m8n8.x2.shared.b16 {%0,%1}, [%2];"
        : "=r"(r[0]), "=r"(r[1]) : "r"(addr));
}

// ---------------- row L2-normalize ----------------
__global__ void norm_kernel(const float* __restrict__ x, float* __restrict__ xn) {
    int row = blockIdx.x;
    int t = threadIdx.x;
    const float4* xr = (const float4*)(x + (size_t)row * HID);
    float4 v = xr[t];
    float ss = v.x*v.x + v.y*v.y + v.z*v.z + v.w*v.w;
    #pragma unroll
    for (int o = 16; o > 0; o >>= 1) ss += __shfl_xor_sync(0xffffffffu, ss, o);
    __shared__ float ws[4];
    if ((t & 31) == 0) ws[t >> 5] = ss;
    __syncthreads();
    float tot = ws[0] + ws[1] + ws[2] + ws[3];
    float inv = 1.0f / sqrtf(tot);
    v.x *= inv; v.y *= inv; v.z *= inv; v.w *= inv;
    ((float4*)(xn + (size_t)row * HID))[t] = v;
}

// ---------------- tf32 tensor-core GEMM (ldmatrix fragment path) ----------------
// 128x128 tile, BK=16, 256 threads (8 warps, 2x4, 64x32 warp tiles).
// A smem: [128 rows][AROW floats] (16 valid k) -> ldmatrix.x4 frags.
// TRANSB=1: B gmem [n*ldb+k]; B smem same padded layout -> ldmatrix.x2.
// TRANSB=0: B gmem [k*ldb+n]; B smem [16][136] -> scalar LDS (proven path).
// TWO=1: C = sign * (A1@B1 + s2[z] * A2@B2), each product depth K.
template<int TRANSB, int TWO>
__global__ __launch_bounds__(256)
void gemm_tf32(GemmBatch gb, int K, int lda, int ldb, int ldc, int cstride, float sign) {
    __shared__ alignas(16) float As[128 * AROW];
    __shared__ alignas(16) float Bs[TRANSB ? 128 * AROW : 16 * 136];

    const int tid = threadIdx.x;
    const int bz = blockIdx.z;
    const float* A1 = gb.A1[bz];
    const float* B1 = gb.B1[bz];
    const float* A2 = TWO ? gb.A2[bz] : nullptr;
    const float* B2 = TWO ? gb.B2[bz] : nullptr;
    const float  s2 = TWO ? gb.s2[bz] : 1.f;
    float* C = gb.C[bz];

    const int row0 = blockIdx.y * 128;
    const int col0 = blockIdx.x * 128;
    const int warp = tid >> 5, lane = tid & 31;
    const int wm = (warp & 1) * 64;
    const int wn = (warp >> 1) * 32;
    const int g = lane >> 2, tig = lane & 3;

    // ldmatrix per-thread address components
    const uint32_t As_base = (uint32_t)__cvta_generic_to_shared(As);
    const uint32_t Bs_base = (uint32_t)__cvta_generic_to_shared(Bs);
    const int arow = (lane & 7) + ((lane >> 3) & 1) * 8;   // row within 16-row group
    const int akoff = (lane >> 4) * 4;                      // 0 or 4 floats (k half)
    const int brow = lane & 7;
    const int bkoff = ((lane >> 3) & 1) * 4;

    float c[4][4][4] = {};
    float4 ra[2], rb[2];
    float stage_sc = 1.f;
    const int nk = TWO ? 2 * K : K;

    auto load_stage = [&](int kt) {
        int p = TWO && (kt >= K);
        const float* Ap = p ? A2 : A1;
        const float* Bp = p ? B2 : B1;
        int kk = kt - (p ? K : 0);
        stage_sc = p ? s2 : 1.f;
        #pragma unroll
        for (int i = 0; i < 2; i++) {
            int idx = tid + i * 256;
            int r = idx >> 2, kq = (idx & 3) * 4;
            ra[i] = *(const float4*)(Ap + (size_t)(row0 + r) * lda + kk + kq);
        }
        if (TRANSB) {
            #pragma unroll
            for (int i = 0; i < 2; i++) {
                int idx = tid + i * 256;
                int n = idx >> 2, kq = (idx & 3) * 4;
                rb[i] = *(const float4*)(Bp + (size_t)(col0 + n) * ldb + kk + kq);
            }
        } else {
            #pragma unroll
            for (int i = 0; i < 2; i++) {
                int idx = tid + i * 256;
                int r = idx >> 5, nq = (idx & 31) * 4;
                rb[i] = *(const float4*)(Bp + (size_t)(kk + r) * ldb + col0 + nq);
            }
        }
    };

    load_stage(0);

    for (int kt = 0; kt < nk; kt += 16) {
        float sc = stage_sc;
        #pragma unroll
        for (int i = 0; i < 2; i++) {
            int idx = tid + i * 256;
            int r = idx >> 2, kq = (idx & 3) * 4;
            float4 cv;
            cv.x = to_tf32(ra[i].x); cv.y = to_tf32(ra[i].y);
            cv.z = to_tf32(ra[i].z); cv.w = to_tf32(ra[i].w);
            *(float4*)&As[r * AROW + kq] = cv;
        }
        if (TRANSB) {
            #pragma unroll
            for (int i = 0; i < 2; i++) {
                int idx = tid + i * 256;
                int n = idx >> 2, kq = (idx & 3) * 4;
                float4 cv;
                cv.x = to_tf32(rb[i].x * sc); cv.y = to_tf32(rb[i].y * sc);
                cv.z = to_tf32(rb[i].z * sc); cv.w = to_tf32(rb[i].w * sc);
                *(float4*)&Bs[n * AROW + kq] = cv;
            }
        } else {
            #pragma unroll
            for (int i = 0; i < 2; i++) {
                int idx = tid + i * 256;
                int r = idx >> 5, nq = (idx & 31) * 4;
                float4 cv;
                cv.x = to_tf32(rb[i].x * sc); cv.y = to_tf32(rb[i].y * sc);
                cv.z = to_tf32(rb[i].z * sc); cv.w = to_tf32(rb[i].w * sc);
                *(float4*)&Bs[r * 136 + nq] = cv;
            }
        }
        __syncthreads();

        if (kt + 16 < nk) load_stage(kt + 16);

        #pragma unroll
        for (int kc = 0; kc < 2; kc++) {
            uint32_t a[4][4], b[4][2];
            #pragma unroll
            for (int mi = 0; mi < 4; mi++) {
                uint32_t addr = As_base +
                    (uint32_t)(((wm + mi * 16 + arow) * AROW + kc * 8 + akoff) * 4);
                ldsm_x4(a[mi], addr);
            }
            if (TRANSB) {
                #pragma unroll
                for (int ni = 0; ni < 4; ni++) {
                    uint32_t addr = Bs_base +
                        (uint32_t)(((wn + ni * 8 + brow) * AROW + kc * 8 + bkoff) * 4);
                    ldsm_x2(b[ni], addr);
                }
            } else {
                const int kb = kc * 8;
                #pragma unroll
                for (int ni = 0; ni < 4; ni++) {
                    int n = wn + ni * 8 + g;
                    b[ni][0] = __float_as_uint(Bs[(kb + tig) * 136 + n]);
                    b[ni][1] = __float_as_uint(Bs[(kb + tig + 4) * 136 + n]);
                }
            }
            #pragma unroll
            for (int mi = 0; mi < 4; mi++)
                #pragma unroll
                for (int ni = 0; ni < 4; ni++)
                    mma_tf32(c[mi][ni], a[mi], b[ni]);
        }
        __syncthreads();
    }

    #pragma unroll
    for (int mi = 0; mi < 4; mi++) {
        int m0 = row0 + wm + mi * 16 + g;
        #pragma unroll
        for (int ni = 0; ni < 4; ni++) {
            int n0 = col0 + wn + ni * 8 + tig * 2;
            #pragma unroll
            for (int jj = 0; jj < 4; jj++) {
                int m = m0 + (jj >> 1) * 8;
                int n = n0 + (jj & 1);
                C[(size_t)m * ldc + (size_t)n * cstride] = sign * c[mi][ni][jj];
            }
        }
    }
}

// ---------------- row softmax (scores pre-scaled), in-place on S ----------------
__global__ void softmax_kernel(float* __restrict__ S) {
    size_t base = ((size_t)blockIdx.y * SEQ + blockIdx.x) * SEQ;
    float4* row = (float4*)(S + base);
    int t = threadIdx.x;
    float4 v0 = row[t], v1 = row[t + 256];
    float m = fmaxf(fmaxf(fmaxf(v0.x, v0.y), fmaxf(v0.z, v0.w)),
                    fmaxf(fmaxf(v1.x, v1.y), fmaxf(v1.z, v1.w)));
    #pragma unroll
    for (int o = 16; o > 0; o >>= 1) m = fmaxf(m, __shfl_xor_sync(0xffffffffu, m, o));
    __shared__ float red[8];
    if ((t & 31) == 0) red[t >> 5] = m;
    __syncthreads();
    m = red[0];
    #pragma unroll
    for (int i = 1; i < 8; i++) m = fmaxf(m, red[i]);

    v0.x = expf(v0.x - m); v0.y = expf(v0.y - m); v0.z = expf(v0.z - m); v0.w = expf(v0.w - m);
    v1.x = expf(v1.x - m); v1.y = expf(v1.y - m); v1.z = expf(v1.z - m); v1.w = expf(v1.w - m);
    float s = v0.x + v0.y + v0.z + v0.w + v1.x + v1.y + v1.z + v1.w;
    #pragma unroll
    for (int o = 16; o > 0; o >>= 1) s += __shfl_xor_sync(0xffffffffu, s, o);
    __syncthreads();
    if ((t & 31) == 0) red[t >> 5] = s;
    __syncthreads();
    s = red[0];
    #pragma unroll
    for (int i = 1; i < 8; i++) s += red[i];
    float inv = 1.0f / s;
    v0.x *= inv; v0.y *= inv; v0.z *= inv; v0.w *= inv;
    v1.x *= inv; v1.y *= inv; v1.z *= inv; v1.w *= inv;
    row[t] = v0; row[t + 256] = v1;
}

// ---------------- Wmi back-projection (complex, K=256) + head merge ----------------
__global__ void wmi_kernel(const float* __restrict__ Om_re, const float* __restrict__ Om_im,
                           const float* __restrict__ Wre, const float* __restrict__ Wim,
                           float* __restrict__ o_re, float* __restrict__ o_im) {
    __shared__ float sAr[16][64], sAi[16][64];
    __shared__ float4 sWr[64][16], sWi[64][16];
    int h = blockIdx.y;
    int s0 = blockIdx.x * 16;
    int tx = threadIdx.x, ty = threadIdx.y;
    int tid = ty * 16 + tx;
    const float4* Wre4 = (const float4*)Wre;
    const float4* Wim4 = (const float4*)Wim;
    float4 ar = make_float4(0,0,0,0), ai = make_float4(0,0,0,0);
    for (int kt = 0; kt < MAN; kt += 64) {
        #pragma unroll
        for (int i = 0; i < 4; i++) {
            int idx = tid + i * 256;
            int ss = idx >> 6, kk = idx & 63;
            size_t gg = (size_t)(s0 + ss) * DM2 + h * MAN + kt + kk;
            sAr[ss][kk] = Om_re[gg];
            sAi[ss][kk] = Om_im[gg];
            int wk = idx >> 4, dq = idx & 15;
            sWr[wk][dq] = Wre4[(size_t)(kt + wk) * 16 + dq];
            sWi[wk][dq] = Wim4[(size_t)(kt + wk) * 16 + dq];
        }
        __syncthreads();
        #pragma unroll
        for (int k = 0; k < 64; k++) {
            float xr = sAr[ty][k], xi = sAi[ty][k];
            float4 wr = sWr[k][tx], wi = sWi[k][tx];
            ar.x += xr*wr.x - xi*wi.x;  ai.x += xr*wi.x + xi*wr.x;
            ar.y += xr*wr.y - xi*wi.y;  ai.y += xr*wi.y + xi*wr.y;
            ar.z += xr*wr.z - xi*wi.z;  ai.z += xr*wi.z + xi*wr.z;
            ar.w += xr*wr.w - xi*wi.w;  ai.w += xr*wi.w + xi*wr.w;
        }
        __syncthreads();
    }
    size_t o = (size_t)(s0 + ty) * HID + h * HDIM;
    ((float4*)(o_re + o))[tx] = ar;
    ((float4*)(o_im + o))[tx] = ai;
}

// ---------------- launcher ----------------
extern "C" void kernel_launch(void* const* d_in, const int* in_sizes, int n_in,
                              void* d_out, int out_size) {
    const float* x      = (const float*)d_in[0];
    const float* Wq_re  = (const float*)d_in[1];
    const float* Wq_im  = (const float*)d_in[2];
    const float* Wk_re  = (const float*)d_in[3];
    const float* Wk_im  = (const float*)d_in[4];
    const float* Wv_re  = (const float*)d_in[5];
    const float* Wv_im  = (const float*)d_in[6];
    const float* Wm_re  = (const float*)d_in[7];
    const float* Wm_im  = (const float*)d_in[8];
    const float* Wmi_re = (const float*)d_in[9];
    const float* Wmi_im = (const float*)d_in[10];
    const float* Wo_re  = (const float*)d_in[11];
    const float* Wo_im  = (const float*)d_in[12];
    float* out = (float*)d_out;

    float *xn, *fq_re, *fq_im, *fk_re, *fk_im, *fv_re, *fv_im;
    float *Qre, *Qim, *Kre, *Kim, *Vre, *Vim, *S, *Om_re, *Om_im, *oh_re, *oh_im;
    cudaGetSymbolAddress((void**)&xn,    g_xn);
    cudaGetSymbolAddress((void**)&fq_re, g_fq_re);
    cudaGetSymbolAddress((void**)&fq_im, g_fq_im);
    cudaGetSymbolAddress((void**)&fk_re, g_fk_re);
    cudaGetSymbolAddress((void**)&fk_im, g_fk_im);
    cudaGetSymbolAddress((void**)&fv_re, g_fv_re);
    cudaGetSymbolAddress((void**)&fv_im, g_fv_im);
    cudaGetSymbolAddress((void**)&Qre,   g_Qre);
    cudaGetSymbolAddress((void**)&Qim,   g_Qim);
    cudaGetSymbolAddress((void**)&Kre,   g_Kre);
    cudaGetSymbolAddress((void**)&Kim,   g_Kim);
    cudaGetSymbolAddress((void**)&Vre,   g_Vre);
    cudaGetSymbolAddress((void**)&Vim,   g_Vim);
    cudaGetSymbolAddress((void**)&S,     g_S);
    cudaGetSymbolAddress((void**)&Om_re, g_Om_re);
    cudaGetSymbolAddress((void**)&Om_im, g_Om_im);
    cudaGetSymbolAddress((void**)&oh_re, g_oh_re);
    cudaGetSymbolAddress((void**)&oh_im, g_oh_im);

    norm_kernel<<<NROWS, 128>>>(x, xn);

    dim3 tb(256);

    // --- precompute fused QKV+manifold weights: Wxm = Wx_head @ Wm (complex), z=48 ---
    {
        GemmBatch gb{};
        const float* Wre_[3] = {Wq_re, Wk_re, Wv_re};
        const float* Wim_[3] = {Wq_im, Wk_im, Wv_im};
        float* Fre[3] = {fq_re, fk_re, fv_re};
        float* Fim[3] = {fq_im, fk_im, fv_im};
        int z = 0;
        for (int w = 0; w < 3; w++) {
            for (int h = 0; h < HEADS; h++) {
                gb.A1[z] = Wre_[w] + h * HDIM; gb.B1[z] = Wm_re;
                gb.A2[z] = Wim_[w] + h * HDIM; gb.B2[z] = Wm_im;
                gb.s2[z] = -1.f; gb.C[z] = Fre[w] + h * MAN; z++;
                gb.A1[z] = Wre_[w] + h * HDIM; gb.B1[z] = Wm_im;
                gb.A2[z] = Wim_[w] + h * HDIM; gb.B2[z] = Wm_re;
                gb.s2[z] = 1.f; gb.C[z] = Fim[w] + h * MAN; z++;
            }
        }
        gemm_tf32<0,1><<<dim3(MAN/128, HID/128, 48), tb>>>(gb, HDIM, HID, MAN, DM2, 1, 1.f);
    }

    // --- fused QKV+manifold: [4096,512] @ [512,2048], z=6 ---
    {
        GemmBatch gb{};
        const float* Bp[6] = {fq_re, fq_im, fk_re, fk_im, fv_re, fv_im};
        float* Cp[6] = {Qre, Qim, Kre, Kim, Vre, Vim};
        for (int i = 0; i < 6; i++) { gb.A1[i] = xn; gb.B1[i] = Bp[i]; gb.C[i] = Cp[i]; }
        gemm_tf32<0,0><<<dim3(DM2/128, NROWS/128, 6), tb>>>(gb, HID, HID, DM2, DM2, 1, 1.f);
    }

    // --- scores: S = SCALE * (Qre Kre^T + Qim Kim^T), z=16 ---
    {
        GemmBatch gb{};
        for (int z = 0; z < BH; z++) {
            int b = z >> 3, h = z & 7;
            size_t off = (size_t)b * SEQ * DM2 + (size_t)h * MAN;
            gb.A1[z] = Qre + off; gb.B1[z] = Kre + off;
            gb.A2[z] = Qim + off; gb.B2[z] = Kim + off;
            gb.s2[z] = 1.f;
            gb.C[z] = S + (size_t)z * SEQ * SEQ;
        }
        gemm_tf32<1,1><<<dim3(SEQ/128, SEQ/128, BH), tb>>>(gb, MAN, DM2, DM2, SEQ, 1, SCALE);
    }

    softmax_kernel<<<dim3(SEQ, BH), 256>>>(S);

    // --- PV: Om_re = P Vre, Om_im = P Vim, z=32 ---
    {
        GemmBatch gb{};
        for (int z = 0; z < BH; z++) {
            int b = z >> 3, h = z & 7;
            size_t off = (size_t)b * SEQ * DM2 + (size_t)h * MAN;
            gb.A1[z]      = S + (size_t)z * SEQ * SEQ;
            gb.B1[z]      = Vre + off;
            gb.C[z]       = Om_re + off;
            gb.A1[z + BH] = S + (size_t)z * SEQ * SEQ;
            gb.B1[z + BH] = Vim + off;
            gb.C[z + BH]  = Om_im + off;
        }
        gemm_tf32<0,0><<<dim3(MAN/128, SEQ/128, 2*BH), tb>>>(gb, SEQ, SEQ, DM2, DM2, 1, 1.f);
    }

    // --- Wmi back-projection + head merge ---
    wmi_kernel<<<dim3(NROWS/16, HEADS), dim3(16,16)>>>(Om_re, Om_im, Wmi_re, Wmi_im, oh_re, oh_im);

    // --- output projection: complex Wo, interleaved [.,512,2], z=2 ---
    {
        GemmBatch gb{};
        gb.A1[0] = oh_re; gb.B1[0] = Wo_re; gb.A2[0] = oh_im; gb.B2[0] = Wo_im;
        gb.s2[0] = -1.f;  gb.C[0] = out;
        gb.A1[1] = oh_re; gb.B1[1] = Wo_im; gb.A2[1] = oh_im; gb.B2[1] = Wo_re;
        gb.s2[1] = 1.f;   gb.C[1] = out + 1;
        gemm_tf32<0,1><<<dim3(HID/128, NROWS/128, 2), tb>>>(gb, HID, HID, HID, 2*HID, 2, 1.f);
    }
}

// round 9
// speedup vs baseline: 2.0626x; 1.0561x over previous
#include <cuda_runtime.h>
#include <cuda_bf16.h>
#include <cstdint>

#define BATCH 2
#define SEQ   2048
#define HID   512
#define HEADS 8
#define HDIM  64
#define MAN   256
#define DM2   2048           // HEADS*MAN
#define NROWS (BATCH*SEQ)    // 4096
#define BH    (BATCH*HEADS)  // 16
#define SCALE 0.125f         // 64^-0.5

#define AROW 20              // padded smem row (floats): conflict-free ldmatrix

// ---------------- scratch (device globals; no allocations) ----------------
__device__ float g_xn[NROWS * HID];
__device__ float g_fq_re[HID * DM2];
__device__ float g_fq_im[HID * DM2];
__device__ float g_fk_re[HID * DM2];
__device__ float g_fk_im[HID * DM2];
__device__ float g_fv_re[HID * DM2];
__device__ float g_fv_im[HID * DM2];
__device__ float g_Qre[(size_t)NROWS * DM2];
__device__ float g_Qim[(size_t)NROWS * DM2];
__device__ float g_Kre[(size_t)NROWS * DM2];
__device__ float g_Kim[(size_t)NROWS * DM2];
__device__ float g_Vre[(size_t)NROWS * DM2];
__device__ float g_Vim[(size_t)NROWS * DM2];
__device__ float g_S[(size_t)BH * SEQ * SEQ];   // 268 MB
__device__ float g_Om_re[(size_t)NROWS * DM2];
__device__ float g_Om_im[(size_t)NROWS * DM2];
__device__ float g_oh_re[NROWS * HID];
__device__ float g_oh_im[NROWS * HID];

#define MAXB 48
struct GemmBatch {
    const float* A1[MAXB];
    const float* B1[MAXB];
    const float* A2[MAXB];
    const float* B2[MAXB];
    float*       C[MAXB];
    float        s2[MAXB];
};

// ---------------- helpers ----------------
__device__ __forceinline__ float to_tf32(float x) {
    asm("cvt.rna.tf32.f32 %0, %1;" : "=f"(x) : "f"(x));
    return x;
}
__device__ __forceinline__ void mma_tf32(float c[4], const uint32_t a[4], const uint32_t b[2]) {
    asm volatile(
        "mma.sync.aligned.m16n8k8.row.col.f32.tf32.tf32.f32 "
        "{%0,%1,%2,%3},{%4,%5,%6,%7},{%8,%9},{%0,%1,%2,%3};"
        : "+f"(c[0]), "+f"(c[1]), "+f"(c[2]), "+f"(c[3])
        : "r"(a[0]), "r"(a[1]), "r"(a[2]), "r"(a[3]), "r"(b[0]), "r"(b[1]));
}
__device__ __forceinline__ void ldsm_x4(uint32_t r[4], uint32_t addr) {
    asm volatile("ldmatrix.sync.aligned.m8n8.x4.shared.b16 {%0,%1,%2,%3}, [%4];"
        : "=r"(r[0]), "=r"(r[1]), "=r"(r[2]), "=r"(r[3]) : "r"(addr));
}

// ---------------- row L2-normalize ----------------
__global__ void norm_kernel(const float* __restrict__ x, float* __restrict__ xn) {
    int row = blockIdx.x;
    int t = threadIdx.x;
    const float4* xr = (const float4*)(x + (size_t)row * HID);
    float4 v = xr[t];
    float ss = v.x*v.x + v.y*v.y + v.z*v.z + v.w*v.w;
    #pragma unroll
    for (int o = 16; o > 0; o >>= 1) ss += __shfl_xor_sync(0xffffffffu, ss, o);
    __shared__ float ws[4];
    if ((t & 31) == 0) ws[t >> 5] = ss;
    __syncthreads();
    float tot = ws[0] + ws[1] + ws[2] + ws[3];
    float inv = 1.0f / sqrtf(tot);
    v.x *= inv; v.y *= inv; v.z *= inv; v.w *= inv;
    ((float4*)(xn + (size_t)row * HID))[t] = v;
}

// ---------------- tf32 tensor-core GEMM (64x64 warp tiles, 128 threads) ----------------
// 128x128 CTA tile, BK=16, 4 warps (2x2), 64x64 per warp.
// A smem: [128 rows][AROW floats] -> ldmatrix.x4 frags.
// TRANSB=1: B smem same padded layout -> ldmatrix.x4 (two n-subtiles per instr).
// TRANSB=0: B smem [16][136] -> scalar LDS.
// TWO=1: C = sign * (A1@B1 + s2[z] * A2@B2), each product depth K.
template<int TRANSB, int TWO>
__global__ __launch_bounds__(128)
void gemm_tf32(GemmBatch gb, int K, int lda, int ldb, int ldc, int cstride, float sign) {
    __shared__ alignas(16) float As[128 * AROW];
    __shared__ alignas(16) float Bs[TRANSB ? 128 * AROW : 16 * 136];

    const int tid = threadIdx.x;
    const int bz = blockIdx.z;
    const float* A1 = gb.A1[bz];
    const float* B1 = gb.B1[bz];
    const float* A2 = TWO ? gb.A2[bz] : nullptr;
    const float* B2 = TWO ? gb.B2[bz] : nullptr;
    const float  s2 = TWO ? gb.s2[bz] : 1.f;
    float* C = gb.C[bz];

    const int row0 = blockIdx.y * 128;
    const int col0 = blockIdx.x * 128;
    const int warp = tid >> 5, lane = tid & 31;
    const int wm = (warp & 1) * 64;
    const int wn = (warp >> 1) * 64;
    const int g = lane >> 2, tig = lane & 3;

    const uint32_t As_base = (uint32_t)__cvta_generic_to_shared(As);
    const uint32_t Bs_base = (uint32_t)__cvta_generic_to_shared(Bs);
    const int arow = (lane & 7) + ((lane >> 3) & 1) * 8;   // row within 16-row group
    const int akoff = (lane >> 4) * 4;                      // 0 or 4 floats (k half)

    float c[4][8][4] = {};
    float4 ra[4], rb[4];
    float stage_sc = 1.f;
    const int nk = TWO ? 2 * K : K;

    auto load_stage = [&](int kt) {
        int p = TWO && (kt >= K);
        const float* Ap = p ? A2 : A1;
        const float* Bp = p ? B2 : B1;
        int kk = kt - (p ? K : 0);
        stage_sc = p ? s2 : 1.f;
        #pragma unroll
        for (int i = 0; i < 4; i++) {
            int idx = tid + i * 128;
            int r = idx >> 2, kq = (idx & 3) * 4;
            ra[i] = *(const float4*)(Ap + (size_t)(row0 + r) * lda + kk + kq);
        }
        if (TRANSB) {
            #pragma unroll
            for (int i = 0; i < 4; i++) {
                int idx = tid + i * 128;
                int n = idx >> 2, kq = (idx & 3) * 4;
                rb[i] = *(const float4*)(Bp + (size_t)(col0 + n) * ldb + kk + kq);
            }
        } else {
            #pragma unroll
            for (int i = 0; i < 4; i++) {
                int idx = tid + i * 128;
                int r = idx >> 5, nq = (idx & 31) * 4;
                rb[i] = *(const float4*)(Bp + (size_t)(kk + r) * ldb + col0 + nq);
            }
        }
    };

    load_stage(0);

    for (int kt = 0; kt < nk; kt += 16) {
        float sc = stage_sc;
        #pragma unroll
        for (int i = 0; i < 4; i++) {
            int idx = tid + i * 128;
            int r = idx >> 2, kq = (idx & 3) * 4;
            float4 cv;
            cv.x = to_tf32(ra[i].x); cv.y = to_tf32(ra[i].y);
            cv.z = to_tf32(ra[i].z); cv.w = to_tf32(ra[i].w);
            *(float4*)&As[r * AROW + kq] = cv;
        }
        if (TRANSB) {
            #pragma unroll
            for (int i = 0; i < 4; i++) {
                int idx = tid + i * 128;
                int n = idx >> 2, kq = (idx & 3) * 4;
                float4 cv;
                cv.x = to_tf32(rb[i].x * sc); cv.y = to_tf32(rb[i].y * sc);
                cv.z = to_tf32(rb[i].z * sc); cv.w = to_tf32(rb[i].w * sc);
                *(float4*)&Bs[n * AROW + kq] = cv;
            }
        } else {
            #pragma unroll
            for (int i = 0; i < 4; i++) {
                int idx = tid + i * 128;
                int r = idx >> 5, nq = (idx & 31) * 4;
                float4 cv;
                cv.x = to_tf32(rb[i].x * sc); cv.y = to_tf32(rb[i].y * sc);
                cv.z = to_tf32(rb[i].z * sc); cv.w = to_tf32(rb[i].w * sc);
                *(float4*)&Bs[r * 136 + nq] = cv;
            }
        }
        __syncthreads();

        if (kt + 16 < nk) load_stage(kt + 16);

        #pragma unroll
        for (int kc = 0; kc < 2; kc++) {
            uint32_t a[4][4], b[8][2];
            #pragma unroll
            for (int mi = 0; mi < 4; mi++) {
                uint32_t addr = As_base +
                    (uint32_t)(((wm + mi * 16 + arow) * AROW + kc * 8 + akoff) * 4);
                ldsm_x4(a[mi], addr);
            }
            if (TRANSB) {
                #pragma unroll
                for (int nj = 0; nj < 4; nj++) {
                    uint32_t r4[4];
                    uint32_t addr = Bs_base +
                        (uint32_t)(((wn + nj * 16 + arow) * AROW + kc * 8 + akoff) * 4);
                    ldsm_x4(r4, addr);
                    b[2*nj][0]   = r4[0]; b[2*nj][1]   = r4[2];
                    b[2*nj+1][0] = r4[1]; b[2*nj+1][1] = r4[3];
                }
            } else {
                const int kb = kc * 8;
                #pragma unroll
                for (int ni = 0; ni < 8; ni++) {
                    int n = wn + ni * 8 + g;
                    b[ni][0] = __float_as_uint(Bs[(kb + tig) * 136 + n]);
                    b[ni][1] = __float_as_uint(Bs[(kb + tig + 4) * 136 + n]);
                }
            }
            #pragma unroll
            for (int mi = 0; mi < 4; mi++)
                #pragma unroll
                for (int ni = 0; ni < 8; ni++)
                    mma_tf32(c[mi][ni], a[mi], b[ni]);
        }
        __syncthreads();
    }

    if (cstride == 1) {
        #pragma unroll
        for (int mi = 0; mi < 4; mi++) {
            int m0 = row0 + wm + mi * 16 + g;
            #pragma unroll
            for (int ni = 0; ni < 8; ni++) {
                int n0 = col0 + wn + ni * 8 + tig * 2;
                #pragma unroll
                for (int half = 0; half < 2; half++) {
                    int m = m0 + half * 8;
                    float2 v = make_float2(sign * c[mi][ni][half * 2],
                                           sign * c[mi][ni][half * 2 + 1]);
                    *(float2*)(C + (size_t)m * ldc + n0) = v;
                }
            }
        }
    } else {
        #pragma unroll
        for (int mi = 0; mi < 4; mi++) {
            int m0 = row0 + wm + mi * 16 + g;
            #pragma unroll
            for (int ni = 0; ni < 8; ni++) {
                int n0 = col0 + wn + ni * 8 + tig * 2;
                #pragma unroll
                for (int jj = 0; jj < 4; jj++) {
                    int m = m0 + (jj >> 1) * 8;
                    int n = n0 + (jj & 1);
                    C[(size_t)m * ldc + (size_t)n * cstride] = sign * c[mi][ni][jj];
                }
            }
        }
    }
}

// ---------------- row softmax (scores pre-scaled), in-place on S ----------------
__global__ void softmax_kernel(float* __restrict__ S) {
    size_t base = ((size_t)blockIdx.y * SEQ + blockIdx.x) * SEQ;
    float4* row = (float4*)(S + base);
    int t = threadIdx.x;
    float4 v0 = row[t], v1 = row[t + 256];
    float m = fmaxf(fmaxf(fmaxf(v0.x, v0.y), fmaxf(v0.z, v0.w)),
                    fmaxf(fmaxf(v1.x, v1.y), fmaxf(v1.z, v1.w)));
    #pragma unroll
    for (int o = 16; o > 0; o >>= 1) m = fmaxf(m, __shfl_xor_sync(0xffffffffu, m, o));
    __shared__ float red[8];
    if ((t & 31) == 0) red[t >> 5] = m;
    __syncthreads();
    m = red[0];
    #pragma unroll
    for (int i = 1; i < 8; i++) m = fmaxf(m, red[i]);

    v0.x = expf(v0.x - m); v0.y = expf(v0.y - m); v0.z = expf(v0.z - m); v0.w = expf(v0.w - m);
    v1.x = expf(v1.x - m); v1.y = expf(v1.y - m); v1.z = expf(v1.z - m); v1.w = expf(v1.w - m);
    float s = v0.x + v0.y + v0.z + v0.w + v1.x + v1.y + v1.z + v1.w;
    #pragma unroll
    for (int o = 16; o > 0; o >>= 1) s += __shfl_xor_sync(0xffffffffu, s, o);
    __syncthreads();
    if ((t & 31) == 0) red[t >> 5] = s;
    __syncthreads();
    s = red[0];
    #pragma unroll
    for (int i = 1; i < 8; i++) s += red[i];
    float inv = 1.0f / s;
    v0.x *= inv; v0.y *= inv; v0.z *= inv; v0.w *= inv;
    v1.x *= inv; v1.y *= inv; v1.z *= inv; v1.w *= inv;
    row[t] = v0; row[t + 256] = v1;
}

// ---------------- Wmi back-projection (complex, K=256) + head merge ----------------
__global__ void wmi_kernel(const float* __restrict__ Om_re, const float* __restrict__ Om_im,
                           const float* __restrict__ Wre, const float* __restrict__ Wim,
                           float* __restrict__ o_re, float* __restrict__ o_im) {
    __shared__ float sAr[16][64], sAi[16][64];
    __shared__ float4 sWr[64][16], sWi[64][16];
    int h = blockIdx.y;
    int s0 = blockIdx.x * 16;
    int tx = threadIdx.x, ty = threadIdx.y;
    int tid = ty * 16 + tx;
    const float4* Wre4 = (const float4*)Wre;
    const float4* Wim4 = (const float4*)Wim;
    float4 ar = make_float4(0,0,0,0), ai = make_float4(0,0,0,0);
    for (int kt = 0; kt < MAN; kt += 64) {
        #pragma unroll
        for (int i = 0; i < 4; i++) {
            int idx = tid + i * 256;
            int ss = idx >> 6, kk = idx & 63;
            size_t gg = (size_t)(s0 + ss) * DM2 + h * MAN + kt + kk;
            sAr[ss][kk] = Om_re[gg];
            sAi[ss][kk] = Om_im[gg];
            int wk = idx >> 4, dq = idx & 15;
            sWr[wk][dq] = Wre4[(size_t)(kt + wk) * 16 + dq];
            sWi[wk][dq] = Wim4[(size_t)(kt + wk) * 16 + dq];
        }
        __syncthreads();
        #pragma unroll
        for (int k = 0; k < 64; k++) {
            float xr = sAr[ty][k], xi = sAi[ty][k];
            float4 wr = sWr[k][tx], wi = sWi[k][tx];
            ar.x += xr*wr.x - xi*wi.x;  ai.x += xr*wi.x + xi*wr.x;
            ar.y += xr*wr.y - xi*wi.y;  ai.y += xr*wi.y + xi*wr.y;
            ar.z += xr*wr.z - xi*wi.z;  ai.z += xr*wi.z + xi*wr.z;
            ar.w += xr*wr.w - xi*wi.w;  ai.w += xr*wi.w + xi*wr.w;
        }
        __syncthreads();
    }
    size_t o = (size_t)(s0 + ty) * HID + h * HDIM;
    ((float4*)(o_re + o))[tx] = ar;
    ((float4*)(o_im + o))[tx] = ai;
}

// ---------------- launcher ----------------
extern "C" void kernel_launch(void* const* d_in, const int* in_sizes, int n_in,
                              void* d_out, int out_size) {
    const float* x      = (const float*)d_in[0];
    const float* Wq_re  = (const float*)d_in[1];
    const float* Wq_im  = (const float*)d_in[2];
    const float* Wk_re  = (const float*)d_in[3];
    const float* Wk_im  = (const float*)d_in[4];
    const float* Wv_re  = (const float*)d_in[5];
    const float* Wv_im  = (const float*)d_in[6];
    const float* Wm_re  = (const float*)d_in[7];
    const float* Wm_im  = (const float*)d_in[8];
    const float* Wmi_re = (const float*)d_in[9];
    const float* Wmi_im = (const float*)d_in[10];
    const float* Wo_re  = (const float*)d_in[11];
    const float* Wo_im  = (const float*)d_in[12];
    float* out = (float*)d_out;

    float *xn, *fq_re, *fq_im, *fk_re, *fk_im, *fv_re, *fv_im;
    float *Qre, *Qim, *Kre, *Kim, *Vre, *Vim, *S, *Om_re, *Om_im, *oh_re, *oh_im;
    cudaGetSymbolAddress((void**)&xn,    g_xn);
    cudaGetSymbolAddress((void**)&fq_re, g_fq_re);
    cudaGetSymbolAddress((void**)&fq_im, g_fq_im);
    cudaGetSymbolAddress((void**)&fk_re, g_fk_re);
    cudaGetSymbolAddress((void**)&fk_im, g_fk_im);
    cudaGetSymbolAddress((void**)&fv_re, g_fv_re);
    cudaGetSymbolAddress((void**)&fv_im, g_fv_im);
    cudaGetSymbolAddress((void**)&Qre,   g_Qre);
    cudaGetSymbolAddress((void**)&Qim,   g_Qim);
    cudaGetSymbolAddress((void**)&Kre,   g_Kre);
    cudaGetSymbolAddress((void**)&Kim,   g_Kim);
    cudaGetSymbolAddress((void**)&Vre,   g_Vre);
    cudaGetSymbolAddress((void**)&Vim,   g_Vim);
    cudaGetSymbolAddress((void**)&S,     g_S);
    cudaGetSymbolAddress((void**)&Om_re, g_Om_re);
    cudaGetSymbolAddress((void**)&Om_im, g_Om_im);
    cudaGetSymbolAddress((void**)&oh_re, g_oh_re);
    cudaGetSymbolAddress((void**)&oh_im, g_oh_im);

    norm_kernel<<<NROWS, 128>>>(x, xn);

    dim3 tb(128);

    // --- precompute fused QKV+manifold weights: Wxm = Wx_head @ Wm (complex), z=48 ---
    {
        GemmBatch gb{};
        const float* Wre_[3] = {Wq_re, Wk_re, Wv_re};
        const float* Wim_[3] = {Wq_im, Wk_im, Wv_im};
        float* Fre[3] = {fq_re, fk_re, fv_re};
        float* Fim[3] = {fq_im, fk_im, fv_im};
        int z = 0;
        for (int w = 0; w < 3; w++) {
            for (int h = 0; h < HEADS; h++) {
                gb.A1[z] = Wre_[w] + h * HDIM; gb.B1[z] = Wm_re;
                gb.A2[z] = Wim_[w] + h * HDIM; gb.B2[z] = Wm_im;
                gb.s2[z] = -1.f; gb.C[z] = Fre[w] + h * MAN; z++;
                gb.A1[z] = Wre_[w] + h * HDIM; gb.B1[z] = Wm_im;
                gb.A2[z] = Wim_[w] + h * HDIM; gb.B2[z] = Wm_re;
                gb.s2[z] = 1.f; gb.C[z] = Fim[w] + h * MAN; z++;
            }
        }
        gemm_tf32<0,1><<<dim3(MAN/128, HID/128, 48), tb>>>(gb, HDIM, HID, MAN, DM2, 1, 1.f);
    }

    // --- fused QKV+manifold: [4096,512] @ [512,2048], z=6 ---
    {
        GemmBatch gb{};
        const float* Bp[6] = {fq_re, fq_im, fk_re, fk_im, fv_re, fv_im};
        float* Cp[6] = {Qre, Qim, Kre, Kim, Vre, Vim};
        for (int i = 0; i < 6; i++) { gb.A1[i] = xn; gb.B1[i] = Bp[i]; gb.C[i] = Cp[i]; }
        gemm_tf32<0,0><<<dim3(DM2/128, NROWS/128, 6), tb>>>(gb, HID, HID, DM2, DM2, 1, 1.f);
    }

    // --- scores: S = SCALE * (Qre Kre^T + Qim Kim^T), z=16 ---
    {
        GemmBatch gb{};
        for (int z = 0; z < BH; z++) {
            int b = z >> 3, h = z & 7;
            size_t off = (size_t)b * SEQ * DM2 + (size_t)h * MAN;
            gb.A1[z] = Qre + off; gb.B1[z] = Kre + off;
            gb.A2[z] = Qim + off; gb.B2[z] = Kim + off;
            gb.s2[z] = 1.f;
            gb.C[z] = S + (size_t)z * SEQ * SEQ;
        }
        gemm_tf32<1,1><<<dim3(SEQ/128, SEQ/128, BH), tb>>>(gb, MAN, DM2, DM2, SEQ, 1, SCALE);
    }

    softmax_kernel<<<dim3(SEQ, BH), 256>>>(S);

    // --- PV: Om_re = P Vre, Om_im = P Vim, z=32 ---
    {
        GemmBatch gb{};
        for (int z = 0; z < BH; z++) {
            int b = z >> 3, h = z & 7;
            size_t off = (size_t)b * SEQ * DM2 + (size_t)h * MAN;
            gb.A1[z]      = S + (size_t)z * SEQ * SEQ;
            gb.B1[z]      = Vre + off;
            gb.C[z]       = Om_re + off;
            gb.A1[z + BH] = S + (size_t)z * SEQ * SEQ;
            gb.B1[z + BH] = Vim + off;
            gb.C[z + BH]  = Om_im + off;
        }
        gemm_tf32<0,0><<<dim3(MAN/128, SEQ/128, 2*BH), tb>>>(gb, SEQ, SEQ, DM2, DM2, 1, 1.f);
    }

    // --- Wmi back-projection + head merge ---
    wmi_kernel<<<dim3(NROWS/16, HEADS), dim3(16,16)>>>(Om_re, Om_im, Wmi_re, Wmi_im, oh_re, oh_im);

    // --- output projection: complex Wo, interleaved [.,512,2], z=2 ---
    {
        GemmBatch gb{};
        gb.A1[0] = oh_re; gb.B1[0] = Wo_re; gb.A2[0] = oh_im; gb.B2[0] = Wo_im;
        gb.s2[0] = -1.f;  gb.C[0] = out;
        gb.A1[1] = oh_re; gb.B1[1] = Wo_im; gb.A2[1] = oh_im; gb.B2[1] = Wo_re;
        gb.s2[1] = 1.f;   gb.C[1] = out + 1;
        gemm_tf32<0,1><<<dim3(HID/128, NROWS/128, 2), tb>>>(gb, HID, HID, HID, 2*HID, 2, 1.f);
    }
}

// round 12
// speedup vs baseline: 2.2262x; 1.0793x over previous
#include <cuda_runtime.h>
#include <cuda_bf16.h>
#include <cstdint>

#define BATCH 2
#define SEQ   2048
#define HID   512
#define HEADS 8
#define HDIM  64
#define MAN   256
#define DM2   2048           // HEADS*MAN
#define NROWS (BATCH*SEQ)    // 4096
#define BH    (BATCH*HEADS)  // 16
#define SCALE 0.125f         // 64^-0.5

#define AROW 20              // padded smem row (floats): conflict-free ldmatrix
#define STAGES 4
#define ASZ (128*AROW)       // floats per A stage
#define BSZ0 (16*136)        // floats per B stage (NN)

// ---------------- scratch (device globals; no allocations) ----------------
__device__ float g_xn[NROWS * HID];
__device__ float g_fq_re[HID * DM2];
__device__ float g_fq_im[HID * DM2];
__device__ float g_fk_re[HID * DM2];
__device__ float g_fk_im[HID * DM2];
__device__ float g_fv_re[HID * DM2];
__device__ float g_fv_im[HID * DM2];
__device__ float g_Qre[(size_t)NROWS * DM2];
__device__ float g_Qim[(size_t)NROWS * DM2];
__device__ float g_Kre[(size_t)NROWS * DM2];
__device__ float g_Kim[(size_t)NROWS * DM2];
__device__ float g_Vre[(size_t)NROWS * DM2];
__device__ float g_Vim[(size_t)NROWS * DM2];
__device__ float g_S[(size_t)BH * SEQ * SEQ];   // 268 MB
__device__ float g_Om_re[(size_t)NROWS * DM2];
__device__ float g_Om_im[(size_t)NROWS * DM2];
__device__ float g_oh_re[NROWS * HID];
__device__ float g_oh_im[NROWS * HID];
// pre-rounded (tf32) weight copies
__device__ float g_rWq_re[HID * HID];
__device__ float g_rWq_im[HID * HID];
__device__ float g_rWk_re[HID * HID];
__device__ float g_rWk_im[HID * HID];
__device__ float g_rWv_re[HID * HID];
__device__ float g_rWv_im[HID * HID];
__device__ float g_rWm_re[HDIM * MAN];
__device__ float g_rWm_im[HDIM * MAN];
__device__ float g_rWm_imn[HDIM * MAN];
__device__ float g_rWo_re[HID * HID];
__device__ float g_rWo_im[HID * HID];
__device__ float g_rWo_imn[HID * HID];

#define MAXB 48
struct GemmBatch {
    const float* A1[MAXB];
    const float* B1[MAXB];
    const float* A2[MAXB];
    const float* B2[MAXB];
    float*       C[MAXB];
};
#define NPREP 10
struct PrepBatch {
    const float* src[NPREP];
    float* dst[NPREP];
    float* neg[NPREP];
    int n[NPREP];
};

// ---------------- helpers ----------------
__device__ __forceinline__ float to_tf32(float x) {
    asm("cvt.rna.tf32.f32 %0, %1;" : "=f"(x) : "f"(x));
    return x;
}
__device__ __forceinline__ void mma_tf32(float c[4], const uint32_t a[4], const uint32_t b[2]) {
    asm volatile(
        "mma.sync.aligned.m16n8k8.row.col.f32.tf32.tf32.f32 "
        "{%0,%1,%2,%3},{%4,%5,%6,%7},{%8,%9},{%0,%1,%2,%3};"
        : "+f"(c[0]), "+f"(c[1]), "+f"(c[2]), "+f"(c[3])
        : "r"(a[0]), "r"(a[1]), "r"(a[2]), "r"(a[3]), "r"(b[0]), "r"(b[1]));
}
__device__ __forceinline__ void ldsm_x4(uint32_t r[4], uint32_t addr) {
    asm volatile("ldmatrix.sync.aligned.m8n8.x4.shared.b16 {%0,%1,%2,%3}, [%4];"
        : "=r"(r[0]), "=r"(r[1]), "=r"(r[2]), "=r"(r[3]) : "r"(addr));
}
__device__ __forceinline__ void cp_async16(uint32_t dst, const float* src) {
    asm volatile("cp.async.cg.shared.global [%0], [%1], 16;" :: "r"(dst), "l"(src));
}
__device__ __forceinline__ void cp_commit() {
    asm volatile("cp.async.commit_group;");
}
template<int N>
__device__ __forceinline__ void cp_wait() {
    asm volatile("cp.async.wait_group %0;" :: "n"(N));
}

// ---------------- prep: tf32-round (and negate) weight inputs ----------------
__global__ void prep_kernel(PrepBatch pb) {
    int e = blockIdx.y;
    const float* s = pb.src[e];
    float* d = pb.dst[e];
    float* dn = pb.neg[e];
    int n = pb.n[e];
    for (int i = blockIdx.x * blockDim.x + threadIdx.x; i < n; i += gridDim.x * blockDim.x) {
        float v = to_tf32(s[i]);
        d[i] = v;
        if (dn) dn[i] = -v;
    }
}

// ---------------- row L2-normalize (tf32-rounded output) ----------------
__global__ void norm_kernel(const float* __restrict__ x, float* __restrict__ xn) {
    int row = blockIdx.x;
    int t = threadIdx.x;
    const float4* xr = (const float4*)(x + (size_t)row * HID);
    float4 v = xr[t];
    float ss = v.x*v.x + v.y*v.y + v.z*v.z + v.w*v.w;
    #pragma unroll
    for (int o = 16; o > 0; o >>= 1) ss += __shfl_xor_sync(0xffffffffu, ss, o);
    __shared__ float ws[4];
    if ((t & 31) == 0) ws[t >> 5] = ss;
    __syncthreads();
    float tot = ws[0] + ws[1] + ws[2] + ws[3];
    float inv = 1.0f / sqrtf(tot);
    v.x = to_tf32(v.x * inv); v.y = to_tf32(v.y * inv);
    v.z = to_tf32(v.z * inv); v.w = to_tf32(v.w * inv);
    ((float4*)(xn + (size_t)row * HID))[t] = v;
}

// ---------------- tf32 tensor-core GEMM (cp.async 4-stage pipeline) ----------------
// 128x128 CTA tile, BK=16, 4 warps (2x2), 64x64 per warp.
// Inputs MUST be pre-rounded to tf32.  TWO=1: C = sign*(A1@B1 + A2@B2).
// ROUNDC=1: round C writes to tf32 (for tensors feeding later gemms).
template<int TRANSB, int TWO, int ROUNDC>
__global__ __launch_bounds__(128)
void gemm_tf32(GemmBatch gb, int K, int lda, int ldb, int ldc, int cstride, float sign) {
    extern __shared__ char dynsmem[];
    float* As = (float*)dynsmem;                              // STAGES*ASZ
    float* Bs = (float*)(dynsmem + STAGES * ASZ * 4);         // STAGES*(AROW-based or BSZ0)
    const int BSZ = TRANSB ? ASZ : BSZ0;

    const int tid = threadIdx.x;
    const int bz = blockIdx.z;
    const float* A1 = gb.A1[bz];
    const float* B1 = gb.B1[bz];
    const float* A2 = TWO ? gb.A2[bz] : nullptr;
    const float* B2 = TWO ? gb.B2[bz] : nullptr;
    float* C = gb.C[bz];

    const int row0 = blockIdx.y * 128;
    const int col0 = blockIdx.x * 128;
    const int warp = tid >> 5, lane = tid & 31;
    const int wm = (warp & 1) * 64;
    const int wn = (warp >> 1) * 64;
    const int g = lane >> 2, tig = lane & 3;

    const uint32_t As_u32 = (uint32_t)__cvta_generic_to_shared(As);
    const uint32_t Bs_u32 = (uint32_t)__cvta_generic_to_shared(Bs);
    const int arow = (lane & 7) + ((lane >> 3) & 1) * 8;   // row within 16-row group
    const int akoff = (lane >> 4) * 4;                      // 0 or 4 floats (k half)

    float c[4][8][4] = {};
    const int nk = TWO ? 2 * K : K;

    auto issue_stage = [&](int kt, int sbuf) {
        if (kt < nk) {
            int p = TWO && (kt >= K);
            const float* Ap = p ? A2 : A1;
            const float* Bp = p ? B2 : B1;
            int kk = kt - (p ? K : 0);
            uint32_t ab = As_u32 + (uint32_t)(sbuf * ASZ * 4);
            uint32_t bb = Bs_u32 + (uint32_t)(sbuf * BSZ * 4);
            #pragma unroll
            for (int i = 0; i < 4; i++) {
                int idx = tid + i * 128;
                int r = idx >> 2, kq = (idx & 3) * 4;
                cp_async16(ab + (uint32_t)((r * AROW + kq) * 4),
                           Ap + (size_t)(row0 + r) * lda + kk + kq);
            }
            if (TRANSB) {
                #pragma unroll
                for (int i = 0; i < 4; i++) {
                    int idx = tid + i * 128;
                    int n = idx >> 2, kq = (idx & 3) * 4;
                    cp_async16(bb + (uint32_t)((n * AROW + kq) * 4),
                               Bp + (size_t)(col0 + n) * ldb + kk + kq);
                }
            } else {
                #pragma unroll
                for (int i = 0; i < 4; i++) {
                    int idx = tid + i * 128;
                    int r = idx >> 5, nq = (idx & 31) * 4;
                    cp_async16(bb + (uint32_t)((r * 136 + nq) * 4),
                               Bp + (size_t)(kk + r) * ldb + col0 + nq);
                }
            }
        }
        cp_commit();
    };

    issue_stage(0, 0);
    issue_stage(16, 1);
    issue_stage(32, 2);

    for (int kt = 0; kt < nk; kt += 16) {
        const int s = (kt >> 4) & 3;
        cp_wait<2>();
        __syncthreads();
        issue_stage(kt + 48, (s + 3) & 3);

        #pragma unroll
        for (int kc = 0; kc < 2; kc++) {
            uint32_t a[4][4], b[8][2];
            #pragma unroll
            for (int mi = 0; mi < 4; mi++) {
                uint32_t addr = As_u32 +
                    (uint32_t)(((s * ASZ) + (wm + mi * 16 + arow) * AROW + kc * 8 + akoff) * 4);
                ldsm_x4(a[mi], addr);
            }
            if (TRANSB) {
                #pragma unroll
                for (int nj = 0; nj < 4; nj++) {
                    uint32_t r4[4];
                    uint32_t addr = Bs_u32 +
                        (uint32_t)(((s * ASZ) + (wn + nj * 16 + arow) * AROW + kc * 8 + akoff) * 4);
                    ldsm_x4(r4, addr);
                    b[2*nj][0]   = r4[0]; b[2*nj][1]   = r4[2];
                    b[2*nj+1][0] = r4[1]; b[2*nj+1][1] = r4[3];
                }
            } else {
                const int kb = kc * 8;
                #pragma unroll
                for (int ni = 0; ni < 8; ni++) {
                    int n = wn + ni * 8 + g;
                    b[ni][0] = __float_as_uint(Bs[s * BSZ0 + (kb + tig) * 136 + n]);
                    b[ni][1] = __float_as_uint(Bs[s * BSZ0 + (kb + tig + 4) * 136 + n]);
                }
            }
            #pragma unroll
            for (int mi = 0; mi < 4; mi++)
                #pragma unroll
                for (int ni = 0; ni < 8; ni++)
                    mma_tf32(c[mi][ni], a[mi], b[ni]);
        }
    }

    if (cstride == 1) {
        #pragma unroll
        for (int mi = 0; mi < 4; mi++) {
            int m0 = row0 + wm + mi * 16 + g;
            #pragma unroll
            for (int ni = 0; ni < 8; ni++) {
                int n0 = col0 + wn + ni * 8 + tig * 2;
                #pragma unroll
                for (int half = 0; half < 2; half++) {
                    int m = m0 + half * 8;
                    float vx = sign * c[mi][ni][half * 2];
                    float vy = sign * c[mi][ni][half * 2 + 1];
                    if (ROUNDC) { vx = to_tf32(vx); vy = to_tf32(vy); }
                    *(float2*)(C + (size_t)m * ldc + n0) = make_float2(vx, vy);
                }
            }
        }
    } else {
        #pragma unroll
        for (int mi = 0; mi < 4; mi++) {
            int m0 = row0 + wm + mi * 16 + g;
            #pragma unroll
            for (int ni = 0; ni < 8; ni++) {
                int n0 = col0 + wn + ni * 8 + tig * 2;
                #pragma unroll
                for (int jj = 0; jj < 4; jj++) {
                    int m = m0 + (jj >> 1) * 8;
                    int n = n0 + (jj & 1);
                    float v = sign * c[mi][ni][jj];
                    if (ROUNDC) v = to_tf32(v);
                    C[(size_t)m * ldc + (size_t)n * cstride] = v;
                }
            }
        }
    }
}

// ---------------- row softmax (scores pre-scaled), tf32-rounded output ----------------
__global__ void softmax_kernel(float* __restrict__ S) {
    size_t base = ((size_t)blockIdx.y * SEQ + blockIdx.x) * SEQ;
    float4* row = (float4*)(S + base);
    int t = threadIdx.x;
    float4 v0 = row[t], v1 = row[t + 256];
    float m = fmaxf(fmaxf(fmaxf(v0.x, v0.y), fmaxf(v0.z, v0.w)),
                    fmaxf(fmaxf(v1.x, v1.y), fmaxf(v1.z, v1.w)));
    #pragma unroll
    for (int o = 16; o > 0; o >>= 1) m = fmaxf(m, __shfl_xor_sync(0xffffffffu, m, o));
    __shared__ float red[8];
    if ((t & 31) == 0) red[t >> 5] = m;
    __syncthreads();
    m = red[0];
    #pragma unroll
    for (int i = 1; i < 8; i++) m = fmaxf(m, red[i]);

    v0.x = expf(v0.x - m); v0.y = expf(v0.y - m); v0.z = expf(v0.z - m); v0.w = expf(v0.w - m);
    v1.x = expf(v1.x - m); v1.y = expf(v1.y - m); v1.z = expf(v1.z - m); v1.w = expf(v1.w - m);
    float s = v0.x + v0.y + v0.z + v0.w + v1.x + v1.y + v1.z + v1.w;
    #pragma unroll
    for (int o = 16; o > 0; o >>= 1) s += __shfl_xor_sync(0xffffffffu, s, o);
    __syncthreads();
    if ((t & 31) == 0) red[t >> 5] = s;
    __syncthreads();
    s = red[0];
    #pragma unroll
    for (int i = 1; i < 8; i++) s += red[i];
    float inv = 1.0f / s;
    v0.x = to_tf32(v0.x * inv); v0.y = to_tf32(v0.y * inv);
    v0.z = to_tf32(v0.z * inv); v0.w = to_tf32(v0.w * inv);
    v1.x = to_tf32(v1.x * inv); v1.y = to_tf32(v1.y * inv);
    v1.z = to_tf32(v1.z * inv); v1.w = to_tf32(v1.w * inv);
    row[t] = v0; row[t + 256] = v1;
}

// ---------------- Wmi back-projection (complex, K=256) + head merge ----------------
__global__ void wmi_kernel(const float* __restrict__ Om_re, const float* __restrict__ Om_im,
                           const float* __restrict__ Wre, const float* __restrict__ Wim,
                           float* __restrict__ o_re, float* __restrict__ o_im) {
    __shared__ float sAr[16][64], sAi[16][64];
    __shared__ float4 sWr[64][16], sWi[64][16];
    int h = blockIdx.y;
    int s0 = blockIdx.x * 16;
    int tx = threadIdx.x, ty = threadIdx.y;
    int tid = ty * 16 + tx;
    const float4* Wre4 = (const float4*)Wre;
    const float4* Wim4 = (const float4*)Wim;
    float4 ar = make_float4(0,0,0,0), ai = make_float4(0,0,0,0);
    for (int kt = 0; kt < MAN; kt += 64) {
        #pragma unroll
        for (int i = 0; i < 4; i++) {
            int idx = tid + i * 256;
            int ss = idx >> 6, kk = idx & 63;
            size_t gg = (size_t)(s0 + ss) * DM2 + h * MAN + kt + kk;
            sAr[ss][kk] = Om_re[gg];
            sAi[ss][kk] = Om_im[gg];
            int wk = idx >> 4, dq = idx & 15;
            sWr[wk][dq] = Wre4[(size_t)(kt + wk) * 16 + dq];
            sWi[wk][dq] = Wim4[(size_t)(kt + wk) * 16 + dq];
        }
        __syncthreads();
        #pragma unroll
        for (int k = 0; k < 64; k++) {
            float xr = sAr[ty][k], xi = sAi[ty][k];
            float4 wr = sWr[k][tx], wi = sWi[k][tx];
            ar.x += xr*wr.x - xi*wi.x;  ai.x += xr*wi.x + xi*wr.x;
            ar.y += xr*wr.y - xi*wi.y;  ai.y += xr*wi.y + xi*wr.y;
            ar.z += xr*wr.z - xi*wi.z;  ai.z += xr*wi.z + xi*wr.z;
            ar.w += xr*wr.w - xi*wi.w;  ai.w += xr*wi.w + xi*wr.w;
        }
        __syncthreads();
    }
    ar.x = to_tf32(ar.x); ar.y = to_tf32(ar.y); ar.z = to_tf32(ar.z); ar.w = to_tf32(ar.w);
    ai.x = to_tf32(ai.x); ai.y = to_tf32(ai.y); ai.z = to_tf32(ai.z); ai.w = to_tf32(ai.w);
    size_t o = (size_t)(s0 + ty) * HID + h * HDIM;
    ((float4*)(o_re + o))[tx] = ar;
    ((float4*)(o_im + o))[tx] = ai;
}

// ---------------- launcher ----------------
extern "C" void kernel_launch(void* const* d_in, const int* in_sizes, int n_in,
                              void* d_out, int out_size) {
    const float* x      = (const float*)d_in[0];
    const float* Wq_re  = (const float*)d_in[1];
    const float* Wq_im  = (const float*)d_in[2];
    const float* Wk_re  = (const float*)d_in[3];
    const float* Wk_im  = (const float*)d_in[4];
    const float* Wv_re  = (const float*)d_in[5];
    const float* Wv_im  = (const float*)d_in[6];
    const float* Wm_re  = (const float*)d_in[7];
    const float* Wm_im  = (const float*)d_in[8];
    const float* Wmi_re = (const float*)d_in[9];
    const float* Wmi_im = (const float*)d_in[10];
    const float* Wo_re  = (const float*)d_in[11];
    const float* Wo_im  = (const float*)d_in[12];
    float* out = (float*)d_out;

    float *xn, *fq_re, *fq_im, *fk_re, *fk_im, *fv_re, *fv_im;
    float *Qre, *Qim, *Kre, *Kim, *Vre, *Vim, *S, *Om_re, *Om_im, *oh_re, *oh_im;
    float *rWq_re, *rWq_im, *rWk_re, *rWk_im, *rWv_re, *rWv_im;
    float *rWm_re, *rWm_im, *rWm_imn, *rWo_re, *rWo_im, *rWo_imn;
    cudaGetSymbolAddress((void**)&xn,    g_xn);
    cudaGetSymbolAddress((void**)&fq_re, g_fq_re);
    cudaGetSymbolAddress((void**)&fq_im, g_fq_im);
    cudaGetSymbolAddress((void**)&fk_re, g_fk_re);
    cudaGetSymbolAddress((void**)&fk_im, g_fk_im);
    cudaGetSymbolAddress((void**)&fv_re, g_fv_re);
    cudaGetSymbolAddress((void**)&fv_im, g_fv_im);
    cudaGetSymbolAddress((void**)&Qre,   g_Qre);
    cudaGetSymbolAddress((void**)&Qim,   g_Qim);
    cudaGetSymbolAddress((void**)&Kre,   g_Kre);
    cudaGetSymbolAddress((void**)&Kim,   g_Kim);
    cudaGetSymbolAddress((void**)&Vre,   g_Vre);
    cudaGetSymbolAddress((void**)&Vim,   g_Vim);
    cudaGetSymbolAddress((void**)&S,     g_S);
    cudaGetSymbolAddress((void**)&Om_re, g_Om_re);
    cudaGetSymbolAddress((void**)&Om_im, g_Om_im);
    cudaGetSymbolAddress((void**)&oh_re, g_oh_re);
    cudaGetSymbolAddress((void**)&oh_im, g_oh_im);
    cudaGetSymbolAddress((void**)&rWq_re, g_rWq_re);
    cudaGetSymbolAddress((void**)&rWq_im, g_rWq_im);
    cudaGetSymbolAddress((void**)&rWk_re, g_rWk_re);
    cudaGetSymbolAddress((void**)&rWk_im, g_rWk_im);
    cudaGetSymbolAddress((void**)&rWv_re, g_rWv_re);
    cudaGetSymbolAddress((void**)&rWv_im, g_rWv_im);
    cudaGetSymbolAddress((void**)&rWm_re, g_rWm_re);
    cudaGetSymbolAddress((void**)&rWm_im, g_rWm_im);
    cudaGetSymbolAddress((void**)&rWm_imn, g_rWm_imn);
    cudaGetSymbolAddress((void**)&rWo_re, g_rWo_re);
    cudaGetSymbolAddress((void**)&rWo_im, g_rWo_im);
    cudaGetSymbolAddress((void**)&rWo_imn, g_rWo_imn);

    const int SM_T1 = STAGES * ASZ * 4 * 2;                 // 81920
    const int SM_T0 = STAGES * ASZ * 4 + STAGES * BSZ0 * 4; // 75776
    cudaFuncSetAttribute(gemm_tf32<0,1,1>, cudaFuncAttributeMaxDynamicSharedMemorySize, SM_T0);
    cudaFuncSetAttribute(gemm_tf32<0,0,1>, cudaFuncAttributeMaxDynamicSharedMemorySize, SM_T0);
    cudaFuncSetAttribute(gemm_tf32<1,1,0>, cudaFuncAttributeMaxDynamicSharedMemorySize, SM_T1);
    cudaFuncSetAttribute(gemm_tf32<0,0,0>, cudaFuncAttributeMaxDynamicSharedMemorySize, SM_T0);
    cudaFuncSetAttribute(gemm_tf32<0,1,0>, cudaFuncAttributeMaxDynamicSharedMemorySize, SM_T0);

    // --- prep: tf32-round weights (+ negated Wm_im / Wo_im) ---
    {
        PrepBatch pb{};
        const float* srcs[NPREP] = {Wq_re, Wq_im, Wk_re, Wk_im, Wv_re, Wv_im,
                                    Wm_re, Wm_im, Wo_re, Wo_im};
        float* dsts[NPREP] = {rWq_re, rWq_im, rWk_re, rWk_im, rWv_re, rWv_im,
                              rWm_re, rWm_im, rWo_re, rWo_im};
        float* negs[NPREP] = {nullptr, nullptr, nullptr, nullptr, nullptr, nullptr,
                              nullptr, rWm_imn, nullptr, rWo_imn};
        int ns[NPREP] = {HID*HID, HID*HID, HID*HID, HID*HID, HID*HID, HID*HID,
                         HDIM*MAN, HDIM*MAN, HID*HID, HID*HID};
        for (int i = 0; i < NPREP; i++) {
            pb.src[i] = srcs[i]; pb.dst[i] = dsts[i]; pb.neg[i] = negs[i]; pb.n[i] = ns[i];
        }
        prep_kernel<<<dim3(32, NPREP), 256>>>(pb);
    }

    norm_kernel<<<NROWS, 128>>>(x, xn);

    dim3 tb(128);

    // --- precompute fused QKV+manifold weights: Wxm = Wx_head @ Wm (complex), z=48 ---
    {
        GemmBatch gb{};
        const float* Wre_[3] = {rWq_re, rWk_re, rWv_re};
        const float* Wim_[3] = {rWq_im, rWk_im, rWv_im};
        float* Fre[3] = {fq_re, fk_re, fv_re};
        float* Fim[3] = {fq_im, fk_im, fv_im};
        int z = 0;
        for (int w = 0; w < 3; w++) {
            for (int h = 0; h < HEADS; h++) {
                gb.A1[z] = Wre_[w] + h * HDIM; gb.B1[z] = rWm_re;
                gb.A2[z] = Wim_[w] + h * HDIM; gb.B2[z] = rWm_imn;
                gb.C[z] = Fre[w] + h * MAN; z++;
                gb.A1[z] = Wre_[w] + h * HDIM; gb.B1[z] = rWm_im;
                gb.A2[z] = Wim_[w] + h * HDIM; gb.B2[z] = rWm_re;
                gb.C[z] = Fim[w] + h * MAN; z++;
            }
        }
        gemm_tf32<0,1,1><<<dim3(MAN/128, HID/128, 48), tb, SM_T0>>>(gb, HDIM, HID, MAN, DM2, 1, 1.f);
    }

    // --- fused QKV+manifold: [4096,512] @ [512,2048], z=6 ---
    {
        GemmBatch gb{};
        const float* Bp[6] = {fq_re, fq_im, fk_re, fk_im, fv_re, fv_im};
        float* Cp[6] = {Qre, Qim, Kre, Kim, Vre, Vim};
        for (int i = 0; i < 6; i++) { gb.A1[i] = xn; gb.B1[i] = Bp[i]; gb.C[i] = Cp[i]; }
        gemm_tf32<0,0,1><<<dim3(DM2/128, NROWS/128, 6), tb, SM_T0>>>(gb, HID, HID, DM2, DM2, 1, 1.f);
    }

    // --- scores: S = SCALE * (Qre Kre^T + Qim Kim^T), z=16 ---
    {
        GemmBatch gb{};
        for (int z = 0; z < BH; z++) {
            int b = z >> 3, h = z & 7;
            size_t off = (size_t)b * SEQ * DM2 + (size_t)h * MAN;
            gb.A1[z] = Qre + off; gb.B1[z] = Kre + off;
            gb.A2[z] = Qim + off; gb.B2[z] = Kim + off;
            gb.C[z] = S + (size_t)z * SEQ * SEQ;
        }
        gemm_tf32<1,1,0><<<dim3(SEQ/128, SEQ/128, BH), tb, SM_T1>>>(gb, MAN, DM2, DM2, SEQ, 1, SCALE);
    }

    softmax_kernel<<<dim3(SEQ, BH), 256>>>(S);

    // --- PV: Om_re = P Vre, Om_im = P Vim, z=32 ---
    {
        GemmBatch gb{};
        for (int z = 0; z < BH; z++) {
            int b = z >> 3, h = z & 7;
            size_t off = (size_t)b * SEQ * DM2 + (size_t)h * MAN;
            gb.A1[z]      = S + (size_t)z * SEQ * SEQ;
            gb.B1[z]      = Vre + off;
            gb.C[z]       = Om_re + off;
            gb.A1[z + BH] = S + (size_t)z * SEQ * SEQ;
            gb.B1[z + BH] = Vim + off;
            gb.C[z + BH]  = Om_im + off;
        }
        gemm_tf32<0,0,0><<<dim3(MAN/128, SEQ/128, 2*BH), tb, SM_T0>>>(gb, SEQ, SEQ, DM2, DM2, 1, 1.f);
    }

    // --- Wmi back-projection + head merge (rounds oh outputs) ---
    wmi_kernel<<<dim3(NROWS/16, HEADS), dim3(16,16)>>>(Om_re, Om_im, Wmi_re, Wmi_im, oh_re, oh_im);

    // --- output projection: complex Wo, interleaved [.,512,2], z=2 ---
    {
        GemmBatch gb{};
        gb.A1[0] = oh_re; gb.B1[0] = rWo_re; gb.A2[0] = oh_im; gb.B2[0] = rWo_imn;
        gb.C[0] = out;
        gb.A1[1] = oh_re; gb.B1[1] = rWo_im; gb.A2[1] = oh_im; gb.B2[1] = rWo_re;
        gb.C[1] = out + 1;
        gemm_tf32<0,1,0><<<dim3(HID/128, NROWS/128, 2), tb, SM_T0>>>(gb, HID, HID, HID, 2*HID, 2, 1.f);
    }
}

// round 14
// speedup vs baseline: 2.3706x; 1.0649x over previous
#include <cuda_runtime.h>
#include <cuda_bf16.h>
#include <cstdint>

#define BATCH 2
#define SEQ   2048
#define HID   512
#define HEADS 8
#define HDIM  64
#define MAN   256
#define DM2   2048           // HEADS*MAN
#define NROWS (BATCH*SEQ)    // 4096
#define BH    (BATCH*HEADS)  // 16
#define SCALE 0.125f         // 64^-0.5

#define AROW 20              // padded smem row (floats): conflict-free ldmatrix
#define STAGES 4
#define ASZ (128*AROW)       // floats per A stage

// ---------------- scratch (device globals; no allocations) ----------------
__device__ float g_xn[NROWS * HID];
__device__ float g_fq_re[HID * DM2];
__device__ float g_fq_im[HID * DM2];
__device__ float g_fk_re[HID * DM2];
__device__ float g_fk_im[HID * DM2];
__device__ float g_fv_re[HID * DM2];
__device__ float g_fv_im[HID * DM2];
__device__ float g_Qre[(size_t)NROWS * DM2];
__device__ float g_Qim[(size_t)NROWS * DM2];
__device__ float g_Kre[(size_t)NROWS * DM2];
__device__ float g_Kim[(size_t)NROWS * DM2];
__device__ float g_Vre[(size_t)NROWS * DM2];
__device__ float g_Vim[(size_t)NROWS * DM2];
__device__ float g_S[(size_t)BH * SEQ * SEQ];   // 268 MB
__device__ float g_Om_re[(size_t)NROWS * DM2];
__device__ float g_Om_im[(size_t)NROWS * DM2];
__device__ float g_oh_re[NROWS * HID];
__device__ float g_oh_im[NROWS * HID];
// pre-rounded (tf32) weight copies
__device__ float g_rWq_re[HID * HID];
__device__ float g_rWq_im[HID * HID];
__device__ float g_rWk_re[HID * HID];
__device__ float g_rWk_im[HID * HID];
__device__ float g_rWv_re[HID * HID];
__device__ float g_rWv_im[HID * HID];
__device__ float g_rWm_re[HDIM * MAN];
__device__ float g_rWm_im[HDIM * MAN];
__device__ float g_rWm_imn[HDIM * MAN];
__device__ float g_rWo_re[HID * HID];
__device__ float g_rWo_im[HID * HID];
__device__ float g_rWo_imn[HID * HID];
__device__ float g_rWmi_re[MAN * HDIM];
__device__ float g_rWmi_im[MAN * HDIM];
__device__ float g_rWmi_imn[MAN * HDIM];

#define MAXB 48
struct GemmBatch {
    const float* A1[MAXB];
    const float* B1[MAXB];
    const float* A2[MAXB];
    const float* B2[MAXB];
    float*       C[MAXB];
};
#define NPREP 12
struct PrepBatch {
    const float* src[NPREP];
    float* dst[NPREP];
    float* neg[NPREP];
    int n[NPREP];
};

// ---------------- helpers ----------------
__device__ __forceinline__ float to_tf32(float x) {
    asm("cvt.rna.tf32.f32 %0, %1;" : "=f"(x) : "f"(x));
    return x;
}
__device__ __forceinline__ void mma_tf32(float c[4], const uint32_t a[4], const uint32_t b[2]) {
    asm volatile(
        "mma.sync.aligned.m16n8k8.row.col.f32.tf32.tf32.f32 "
        "{%0,%1,%2,%3},{%4,%5,%6,%7},{%8,%9},{%0,%1,%2,%3};"
        : "+f"(c[0]), "+f"(c[1]), "+f"(c[2]), "+f"(c[3])
        : "r"(a[0]), "r"(a[1]), "r"(a[2]), "r"(a[3]), "r"(b[0]), "r"(b[1]));
}
__device__ __forceinline__ void ldsm_x4(uint32_t r[4], uint32_t addr) {
    asm volatile("ldmatrix.sync.aligned.m8n8.x4.shared.b16 {%0,%1,%2,%3}, [%4];"
        : "=r"(r[0]), "=r"(r[1]), "=r"(r[2]), "=r"(r[3]) : "r"(addr));
}
__device__ __forceinline__ void cp_async16(uint32_t dst, const float* src) {
    asm volatile("cp.async.cg.shared.global [%0], [%1], 16;" :: "r"(dst), "l"(src));
}
__device__ __forceinline__ void cp_commit() {
    asm volatile("cp.async.commit_group;");
}
template<int N>
__device__ __forceinline__ void cp_wait() {
    asm volatile("cp.async.wait_group %0;" :: "n"(N));
}

// ---------------- prep: tf32-round (and negate) weight inputs ----------------
__global__ void prep_kernel(PrepBatch pb) {
    int e = blockIdx.y;
    const float* s = pb.src[e];
    float* d = pb.dst[e];
    float* dn = pb.neg[e];
    int n = pb.n[e];
    for (int i = blockIdx.x * blockDim.x + threadIdx.x; i < n; i += gridDim.x * blockDim.x) {
        float v = to_tf32(s[i]);
        d[i] = v;
        if (dn) dn[i] = -v;
    }
}

// ---------------- row L2-normalize (tf32-rounded output) ----------------
__global__ void norm_kernel(const float* __restrict__ x, float* __restrict__ xn) {
    int row = blockIdx.x;
    int t = threadIdx.x;
    const float4* xr = (const float4*)(x + (size_t)row * HID);
    float4 v = xr[t];
    float ss = v.x*v.x + v.y*v.y + v.z*v.z + v.w*v.w;
    #pragma unroll
    for (int o = 16; o > 0; o >>= 1) ss += __shfl_xor_sync(0xffffffffu, ss, o);
    __shared__ float ws[4];
    if ((t & 31) == 0) ws[t >> 5] = ss;
    __syncthreads();
    float tot = ws[0] + ws[1] + ws[2] + ws[3];
    float inv = 1.0f / sqrtf(tot);
    v.x = to_tf32(v.x * inv); v.y = to_tf32(v.y * inv);
    v.z = to_tf32(v.z * inv); v.w = to_tf32(v.w * inv);
    ((float4*)(xn + (size_t)row * HID))[t] = v;
}

// ---------------- tf32 tensor-core GEMM (cp.async 4-stage pipeline) ----------------
// 128xBN CTA tile, BK=16, 4 warps (2x2), 64x(BN/2) per warp.
// Inputs MUST be pre-rounded to tf32.  TWO=1: C = sign*(A1@B1 + A2@B2).
// ROUNDC=1: round C writes to tf32 (for tensors feeding later gemms).
template<int TRANSB, int TWO, int ROUNDC, int BN>
__global__ __launch_bounds__(128)
void gemm_tf32(GemmBatch gb, int K, int lda, int ldb, int ldc, int cstride, float sign) {
    constexpr int NI = BN / 16;                 // 8-wide n-frags per warp
    constexpr int BROW = (BN == 128) ? 136 : 72;
    constexpr int BSZ = TRANSB ? (BN * AROW) : (16 * BROW);
    constexpr int BITER = BN / 32;              // cp.async iters for B

    extern __shared__ char dynsmem[];
    float* As = (float*)dynsmem;
    float* Bs = (float*)(dynsmem + STAGES * ASZ * 4);

    const int tid = threadIdx.x;
    const int bz = blockIdx.z;
    const float* A1 = gb.A1[bz];
    const float* B1 = gb.B1[bz];
    const float* A2 = TWO ? gb.A2[bz] : nullptr;
    const float* B2 = TWO ? gb.B2[bz] : nullptr;
    float* C = gb.C[bz];

    const int row0 = blockIdx.y * 128;
    const int col0 = blockIdx.x * BN;
    const int warp = tid >> 5, lane = tid & 31;
    const int wm = (warp & 1) * 64;
    const int wn = (warp >> 1) * (BN / 2);
    const int g = lane >> 2, tig = lane & 3;

    const uint32_t As_u32 = (uint32_t)__cvta_generic_to_shared(As);
    const uint32_t Bs_u32 = (uint32_t)__cvta_generic_to_shared(Bs);
    const int arow = (lane & 7) + ((lane >> 3) & 1) * 8;
    const int akoff = (lane >> 4) * 4;

    float c[4][NI][4] = {};
    const int nk = TWO ? 2 * K : K;

    auto issue_stage = [&](int kt, int sbuf) {
        if (kt < nk) {
            int p = TWO && (kt >= K);
            const float* Ap = p ? A2 : A1;
            const float* Bp = p ? B2 : B1;
            int kk = kt - (p ? K : 0);
            uint32_t ab = As_u32 + (uint32_t)(sbuf * ASZ * 4);
            uint32_t bb = Bs_u32 + (uint32_t)(sbuf * BSZ * 4);
            #pragma unroll
            for (int i = 0; i < 4; i++) {
                int idx = tid + i * 128;
                int r = idx >> 2, kq = (idx & 3) * 4;
                cp_async16(ab + (uint32_t)((r * AROW + kq) * 4),
                           Ap + (size_t)(row0 + r) * lda + kk + kq);
            }
            if (TRANSB) {
                #pragma unroll
                for (int i = 0; i < BITER; i++) {
                    int idx = tid + i * 128;
                    int n = idx >> 2, kq = (idx & 3) * 4;
                    cp_async16(bb + (uint32_t)((n * AROW + kq) * 4),
                               Bp + (size_t)(col0 + n) * ldb + kk + kq);
                }
            } else {
                #pragma unroll
                for (int i = 0; i < BITER; i++) {
                    int idx = tid + i * 128;
                    int r = idx / (BN / 4), nq = (idx % (BN / 4)) * 4;
                    cp_async16(bb + (uint32_t)((r * BROW + nq) * 4),
                               Bp + (size_t)(kk + r) * ldb + col0 + nq);
                }
            }
        }
        cp_commit();
    };

    issue_stage(0, 0);
    issue_stage(16, 1);
    issue_stage(32, 2);

    for (int kt = 0; kt < nk; kt += 16) {
        const int s = (kt >> 4) & 3;
        cp_wait<2>();
        __syncthreads();
        issue_stage(kt + 48, (s + 3) & 3);

        #pragma unroll
        for (int kc = 0; kc < 2; kc++) {
            uint32_t a[4][4], b[NI][2];
            #pragma unroll
            for (int mi = 0; mi < 4; mi++) {
                uint32_t addr = As_u32 +
                    (uint32_t)(((s * ASZ) + (wm + mi * 16 + arow) * AROW + kc * 8 + akoff) * 4);
                ldsm_x4(a[mi], addr);
            }
            if (TRANSB) {
                #pragma unroll
                for (int nj = 0; nj < NI / 2; nj++) {
                    uint32_t r4[4];
                    uint32_t addr = Bs_u32 +
                        (uint32_t)(((s * BSZ) + (wn + nj * 16 + arow) * AROW + kc * 8 + akoff) * 4);
                    ldsm_x4(r4, addr);
                    b[2*nj][0]   = r4[0]; b[2*nj][1]   = r4[2];
                    b[2*nj+1][0] = r4[1]; b[2*nj+1][1] = r4[3];
                }
            } else {
                const int kb = kc * 8;
                #pragma unroll
                for (int ni = 0; ni < NI; ni++) {
                    int n = wn + ni * 8 + g;
                    b[ni][0] = __float_as_uint(Bs[s * BSZ + (kb + tig) * BROW + n]);
                    b[ni][1] = __float_as_uint(Bs[s * BSZ + (kb + tig + 4) * BROW + n]);
                }
            }
            #pragma unroll
            for (int mi = 0; mi < 4; mi++)
                #pragma unroll
                for (int ni = 0; ni < NI; ni++)
                    mma_tf32(c[mi][ni], a[mi], b[ni]);
        }
    }

    if (cstride == 1) {
        #pragma unroll
        for (int mi = 0; mi < 4; mi++) {
            int m0 = row0 + wm + mi * 16 + g;
            #pragma unroll
            for (int ni = 0; ni < NI; ni++) {
                int n0 = col0 + wn + ni * 8 + tig * 2;
                #pragma unroll
                for (int half = 0; half < 2; half++) {
                    int m = m0 + half * 8;
                    float vx = sign * c[mi][ni][half * 2];
                    float vy = sign * c[mi][ni][half * 2 + 1];
                    if (ROUNDC) { vx = to_tf32(vx); vy = to_tf32(vy); }
                    *(float2*)(C + (size_t)m * ldc + n0) = make_float2(vx, vy);
                }
            }
        }
    } else {
        #pragma unroll
        for (int mi = 0; mi < 4; mi++) {
            int m0 = row0 + wm + mi * 16 + g;
            #pragma unroll
            for (int ni = 0; ni < NI; ni++) {
                int n0 = col0 + wn + ni * 8 + tig * 2;
                #pragma unroll
                for (int jj = 0; jj < 4; jj++) {
                    int m = m0 + (jj >> 1) * 8;
                    int n = n0 + (jj & 1);
                    float v = sign * c[mi][ni][jj];
                    if (ROUNDC) v = to_tf32(v);
                    C[(size_t)m * ldc + (size_t)n * cstride] = v;
                }
            }
        }
    }
}

// ---------------- row softmax (scores pre-scaled), tf32-rounded output ----------------
__global__ void softmax_kernel(float* __restrict__ S) {
    size_t base = ((size_t)blockIdx.y * SEQ + blockIdx.x) * SEQ;
    float4* row = (float4*)(S + base);
    int t = threadIdx.x;
    float4 v0 = row[t], v1 = row[t + 256];
    float m = fmaxf(fmaxf(fmaxf(v0.x, v0.y), fmaxf(v0.z, v0.w)),
                    fmaxf(fmaxf(v1.x, v1.y), fmaxf(v1.z, v1.w)));
    #pragma unroll
    for (int o = 16; o > 0; o >>= 1) m = fmaxf(m, __shfl_xor_sync(0xffffffffu, m, o));
    __shared__ float red[8];
    if ((t & 31) == 0) red[t >> 5] = m;
    __syncthreads();
    m = red[0];
    #pragma unroll
    for (int i = 1; i < 8; i++) m = fmaxf(m, red[i]);

    v0.x = expf(v0.x - m); v0.y = expf(v0.y - m); v0.z = expf(v0.z - m); v0.w = expf(v0.w - m);
    v1.x = expf(v1.x - m); v1.y = expf(v1.y - m); v1.z = expf(v1.z - m); v1.w = expf(v1.w - m);
    float s = v0.x + v0.y + v0.z + v0.w + v1.x + v1.y + v1.z + v1.w;
    #pragma unroll
    for (int o = 16; o > 0; o >>= 1) s += __shfl_xor_sync(0xffffffffu, s, o);
    __syncthreads();
    if ((t & 31) == 0) red[t >> 5] = s;
    __syncthreads();
    s = red[0];
    #pragma unroll
    for (int i = 1; i < 8; i++) s += red[i];
    float inv = 1.0f / s;
    v0.x = to_tf32(v0.x * inv); v0.y = to_tf32(v0.y * inv);
    v0.z = to_tf32(v0.z * inv); v0.w = to_tf32(v0.w * inv);
    v1.x = to_tf32(v1.x * inv); v1.y = to_tf32(v1.y * inv);
    v1.z = to_tf32(v1.z * inv); v1.w = to_tf32(v1.w * inv);
    row[t] = v0; row[t + 256] = v1;
}

// ---------------- launcher ----------------
extern "C" void kernel_launch(void* const* d_in, const int* in_sizes, int n_in,
                              void* d_out, int out_size) {
    const float* x      = (const float*)d_in[0];
    const float* Wq_re  = (const float*)d_in[1];
    const float* Wq_im  = (const float*)d_in[2];
    const float* Wk_re  = (const float*)d_in[3];
    const float* Wk_im  = (const float*)d_in[4];
    const float* Wv_re  = (const float*)d_in[5];
    const float* Wv_im  = (const float*)d_in[6];
    const float* Wm_re  = (const float*)d_in[7];
    const float* Wm_im  = (const float*)d_in[8];
    const float* Wmi_re = (const float*)d_in[9];
    const float* Wmi_im = (const float*)d_in[10];
    const float* Wo_re  = (const float*)d_in[11];
    const float* Wo_im  = (const float*)d_in[12];
    float* out = (float*)d_out;

    float *xn, *fq_re, *fq_im, *fk_re, *fk_im, *fv_re, *fv_im;
    float *Qre, *Qim, *Kre, *Kim, *Vre, *Vim, *S, *Om_re, *Om_im, *oh_re, *oh_im;
    float *rWq_re, *rWq_im, *rWk_re, *rWk_im, *rWv_re, *rWv_im;
    float *rWm_re, *rWm_im, *rWm_imn, *rWo_re, *rWo_im, *rWo_imn;
    float *rWmi_re, *rWmi_im, *rWmi_imn;
    cudaGetSymbolAddress((void**)&xn,    g_xn);
    cudaGetSymbolAddress((void**)&fq_re, g_fq_re);
    cudaGetSymbolAddress((void**)&fq_im, g_fq_im);
    cudaGetSymbolAddress((void**)&fk_re, g_fk_re);
    cudaGetSymbolAddress((void**)&fk_im, g_fk_im);
    cudaGetSymbolAddress((void**)&fv_re, g_fv_re);
    cudaGetSymbolAddress((void**)&fv_im, g_fv_im);
    cudaGetSymbolAddress((void**)&Qre,   g_Qre);
    cudaGetSymbolAddress((void**)&Qim,   g_Qim);
    cudaGetSymbolAddress((void**)&Kre,   g_Kre);
    cudaGetSymbolAddress((void**)&Kim,   g_Kim);
    cudaGetSymbolAddress((void**)&Vre,   g_Vre);
    cudaGetSymbolAddress((void**)&Vim,   g_Vim);
    cudaGetSymbolAddress((void**)&S,     g_S);
    cudaGetSymbolAddress((void**)&Om_re, g_Om_re);
    cudaGetSymbolAddress((void**)&Om_im, g_Om_im);
    cudaGetSymbolAddress((void**)&oh_re, g_oh_re);
    cudaGetSymbolAddress((void**)&oh_im, g_oh_im);
    cudaGetSymbolAddress((void**)&rWq_re, g_rWq_re);
    cudaGetSymbolAddress((void**)&rWq_im, g_rWq_im);
    cudaGetSymbolAddress((void**)&rWk_re, g_rWk_re);
    cudaGetSymbolAddress((void**)&rWk_im, g_rWk_im);
    cudaGetSymbolAddress((void**)&rWv_re, g_rWv_re);
    cudaGetSymbolAddress((void**)&rWv_im, g_rWv_im);
    cudaGetSymbolAddress((void**)&rWm_re, g_rWm_re);
    cudaGetSymbolAddress((void**)&rWm_im, g_rWm_im);
    cudaGetSymbolAddress((void**)&rWm_imn, g_rWm_imn);
    cudaGetSymbolAddress((void**)&rWo_re, g_rWo_re);
    cudaGetSymbolAddress((void**)&rWo_im, g_rWo_im);
    cudaGetSymbolAddress((void**)&rWo_imn, g_rWo_imn);
    cudaGetSymbolAddress((void**)&rWmi_re, g_rWmi_re);
    cudaGetSymbolAddress((void**)&rWmi_im, g_rWmi_im);
    cudaGetSymbolAddress((void**)&rWmi_imn, g_rWmi_imn);

    const int SM_T1  = STAGES * ASZ * 4 * 2;                  // TRANSB=1, BN=128
    const int SM_T0  = STAGES * ASZ * 4 + STAGES * 16*136*4;  // NN, BN=128
    const int SM_T64 = STAGES * ASZ * 4 + STAGES * 16*72*4;   // NN, BN=64
    cudaFuncSetAttribute(gemm_tf32<0,1,1,128>, cudaFuncAttributeMaxDynamicSharedMemorySize, SM_T0);
    cudaFuncSetAttribute(gemm_tf32<0,0,1,128>, cudaFuncAttributeMaxDynamicSharedMemorySize, SM_T0);
    cudaFuncSetAttribute(gemm_tf32<1,1,0,128>, cudaFuncAttributeMaxDynamicSharedMemorySize, SM_T1);
    cudaFuncSetAttribute(gemm_tf32<0,1,0,128>, cudaFuncAttributeMaxDynamicSharedMemorySize, SM_T0);
    cudaFuncSetAttribute(gemm_tf32<0,1,1,64>,  cudaFuncAttributeMaxDynamicSharedMemorySize, SM_T64);

    // --- prep: tf32-round weights (+ negated Wm_im / Wo_im / Wmi_im) ---
    {
        PrepBatch pb{};
        const float* srcs[NPREP] = {Wq_re, Wq_im, Wk_re, Wk_im, Wv_re, Wv_im,
                                    Wm_re, Wm_im, Wo_re, Wo_im, Wmi_re, Wmi_im};
        float* dsts[NPREP] = {rWq_re, rWq_im, rWk_re, rWk_im, rWv_re, rWv_im,
                              rWm_re, rWm_im, rWo_re, rWo_im, rWmi_re, rWmi_im};
        float* negs[NPREP] = {nullptr, nullptr, nullptr, nullptr, nullptr, nullptr,
                              nullptr, rWm_imn, nullptr, rWo_imn, nullptr, rWmi_imn};
        int ns[NPREP] = {HID*HID, HID*HID, HID*HID, HID*HID, HID*HID, HID*HID,
                         HDIM*MAN, HDIM*MAN, HID*HID, HID*HID, MAN*HDIM, MAN*HDIM};
        for (int i = 0; i < NPREP; i++) {
            pb.src[i] = srcs[i]; pb.dst[i] = dsts[i]; pb.neg[i] = negs[i]; pb.n[i] = ns[i];
        }
        prep_kernel<<<dim3(32, NPREP), 256>>>(pb);
    }

    norm_kernel<<<NROWS, 128>>>(x, xn);

    dim3 tb(128);

    // --- precompute fused QKV+manifold weights: Wxm = Wx_head @ Wm (complex), z=48 ---
    {
        GemmBatch gb{};
        const float* Wre_[3] = {rWq_re, rWk_re, rWv_re};
        const float* Wim_[3] = {rWq_im, rWk_im, rWv_im};
        float* Fre[3] = {fq_re, fk_re, fv_re};
        float* Fim[3] = {fq_im, fk_im, fv_im};
        int z = 0;
        for (int w = 0; w < 3; w++) {
            for (int h = 0; h < HEADS; h++) {
                gb.A1[z] = Wre_[w] + h * HDIM; gb.B1[z] = rWm_re;
                gb.A2[z] = Wim_[w] + h * HDIM; gb.B2[z] = rWm_imn;
                gb.C[z] = Fre[w] + h * MAN; z++;
                gb.A1[z] = Wre_[w] + h * HDIM; gb.B1[z] = rWm_im;
                gb.A2[z] = Wim_[w] + h * HDIM; gb.B2[z] = rWm_re;
                gb.C[z] = Fim[w] + h * MAN; z++;
            }
        }
        gemm_tf32<0,1,1,128><<<dim3(MAN/128, HID/128, 48), tb, SM_T0>>>(gb, HDIM, HID, MAN, DM2, 1, 1.f);
    }

    // --- fused QKV+manifold: [4096,512] @ [512,2048], z=6 ---
    {
        GemmBatch gb{};
        const float* Bp[6] = {fq_re, fq_im, fk_re, fk_im, fv_re, fv_im};
        float* Cp[6] = {Qre, Qim, Kre, Kim, Vre, Vim};
        for (int i = 0; i < 6; i++) { gb.A1[i] = xn; gb.B1[i] = Bp[i]; gb.C[i] = Cp[i]; }
        gemm_tf32<0,0,1,128><<<dim3(DM2/128, NROWS/128, 6), tb, SM_T0>>>(gb, HID, HID, DM2, DM2, 1, 1.f);
    }

    // --- scores: S = SCALE * (Qre Kre^T + Qim Kim^T), z=16 ---
    {
        GemmBatch gb{};
        for (int z = 0; z < BH; z++) {
            int b = z >> 3, h = z & 7;
            size_t off = (size_t)b * SEQ * DM2 + (size_t)h * MAN;
            gb.A1[z] = Qre + off; gb.B1[z] = Kre + off;
            gb.A2[z] = Qim + off; gb.B2[z] = Kim + off;
            gb.C[z] = S + (size_t)z * SEQ * SEQ;
        }
        gemm_tf32<1,1,0,128><<<dim3(SEQ/128, SEQ/128, BH), tb, SM_T1>>>(gb, MAN, DM2, DM2, SEQ, 1, SCALE);
    }

    softmax_kernel<<<dim3(SEQ, BH), 256>>>(S);

    // --- PV: Om_re = P Vre, Om_im = P Vim, z=32 (rounded: feeds wmi gemm) ---
    {
        GemmBatch gb{};
        for (int z = 0; z < BH; z++) {
            int b = z >> 3, h = z & 7;
            size_t off = (size_t)b * SEQ * DM2 + (size_t)h * MAN;
            gb.A1[z]      = S + (size_t)z * SEQ * SEQ;
            gb.B1[z]      = Vre + off;
            gb.C[z]       = Om_re + off;
            gb.A1[z + BH] = S + (size_t)z * SEQ * SEQ;
            gb.B1[z + BH] = Vim + off;
            gb.C[z + BH]  = Om_im + off;
        }
        gemm_tf32<0,0,1,128><<<dim3(MAN/128, SEQ/128, 2*BH), tb, SM_T0>>>(gb, SEQ, SEQ, DM2, DM2, 1, 1.f);
    }

    // --- Wmi back-projection + head merge as tensor-core gemm: z=16 (8 heads x {re,im}) ---
    // oh_re[.,h*64+] = Om_re_h @ Wmi_re - Om_im_h @ Wmi_im ; oh_im = Om_re_h @ Wmi_im + Om_im_h @ Wmi_re
    {
        GemmBatch gb{};
        for (int h = 0; h < HEADS; h++) {
            int z0 = 2 * h;
            gb.A1[z0] = Om_re + (size_t)h * MAN; gb.B1[z0] = rWmi_re;
            gb.A2[z0] = Om_im + (size_t)h * MAN; gb.B2[z0] = rWmi_imn;
            gb.C[z0]  = oh_re + (size_t)h * HDIM;
            gb.A1[z0+1] = Om_re + (size_t)h * MAN; gb.B1[z0+1] = rWmi_im;
            gb.A2[z0+1] = Om_im + (size_t)h * MAN; gb.B2[z0+1] = rWmi_re;
            gb.C[z0+1]  = oh_im + (size_t)h * HDIM;
        }
        gemm_tf32<0,1,1,64><<<dim3(1, NROWS/128, 16), tb, SM_T64>>>(gb, MAN, DM2, HDIM, HID, 1, 1.f);
    }

    // --- output projection: complex Wo, interleaved [.,512,2], z=2 ---
    {
        GemmBatch gb{};
        gb.A1[0] = oh_re; gb.B1[0] = rWo_re; gb.A2[0] = oh_im; gb.B2[0] = rWo_imn;
        gb.C[0] = out;
        gb.A1[1] = oh_re; gb.B1[1] = rWo_im; gb.A2[1] = oh_im; gb.B2[1] = rWo_re;
        gb.C[1] = out + 1;
        gemm_tf32<0,1,0,128><<<dim3(HID/128, NROWS/128, 2), tb, SM_T0>>>(gb, HID, HID, HID, 2*HID, 2, 1.f);
    }
}

// round 15
// speedup vs baseline: 2.4797x; 1.0460x over previous
#include <cuda_runtime.h>
#include <cuda_bf16.h>
#include <cstdint>

#define BATCH 2
#define SEQ   2048
#define HID   512
#define HEADS 8
#define HDIM  64
#define MAN   256
#define DM2   2048           // HEADS*MAN
#define NROWS (BATCH*SEQ)    // 4096
#define BH    (BATCH*HEADS)  // 16
#define SCALE 0.125f         // 64^-0.5
#define QLD   4096           // HEADS*512, Qeff row stride

#define AROW 20              // padded smem row (floats): conflict-free ldmatrix
#define STAGES 4
#define ASZ (128*AROW)       // floats per A stage

// ---------------- scratch (device globals; no allocations) ----------------
__device__ float g_xn[NROWS * HID];
__device__ float g_fq_re[HID * DM2];
__device__ float g_fq_im[HID * DM2];
__device__ float g_fk_re[HID * DM2];
__device__ float g_fk_im[HID * DM2];
__device__ float g_fv_re[HID * DM2];
__device__ float g_fv_im[HID * DM2];
__device__ float g_R[(size_t)HEADS * HID * HID];        // per-head real score matrix
__device__ float g_Qeff[(size_t)NROWS * QLD];           // xn @ R_h, per head col block
__device__ float g_Vre[(size_t)NROWS * DM2];
__device__ float g_Vim[(size_t)NROWS * DM2];
__device__ float g_S[(size_t)BH * SEQ * SEQ];           // 268 MB
__device__ float g_Om_re[(size_t)NROWS * DM2];
__device__ float g_Om_im[(size_t)NROWS * DM2];
__device__ float g_oh_re[NROWS * HID];
__device__ float g_oh_im[NROWS * HID];
// pre-rounded (tf32) weight copies
__device__ float g_rWq_re[HID * HID];
__device__ float g_rWq_im[HID * HID];
__device__ float g_rWk_re[HID * HID];
__device__ float g_rWk_im[HID * HID];
__device__ float g_rWv_re[HID * HID];
__device__ float g_rWv_im[HID * HID];
__device__ float g_rWm_re[HDIM * MAN];
__device__ float g_rWm_im[HDIM * MAN];
__device__ float g_rWm_imn[HDIM * MAN];
__device__ float g_rWo_re[HID * HID];
__device__ float g_rWo_im[HID * HID];
__device__ float g_rWo_imn[HID * HID];
__device__ float g_rWmi_re[MAN * HDIM];
__device__ float g_rWmi_im[MAN * HDIM];
__device__ float g_rWmi_imn[MAN * HDIM];

#define MAXB 48
struct GemmBatch {
    const float* A1[MAXB];
    const float* B1[MAXB];
    const float* A2[MAXB];
    const float* B2[MAXB];
    float*       C[MAXB];
};
#define NPREP 12
struct PrepBatch {
    const float* src[NPREP];
    float* dst[NPREP];
    float* neg[NPREP];
    int n[NPREP];
};

// ---------------- helpers ----------------
__device__ __forceinline__ float to_tf32(float x) {
    asm("cvt.rna.tf32.f32 %0, %1;" : "=f"(x) : "f"(x));
    return x;
}
__device__ __forceinline__ void mma_tf32(float c[4], const uint32_t a[4], const uint32_t b[2]) {
    asm volatile(
        "mma.sync.aligned.m16n8k8.row.col.f32.tf32.tf32.f32 "
        "{%0,%1,%2,%3},{%4,%5,%6,%7},{%8,%9},{%0,%1,%2,%3};"
        : "+f"(c[0]), "+f"(c[1]), "+f"(c[2]), "+f"(c[3])
        : "r"(a[0]), "r"(a[1]), "r"(a[2]), "r"(a[3]), "r"(b[0]), "r"(b[1]));
}
__device__ __forceinline__ void ldsm_x4(uint32_t r[4], uint32_t addr) {
    asm volatile("ldmatrix.sync.aligned.m8n8.x4.shared.b16 {%0,%1,%2,%3}, [%4];"
        : "=r"(r[0]), "=r"(r[1]), "=r"(r[2]), "=r"(r[3]) : "r"(addr));
}
__device__ __forceinline__ void cp_async16(uint32_t dst, const float* src) {
    asm volatile("cp.async.cg.shared.global [%0], [%1], 16;" :: "r"(dst), "l"(src));
}
__device__ __forceinline__ void cp_commit() {
    asm volatile("cp.async.commit_group;");
}
template<int N>
__device__ __forceinline__ void cp_wait() {
    asm volatile("cp.async.wait_group %0;" :: "n"(N));
}

// ---------------- prep: tf32-round (and negate) weight inputs ----------------
__global__ void prep_kernel(PrepBatch pb) {
    int e = blockIdx.y;
    const float* s = pb.src[e];
    float* d = pb.dst[e];
    float* dn = pb.neg[e];
    int n = pb.n[e];
    for (int i = blockIdx.x * blockDim.x + threadIdx.x; i < n; i += gridDim.x * blockDim.x) {
        float v = to_tf32(s[i]);
        d[i] = v;
        if (dn) dn[i] = -v;
    }
}

// ---------------- row L2-normalize (tf32-rounded output) ----------------
__global__ void norm_kernel(const float* __restrict__ x, float* __restrict__ xn) {
    int row = blockIdx.x;
    int t = threadIdx.x;
    const float4* xr = (const float4*)(x + (size_t)row * HID);
    float4 v = xr[t];
    float ss = v.x*v.x + v.y*v.y + v.z*v.z + v.w*v.w;
    #pragma unroll
    for (int o = 16; o > 0; o >>= 1) ss += __shfl_xor_sync(0xffffffffu, ss, o);
    __shared__ float ws[4];
    if ((t & 31) == 0) ws[t >> 5] = ss;
    __syncthreads();
    float tot = ws[0] + ws[1] + ws[2] + ws[3];
    float inv = 1.0f / sqrtf(tot);
    v.x = to_tf32(v.x * inv); v.y = to_tf32(v.y * inv);
    v.z = to_tf32(v.z * inv); v.w = to_tf32(v.w * inv);
    ((float4*)(xn + (size_t)row * HID))[t] = v;
}

// ---------------- tf32 tensor-core GEMM (cp.async 4-stage pipeline) ----------------
// 128xBN CTA tile, BK=16, 4 warps (2x2), 64x(BN/2) per warp.
// Inputs MUST be pre-rounded to tf32.  TWO=1: C = sign*(A1@B1 + A2@B2).
// ROUNDC=1: round C writes to tf32 (for tensors feeding later gemms).
template<int TRANSB, int TWO, int ROUNDC, int BN>
__global__ __launch_bounds__(128)
void gemm_tf32(GemmBatch gb, int K, int lda, int ldb, int ldc, int cstride, float sign) {
    constexpr int NI = BN / 16;                 // 8-wide n-frags per warp
    constexpr int BROW = (BN == 128) ? 136 : 72;
    constexpr int BSZ = TRANSB ? (BN * AROW) : (16 * BROW);
    constexpr int BITER = BN / 32;              // cp.async iters for B

    extern __shared__ char dynsmem[];
    float* As = (float*)dynsmem;
    float* Bs = (float*)(dynsmem + STAGES * ASZ * 4);

    const int tid = threadIdx.x;
    const int bz = blockIdx.z;
    const float* A1 = gb.A1[bz];
    const float* B1 = gb.B1[bz];
    const float* A2 = TWO ? gb.A2[bz] : nullptr;
    const float* B2 = TWO ? gb.B2[bz] : nullptr;
    float* C = gb.C[bz];

    const int row0 = blockIdx.y * 128;
    const int col0 = blockIdx.x * BN;
    const int warp = tid >> 5, lane = tid & 31;
    const int wm = (warp & 1) * 64;
    const int wn = (warp >> 1) * (BN / 2);
    const int g = lane >> 2, tig = lane & 3;

    const uint32_t As_u32 = (uint32_t)__cvta_generic_to_shared(As);
    const uint32_t Bs_u32 = (uint32_t)__cvta_generic_to_shared(Bs);
    const int arow = (lane & 7) + ((lane >> 3) & 1) * 8;
    const int akoff = (lane >> 4) * 4;

    float c[4][NI][4] = {};
    const int nk = TWO ? 2 * K : K;

    auto issue_stage = [&](int kt, int sbuf) {
        if (kt < nk) {
            int p = TWO && (kt >= K);
            const float* Ap = p ? A2 : A1;
            const float* Bp = p ? B2 : B1;
            int kk = kt - (p ? K : 0);
            uint32_t ab = As_u32 + (uint32_t)(sbuf * ASZ * 4);
            uint32_t bb = Bs_u32 + (uint32_t)(sbuf * BSZ * 4);
            #pragma unroll
            for (int i = 0; i < 4; i++) {
                int idx = tid + i * 128;
                int r = idx >> 2, kq = (idx & 3) * 4;
                cp_async16(ab + (uint32_t)((r * AROW + kq) * 4),
                           Ap + (size_t)(row0 + r) * lda + kk + kq);
            }
            if (TRANSB) {
                #pragma unroll
                for (int i = 0; i < BITER; i++) {
                    int idx = tid + i * 128;
                    int n = idx >> 2, kq = (idx & 3) * 4;
                    cp_async16(bb + (uint32_t)((n * AROW + kq) * 4),
                               Bp + (size_t)(col0 + n) * ldb + kk + kq);
                }
            } else {
                #pragma unroll
                for (int i = 0; i < BITER; i++) {
                    int idx = tid + i * 128;
                    int r = idx / (BN / 4), nq = (idx % (BN / 4)) * 4;
                    cp_async16(bb + (uint32_t)((r * BROW + nq) * 4),
                               Bp + (size_t)(kk + r) * ldb + col0 + nq);
                }
            }
        }
        cp_commit();
    };

    issue_stage(0, 0);
    issue_stage(16, 1);
    issue_stage(32, 2);

    for (int kt = 0; kt < nk; kt += 16) {
        const int s = (kt >> 4) & 3;
        cp_wait<2>();
        __syncthreads();
        issue_stage(kt + 48, (s + 3) & 3);

        #pragma unroll
        for (int kc = 0; kc < 2; kc++) {
            uint32_t a[4][4], b[NI][2];
            #pragma unroll
            for (int mi = 0; mi < 4; mi++) {
                uint32_t addr = As_u32 +
                    (uint32_t)(((s * ASZ) + (wm + mi * 16 + arow) * AROW + kc * 8 + akoff) * 4);
                ldsm_x4(a[mi], addr);
            }
            if (TRANSB) {
                #pragma unroll
                for (int nj = 0; nj < NI / 2; nj++) {
                    uint32_t r4[4];
                    uint32_t addr = Bs_u32 +
                        (uint32_t)(((s * BSZ) + (wn + nj * 16 + arow) * AROW + kc * 8 + akoff) * 4);
                    ldsm_x4(r4, addr);
                    b[2*nj][0]   = r4[0]; b[2*nj][1]   = r4[2];
                    b[2*nj+1][0] = r4[1]; b[2*nj+1][1] = r4[3];
                }
            } else {
                const int kb = kc * 8;
                #pragma unroll
                for (int ni = 0; ni < NI; ni++) {
                    int n = wn + ni * 8 + g;
                    b[ni][0] = __float_as_uint(Bs[s * BSZ + (kb + tig) * BROW + n]);
                    b[ni][1] = __float_as_uint(Bs[s * BSZ + (kb + tig + 4) * BROW + n]);
                }
            }
            #pragma unroll
            for (int mi = 0; mi < 4; mi++)
                #pragma unroll
                for (int ni = 0; ni < NI; ni++)
                    mma_tf32(c[mi][ni], a[mi], b[ni]);
        }
    }

    if (cstride == 1) {
        #pragma unroll
        for (int mi = 0; mi < 4; mi++) {
            int m0 = row0 + wm + mi * 16 + g;
            #pragma unroll
            for (int ni = 0; ni < NI; ni++) {
                int n0 = col0 + wn + ni * 8 + tig * 2;
                #pragma unroll
                for (int half = 0; half < 2; half++) {
                    int m = m0 + half * 8;
                    float vx = sign * c[mi][ni][half * 2];
                    float vy = sign * c[mi][ni][half * 2 + 1];
                    if (ROUNDC) { vx = to_tf32(vx); vy = to_tf32(vy); }
                    *(float2*)(C + (size_t)m * ldc + n0) = make_float2(vx, vy);
                }
            }
        }
    } else {
        #pragma unroll
        for (int mi = 0; mi < 4; mi++) {
            int m0 = row0 + wm + mi * 16 + g;
            #pragma unroll
            for (int ni = 0; ni < NI; ni++) {
                int n0 = col0 + wn + ni * 8 + tig * 2;
                #pragma unroll
                for (int jj = 0; jj < 4; jj++) {
                    int m = m0 + (jj >> 1) * 8;
                    int n = n0 + (jj & 1);
                    float v = sign * c[mi][ni][jj];
                    if (ROUNDC) v = to_tf32(v);
                    C[(size_t)m * ldc + (size_t)n * cstride] = v;
                }
            }
        }
    }
}

// ---------------- row softmax (scores pre-scaled), tf32-rounded output ----------------
__global__ void softmax_kernel(float* __restrict__ S) {
    size_t base = ((size_t)blockIdx.y * SEQ + blockIdx.x) * SEQ;
    float4* row = (float4*)(S + base);
    int t = threadIdx.x;
    float4 v0 = row[t], v1 = row[t + 256];
    float m = fmaxf(fmaxf(fmaxf(v0.x, v0.y), fmaxf(v0.z, v0.w)),
                    fmaxf(fmaxf(v1.x, v1.y), fmaxf(v1.z, v1.w)));
    #pragma unroll
    for (int o = 16; o > 0; o >>= 1) m = fmaxf(m, __shfl_xor_sync(0xffffffffu, m, o));
    __shared__ float red[8];
    if ((t & 31) == 0) red[t >> 5] = m;
    __syncthreads();
    m = red[0];
    #pragma unroll
    for (int i = 1; i < 8; i++) m = fmaxf(m, red[i]);

    v0.x = expf(v0.x - m); v0.y = expf(v0.y - m); v0.z = expf(v0.z - m); v0.w = expf(v0.w - m);
    v1.x = expf(v1.x - m); v1.y = expf(v1.y - m); v1.z = expf(v1.z - m); v1.w = expf(v1.w - m);
    float s = v0.x + v0.y + v0.z + v0.w + v1.x + v1.y + v1.z + v1.w;
    #pragma unroll
    for (int o = 16; o > 0; o >>= 1) s += __shfl_xor_sync(0xffffffffu, s, o);
    __syncthreads();
    if ((t & 31) == 0) red[t >> 5] = s;
    __syncthreads();
    s = red[0];
    #pragma unroll
    for (int i = 1; i < 8; i++) s += red[i];
    float inv = 1.0f / s;
    v0.x = to_tf32(v0.x * inv); v0.y = to_tf32(v0.y * inv);
    v0.z = to_tf32(v0.z * inv); v0.w = to_tf32(v0.w * inv);
    v1.x = to_tf32(v1.x * inv); v1.y = to_tf32(v1.y * inv);
    v1.z = to_tf32(v1.z * inv); v1.w = to_tf32(v1.w * inv);
    row[t] = v0; row[t + 256] = v1;
}

// ---------------- launcher ----------------
extern "C" void kernel_launch(void* const* d_in, const int* in_sizes, int n_in,
                              void* d_out, int out_size) {
    const float* x      = (const float*)d_in[0];
    const float* Wq_re  = (const float*)d_in[1];
    const float* Wq_im  = (const float*)d_in[2];
    const float* Wk_re  = (const float*)d_in[3];
    const float* Wk_im  = (const float*)d_in[4];
    const float* Wv_re  = (const float*)d_in[5];
    const float* Wv_im  = (const float*)d_in[6];
    const float* Wm_re  = (const float*)d_in[7];
    const float* Wm_im  = (const float*)d_in[8];
    const float* Wmi_re = (const float*)d_in[9];
    const float* Wmi_im = (const float*)d_in[10];
    const float* Wo_re  = (const float*)d_in[11];
    const float* Wo_im  = (const float*)d_in[12];
    float* out = (float*)d_out;

    float *xn, *fq_re, *fq_im, *fk_re, *fk_im, *fv_re, *fv_im;
    float *R, *Qeff, *Vre, *Vim, *S, *Om_re, *Om_im, *oh_re, *oh_im;
    float *rWq_re, *rWq_im, *rWk_re, *rWk_im, *rWv_re, *rWv_im;
    float *rWm_re, *rWm_im, *rWm_imn, *rWo_re, *rWo_im, *rWo_imn;
    float *rWmi_re, *rWmi_im, *rWmi_imn;
    cudaGetSymbolAddress((void**)&xn,    g_xn);
    cudaGetSymbolAddress((void**)&fq_re, g_fq_re);
    cudaGetSymbolAddress((void**)&fq_im, g_fq_im);
    cudaGetSymbolAddress((void**)&fk_re, g_fk_re);
    cudaGetSymbolAddress((void**)&fk_im, g_fk_im);
    cudaGetSymbolAddress((void**)&fv_re, g_fv_re);
    cudaGetSymbolAddress((void**)&fv_im, g_fv_im);
    cudaGetSymbolAddress((void**)&R,     g_R);
    cudaGetSymbolAddress((void**)&Qeff,  g_Qeff);
    cudaGetSymbolAddress((void**)&Vre,   g_Vre);
    cudaGetSymbolAddress((void**)&Vim,   g_Vim);
    cudaGetSymbolAddress((void**)&S,     g_S);
    cudaGetSymbolAddress((void**)&Om_re, g_Om_re);
    cudaGetSymbolAddress((void**)&Om_im, g_Om_im);
    cudaGetSymbolAddress((void**)&oh_re, g_oh_re);
    cudaGetSymbolAddress((void**)&oh_im, g_oh_im);
    cudaGetSymbolAddress((void**)&rWq_re, g_rWq_re);
    cudaGetSymbolAddress((void**)&rWq_im, g_rWq_im);
    cudaGetSymbolAddress((void**)&rWk_re, g_rWk_re);
    cudaGetSymbolAddress((void**)&rWk_im, g_rWk_im);
    cudaGetSymbolAddress((void**)&rWv_re, g_rWv_re);
    cudaGetSymbolAddress((void**)&rWv_im, g_rWv_im);
    cudaGetSymbolAddress((void**)&rWm_re, g_rWm_re);
    cudaGetSymbolAddress((void**)&rWm_im, g_rWm_im);
    cudaGetSymbolAddress((void**)&rWm_imn, g_rWm_imn);
    cudaGetSymbolAddress((void**)&rWo_re, g_rWo_re);
    cudaGetSymbolAddress((void**)&rWo_im, g_rWo_im);
    cudaGetSymbolAddress((void**)&rWo_imn, g_rWo_imn);
    cudaGetSymbolAddress((void**)&rWmi_re, g_rWmi_re);
    cudaGetSymbolAddress((void**)&rWmi_im, g_rWmi_im);
    cudaGetSymbolAddress((void**)&rWmi_imn, g_rWmi_imn);

    const int SM_T1  = STAGES * ASZ * 4 * 2;                  // TRANSB=1, BN=128
    const int SM_T0  = STAGES * ASZ * 4 + STAGES * 16*136*4;  // NN, BN=128
    const int SM_T64 = STAGES * ASZ * 4 + STAGES * 16*72*4;   // NN, BN=64
    cudaFuncSetAttribute(gemm_tf32<0,1,1,128>, cudaFuncAttributeMaxDynamicSharedMemorySize, SM_T0);
    cudaFuncSetAttribute(gemm_tf32<0,0,1,128>, cudaFuncAttributeMaxDynamicSharedMemorySize, SM_T0);
    cudaFuncSetAttribute(gemm_tf32<1,1,1,128>, cudaFuncAttributeMaxDynamicSharedMemorySize, SM_T1);
    cudaFuncSetAttribute(gemm_tf32<1,0,0,128>, cudaFuncAttributeMaxDynamicSharedMemorySize, SM_T1);
    cudaFuncSetAttribute(gemm_tf32<0,1,0,128>, cudaFuncAttributeMaxDynamicSharedMemorySize, SM_T0);
    cudaFuncSetAttribute(gemm_tf32<0,1,1,64>,  cudaFuncAttributeMaxDynamicSharedMemorySize, SM_T64);

    // --- prep: tf32-round weights (+ negated Wm_im / Wo_im / Wmi_im) ---
    {
        PrepBatch pb{};
        const float* srcs[NPREP] = {Wq_re, Wq_im, Wk_re, Wk_im, Wv_re, Wv_im,
                                    Wm_re, Wm_im, Wo_re, Wo_im, Wmi_re, Wmi_im};
        float* dsts[NPREP] = {rWq_re, rWq_im, rWk_re, rWk_im, rWv_re, rWv_im,
                              rWm_re, rWm_im, rWo_re, rWo_im, rWmi_re, rWmi_im};
        float* negs[NPREP] = {nullptr, nullptr, nullptr, nullptr, nullptr, nullptr,
                              nullptr, rWm_imn, nullptr, rWo_imn, nullptr, rWmi_imn};
        int ns[NPREP] = {HID*HID, HID*HID, HID*HID, HID*HID, HID*HID, HID*HID,
                         HDIM*MAN, HDIM*MAN, HID*HID, HID*HID, MAN*HDIM, MAN*HDIM};
        for (int i = 0; i < NPREP; i++) {
            pb.src[i] = srcs[i]; pb.dst[i] = dsts[i]; pb.neg[i] = negs[i]; pb.n[i] = ns[i];
        }
        prep_kernel<<<dim3(32, NPREP), 256>>>(pb);
    }

    norm_kernel<<<NROWS, 128>>>(x, xn);

    dim3 tb(128);

    // --- precompute fused QKV+manifold weights: Wxm = Wx_head @ Wm (complex), z=48 ---
    {
        GemmBatch gb{};
        const float* Wre_[3] = {rWq_re, rWk_re, rWv_re};
        const float* Wim_[3] = {rWq_im, rWk_im, rWv_im};
        float* Fre[3] = {fq_re, fk_re, fv_re};
        float* Fim[3] = {fq_im, fk_im, fv_im};
        int z = 0;
        for (int w = 0; w < 3; w++) {
            for (int h = 0; h < HEADS; h++) {
                gb.A1[z] = Wre_[w] + h * HDIM; gb.B1[z] = rWm_re;
                gb.A2[z] = Wim_[w] + h * HDIM; gb.B2[z] = rWm_imn;
                gb.C[z] = Fre[w] + h * MAN; z++;
                gb.A1[z] = Wre_[w] + h * HDIM; gb.B1[z] = rWm_im;
                gb.A2[z] = Wim_[w] + h * HDIM; gb.B2[z] = rWm_re;
                gb.C[z] = Fim[w] + h * MAN; z++;
            }
        }
        gemm_tf32<0,1,1,128><<<dim3(MAN/128, HID/128, 48), tb, SM_T0>>>(gb, HDIM, HID, MAN, DM2, 1, 1.f);
    }

    // --- R_h = Wqm_re_h Wkm_re_h^T + Wqm_im_h Wkm_im_h^T  [512,512] per head, z=8 ---
    {
        GemmBatch gb{};
        for (int h = 0; h < HEADS; h++) {
            gb.A1[h] = fq_re + h * MAN; gb.B1[h] = fk_re + h * MAN;
            gb.A2[h] = fq_im + h * MAN; gb.B2[h] = fk_im + h * MAN;
            gb.C[h]  = R + (size_t)h * HID * HID;
        }
        gemm_tf32<1,1,1,128><<<dim3(HID/128, HID/128, HEADS), tb, SM_T1>>>(gb, MAN, DM2, DM2, HID, 1, 1.f);
    }

    // --- Qeff_h = xn @ R_h  [4096,512] per head, z=8 ---
    {
        GemmBatch gb{};
        for (int h = 0; h < HEADS; h++) {
            gb.A1[h] = xn;
            gb.B1[h] = R + (size_t)h * HID * HID;
            gb.C[h]  = Qeff + (size_t)h * HID;
        }
        gemm_tf32<0,0,1,128><<<dim3(HID/128, NROWS/128, HEADS), tb, SM_T0>>>(gb, HID, HID, HID, QLD, 1, 1.f);
    }

    // --- V projection only: [4096,512] @ [512,2048], z=2 ---
    {
        GemmBatch gb{};
        gb.A1[0] = xn; gb.B1[0] = fv_re; gb.C[0] = Vre;
        gb.A1[1] = xn; gb.B1[1] = fv_im; gb.C[1] = Vim;
        gemm_tf32<0,0,1,128><<<dim3(DM2/128, NROWS/128, 2), tb, SM_T0>>>(gb, HID, HID, DM2, DM2, 1, 1.f);
    }

    // --- scores: S_h = SCALE * Qeff_h @ xn^T, z=16 (single product) ---
    {
        GemmBatch gb{};
        for (int z = 0; z < BH; z++) {
            int b = z >> 3, h = z & 7;
            gb.A1[z] = Qeff + (size_t)b * SEQ * QLD + (size_t)h * HID;
            gb.B1[z] = xn + (size_t)b * SEQ * HID;
            gb.C[z] = S + (size_t)z * SEQ * SEQ;
        }
        gemm_tf32<1,0,0,128><<<dim3(SEQ/128, SEQ/128, BH), tb, SM_T1>>>(gb, HID, QLD, HID, SEQ, 1, SCALE);
    }

    softmax_kernel<<<dim3(SEQ, BH), 256>>>(S);

    // --- PV: Om_re = P Vre, Om_im = P Vim, z=32 (rounded: feeds wmi gemm) ---
    {
        GemmBatch gb{};
        for (int z = 0; z < BH; z++) {
            int b = z >> 3, h = z & 7;
            size_t off = (size_t)b * SEQ * DM2 + (size_t)h * MAN;
            gb.A1[z]      = S + (size_t)z * SEQ * SEQ;
            gb.B1[z]      = Vre + off;
            gb.C[z]       = Om_re + off;
            gb.A1[z + BH] = S + (size_t)z * SEQ * SEQ;
            gb.B1[z + BH] = Vim + off;
            gb.C[z + BH]  = Om_im + off;
        }
        gemm_tf32<0,0,1,128><<<dim3(MAN/128, SEQ/128, 2*BH), tb, SM_T0>>>(gb, SEQ, SEQ, DM2, DM2, 1, 1.f);
    }

    // --- Wmi back-projection + head merge as tensor-core gemm: z=16 (8 heads x {re,im}) ---
    {
        GemmBatch gb{};
        for (int h = 0; h < HEADS; h++) {
            int z0 = 2 * h;
            gb.A1[z0] = Om_re + (size_t)h * MAN; gb.B1[z0] = rWmi_re;
            gb.A2[z0] = Om_im + (size_t)h * MAN; gb.B2[z0] = rWmi_imn;
            gb.C[z0]  = oh_re + (size_t)h * HDIM;
            gb.A1[z0+1] = Om_re + (size_t)h * MAN; gb.B1[z0+1] = rWmi_im;
            gb.A2[z0+1] = Om_im + (size_t)h * MAN; gb.B2[z0+1] = rWmi_re;
            gb.C[z0+1]  = oh_im + (size_t)h * HDIM;
        }
        gemm_tf32<0,1,1,64><<<dim3(1, NROWS/128, 16), tb, SM_T64>>>(gb, MAN, DM2, HDIM, HID, 1, 1.f);
    }

    // --- output projection: complex Wo, interleaved [.,512,2], z=2 ---
    {
        GemmBatch gb{};
        gb.A1[0] = oh_re; gb.B1[0] = rWo_re; gb.A2[0] = oh_im; gb.B2[0] = rWo_imn;
        gb.C[0] = out;
        gb.A1[1] = oh_re; gb.B1[1] = rWo_im; gb.A2[1] = oh_im; gb.B2[1] = rWo_re;
        gb.C[1] = out + 1;
        gemm_tf32<0,1,0,128><<<dim3(HID/128, NROWS/128, 2), tb, SM_T0>>>(gb, HID, HID, HID, 2*HID, 2, 1.f);
    }
}

// round 16
// speedup vs baseline: 3.4637x; 1.3968x over previous
#include <cuda_runtime.h>
#include <cuda_bf16.h>
#include <cstdint>

#define BATCH 2
#define SEQ   2048
#define HID   512
#define HEADS 8
#define HDIM  64
#define MAN   256
#define DM2   2048           // HEADS*MAN
#define NROWS (BATCH*SEQ)    // 4096
#define BH    (BATCH*HEADS)  // 16
#define SCALE 0.125f         // 64^-0.5

#define AROW 20              // padded smem row (floats): conflict-free ldmatrix
#define STAGES 4
#define ASZ (128*AROW)       // floats per A stage

// ---------------- scratch (device globals; no allocations) ----------------
__device__ float g_xn[NROWS * HID];
__device__ float g_fv_re[HID * DM2];
__device__ float g_fv_im[HID * DM2];
__device__ float g_qre[NROWS * HID];    // xn @ Wq_re   (heads in 64-col blocks)
__device__ float g_qim[NROWS * HID];
__device__ float g_kre[NROWS * HID];    // xn @ (Wk M)_re
__device__ float g_kim[NROWS * HID];
__device__ float g_Vre[(size_t)NROWS * DM2];
__device__ float g_Vim[(size_t)NROWS * DM2];
__device__ float g_S[(size_t)BH * SEQ * SEQ];           // 268 MB
__device__ float g_Om_re[(size_t)NROWS * DM2];
__device__ float g_Om_im[(size_t)NROWS * DM2];
__device__ float g_oh_re[NROWS * HID];
__device__ float g_oh_im[NROWS * HID];
__device__ float g_WkM_re[HID * HID];   // Wk_h @ M, heads in 64-col blocks
__device__ float g_WkM_im[HID * HID];
__device__ float g_M_re[HDIM * HDIM];
__device__ float g_M_im[HDIM * HDIM];
__device__ float g_M_imn[HDIM * HDIM];
// pre-rounded (tf32) weight copies
__device__ float g_rWq_re[HID * HID];
__device__ float g_rWq_im[HID * HID];
__device__ float g_rWk_re[HID * HID];
__device__ float g_rWk_im[HID * HID];
__device__ float g_rWv_re[HID * HID];
__device__ float g_rWv_im[HID * HID];
__device__ float g_rWm_re[HDIM * MAN];
__device__ float g_rWm_im[HDIM * MAN];
__device__ float g_rWm_imn[HDIM * MAN];
__device__ float g_rWo_re[HID * HID];
__device__ float g_rWo_im[HID * HID];
__device__ float g_rWo_imn[HID * HID];
__device__ float g_rWmi_re[MAN * HDIM];
__device__ float g_rWmi_im[MAN * HDIM];
__device__ float g_rWmi_imn[MAN * HDIM];

#define MAXB 48
struct GemmBatch {
    const float* A1[MAXB];
    const float* B1[MAXB];
    const float* A2[MAXB];
    const float* B2[MAXB];
    float*       C[MAXB];
};
#define NPREP 12
struct PrepBatch {
    const float* src[NPREP];
    float* dst[NPREP];
    float* neg[NPREP];
    int n[NPREP];
};

// ---------------- helpers ----------------
__device__ __forceinline__ float to_tf32(float x) {
    asm("cvt.rna.tf32.f32 %0, %1;" : "=f"(x) : "f"(x));
    return x;
}
__device__ __forceinline__ void mma_tf32(float c[4], const uint32_t a[4], const uint32_t b[2]) {
    asm volatile(
        "mma.sync.aligned.m16n8k8.row.col.f32.tf32.tf32.f32 "
        "{%0,%1,%2,%3},{%4,%5,%6,%7},{%8,%9},{%0,%1,%2,%3};"
        : "+f"(c[0]), "+f"(c[1]), "+f"(c[2]), "+f"(c[3])
        : "r"(a[0]), "r"(a[1]), "r"(a[2]), "r"(a[3]), "r"(b[0]), "r"(b[1]));
}
__device__ __forceinline__ void ldsm_x4(uint32_t r[4], uint32_t addr) {
    asm volatile("ldmatrix.sync.aligned.m8n8.x4.shared.b16 {%0,%1,%2,%3}, [%4];"
        : "=r"(r[0]), "=r"(r[1]), "=r"(r[2]), "=r"(r[3]) : "r"(addr));
}
__device__ __forceinline__ void cp_async16(uint32_t dst, const float* src) {
    asm volatile("cp.async.cg.shared.global [%0], [%1], 16;" :: "r"(dst), "l"(src));
}
__device__ __forceinline__ void cp_commit() {
    asm volatile("cp.async.commit_group;");
}
template<int N>
__device__ __forceinline__ void cp_wait() {
    asm volatile("cp.async.wait_group %0;" :: "n"(N));
}

// ---------------- prep: tf32-round (and negate) weight inputs ----------------
__global__ void prep_kernel(PrepBatch pb) {
    int e = blockIdx.y;
    const float* s = pb.src[e];
    float* d = pb.dst[e];
    float* dn = pb.neg[e];
    int n = pb.n[e];
    for (int i = blockIdx.x * blockDim.x + threadIdx.x; i < n; i += gridDim.x * blockDim.x) {
        float v = to_tf32(s[i]);
        d[i] = v;
        if (dn) dn[i] = -v;
    }
}

// ---------------- M = Wm Wm^H  [64,64] complex Hermitian, tf32-rounded ----------------
__global__ void m_kernel(const float* __restrict__ Wm_re, const float* __restrict__ Wm_im,
                         float* __restrict__ M_re, float* __restrict__ M_im,
                         float* __restrict__ M_imn) {
    int i = blockIdx.x;        // 64
    int j = threadIdx.x;       // 64
    float sre = 0.f, sim = 0.f;
    for (int m = 0; m < MAN; m++) {
        float ar = Wm_re[i * MAN + m], ai = Wm_im[i * MAN + m];
        float br = Wm_re[j * MAN + m], bi = Wm_im[j * MAN + m];
        sre += ar * br + ai * bi;
        sim += ai * br - ar * bi;
    }
    sre = to_tf32(sre); sim = to_tf32(sim);
    M_re[i * HDIM + j] = sre;
    M_im[i * HDIM + j] = sim;
    M_imn[i * HDIM + j] = -sim;
}

// ---------------- row L2-normalize (tf32-rounded output) ----------------
__global__ void norm_kernel(const float* __restrict__ x, float* __restrict__ xn) {
    int row = blockIdx.x;
    int t = threadIdx.x;
    const float4* xr = (const float4*)(x + (size_t)row * HID);
    float4 v = xr[t];
    float ss = v.x*v.x + v.y*v.y + v.z*v.z + v.w*v.w;
    #pragma unroll
    for (int o = 16; o > 0; o >>= 1) ss += __shfl_xor_sync(0xffffffffu, ss, o);
    __shared__ float ws[4];
    if ((t & 31) == 0) ws[t >> 5] = ss;
    __syncthreads();
    float tot = ws[0] + ws[1] + ws[2] + ws[3];
    float inv = 1.0f / sqrtf(tot);
    v.x = to_tf32(v.x * inv); v.y = to_tf32(v.y * inv);
    v.z = to_tf32(v.z * inv); v.w = to_tf32(v.w * inv);
    ((float4*)(xn + (size_t)row * HID))[t] = v;
}

// ---------------- tf32 tensor-core GEMM (cp.async 4-stage pipeline) ----------------
// 128xBN CTA tile, BK=16, 4 warps (2x2), 64x(BN/2) per warp.
// Inputs MUST be pre-rounded to tf32.  TWO=1: C = sign*(A1@B1 + A2@B2).
// ROUNDC=1: round C writes to tf32 (for tensors feeding later gemms).
template<int TRANSB, int TWO, int ROUNDC, int BN>
__global__ __launch_bounds__(128)
void gemm_tf32(GemmBatch gb, int K, int lda, int ldb, int ldc, int cstride, float sign) {
    constexpr int NI = BN / 16;                 // 8-wide n-frags per warp
    constexpr int BROW = (BN == 128) ? 136 : 72;
    constexpr int BSZ = TRANSB ? (BN * AROW) : (16 * BROW);
    constexpr int BITER = BN / 32;              // cp.async iters for B

    extern __shared__ char dynsmem[];
    float* As = (float*)dynsmem;
    float* Bs = (float*)(dynsmem + STAGES * ASZ * 4);

    const int tid = threadIdx.x;
    const int bz = blockIdx.z;
    const float* A1 = gb.A1[bz];
    const float* B1 = gb.B1[bz];
    const float* A2 = TWO ? gb.A2[bz] : nullptr;
    const float* B2 = TWO ? gb.B2[bz] : nullptr;
    float* C = gb.C[bz];

    const int row0 = blockIdx.y * 128;
    const int col0 = blockIdx.x * BN;
    const int warp = tid >> 5, lane = tid & 31;
    const int wm = (warp & 1) * 64;
    const int wn = (warp >> 1) * (BN / 2);
    const int g = lane >> 2, tig = lane & 3;

    const uint32_t As_u32 = (uint32_t)__cvta_generic_to_shared(As);
    const uint32_t Bs_u32 = (uint32_t)__cvta_generic_to_shared(Bs);
    const int arow = (lane & 7) + ((lane >> 3) & 1) * 8;
    const int akoff = (lane >> 4) * 4;

    float c[4][NI][4] = {};
    const int nk = TWO ? 2 * K : K;

    auto issue_stage = [&](int kt, int sbuf) {
        if (kt < nk) {
            int p = TWO && (kt >= K);
            const float* Ap = p ? A2 : A1;
            const float* Bp = p ? B2 : B1;
            int kk = kt - (p ? K : 0);
            uint32_t ab = As_u32 + (uint32_t)(sbuf * ASZ * 4);
            uint32_t bb = Bs_u32 + (uint32_t)(sbuf * BSZ * 4);
            #pragma unroll
            for (int i = 0; i < 4; i++) {
                int idx = tid + i * 128;
                int r = idx >> 2, kq = (idx & 3) * 4;
                cp_async16(ab + (uint32_t)((r * AROW + kq) * 4),
                           Ap + (size_t)(row0 + r) * lda + kk + kq);
            }
            if (TRANSB) {
                #pragma unroll
                for (int i = 0; i < BITER; i++) {
                    int idx = tid + i * 128;
                    int n = idx >> 2, kq = (idx & 3) * 4;
                    cp_async16(bb + (uint32_t)((n * AROW + kq) * 4),
                               Bp + (size_t)(col0 + n) * ldb + kk + kq);
                }
            } else {
                #pragma unroll
                for (int i = 0; i < BITER; i++) {
                    int idx = tid + i * 128;
                    int r = idx / (BN / 4), nq = (idx % (BN / 4)) * 4;
                    cp_async16(bb + (uint32_t)((r * BROW + nq) * 4),
                               Bp + (size_t)(kk + r) * ldb + col0 + nq);
                }
            }
        }
        cp_commit();
    };

    issue_stage(0, 0);
    issue_stage(16, 1);
    issue_stage(32, 2);

    for (int kt = 0; kt < nk; kt += 16) {
        const int s = (kt >> 4) & 3;
        cp_wait<2>();
        __syncthreads();
        issue_stage(kt + 48, (s + 3) & 3);

        #pragma unroll
        for (int kc = 0; kc < 2; kc++) {
            uint32_t a[4][4], b[NI][2];
            #pragma unroll
            for (int mi = 0; mi < 4; mi++) {
                uint32_t addr = As_u32 +
                    (uint32_t)(((s * ASZ) + (wm + mi * 16 + arow) * AROW + kc * 8 + akoff) * 4);
                ldsm_x4(a[mi], addr);
            }
            if (TRANSB) {
                #pragma unroll
                for (int nj = 0; nj < NI / 2; nj++) {
                    uint32_t r4[4];
                    uint32_t addr = Bs_u32 +
                        (uint32_t)(((s * BSZ) + (wn + nj * 16 + arow) * AROW + kc * 8 + akoff) * 4);
                    ldsm_x4(r4, addr);
                    b[2*nj][0]   = r4[0]; b[2*nj][1]   = r4[2];
                    b[2*nj+1][0] = r4[1]; b[2*nj+1][1] = r4[3];
                }
            } else {
                const int kb = kc * 8;
                #pragma unroll
                for (int ni = 0; ni < NI; ni++) {
                    int n = wn + ni * 8 + g;
                    b[ni][0] = __float_as_uint(Bs[s * BSZ + (kb + tig) * BROW + n]);
                    b[ni][1] = __float_as_uint(Bs[s * BSZ + (kb + tig + 4) * BROW + n]);
                }
            }
            #pragma unroll
            for (int mi = 0; mi < 4; mi++)
                #pragma unroll
                for (int ni = 0; ni < NI; ni++)
                    mma_tf32(c[mi][ni], a[mi], b[ni]);
        }
    }

    if (cstride == 1) {
        #pragma unroll
        for (int mi = 0; mi < 4; mi++) {
            int m0 = row0 + wm + mi * 16 + g;
            #pragma unroll
            for (int ni = 0; ni < NI; ni++) {
                int n0 = col0 + wn + ni * 8 + tig * 2;
                #pragma unroll
                for (int half = 0; half < 2; half++) {
                    int m = m0 + half * 8;
                    float vx = sign * c[mi][ni][half * 2];
                    float vy = sign * c[mi][ni][half * 2 + 1];
                    if (ROUNDC) { vx = to_tf32(vx); vy = to_tf32(vy); }
                    *(float2*)(C + (size_t)m * ldc + n0) = make_float2(vx, vy);
                }
            }
        }
    } else {
        #pragma unroll
        for (int mi = 0; mi < 4; mi++) {
            int m0 = row0 + wm + mi * 16 + g;
            #pragma unroll
            for (int ni = 0; ni < NI; ni++) {
                int n0 = col0 + wn + ni * 8 + tig * 2;
                #pragma unroll
                for (int jj = 0; jj < 4; jj++) {
                    int m = m0 + (jj >> 1) * 8;
                    int n = n0 + (jj & 1);
                    float v = sign * c[mi][ni][jj];
                    if (ROUNDC) v = to_tf32(v);
                    C[(size_t)m * ldc + (size_t)n * cstride] = v;
                }
            }
        }
    }
}

// ---------------- row softmax (scores pre-scaled), tf32-rounded output ----------------
__global__ void softmax_kernel(float* __restrict__ S) {
    size_t base = ((size_t)blockIdx.y * SEQ + blockIdx.x) * SEQ;
    float4* row = (float4*)(S + base);
    int t = threadIdx.x;
    float4 v0 = row[t], v1 = row[t + 256];
    float m = fmaxf(fmaxf(fmaxf(v0.x, v0.y), fmaxf(v0.z, v0.w)),
                    fmaxf(fmaxf(v1.x, v1.y), fmaxf(v1.z, v1.w)));
    #pragma unroll
    for (int o = 16; o > 0; o >>= 1) m = fmaxf(m, __shfl_xor_sync(0xffffffffu, m, o));
    __shared__ float red[8];
    if ((t & 31) == 0) red[t >> 5] = m;
    __syncthreads();
    m = red[0];
    #pragma unroll
    for (int i = 1; i < 8; i++) m = fmaxf(m, red[i]);

    v0.x = expf(v0.x - m); v0.y = expf(v0.y - m); v0.z = expf(v0.z - m); v0.w = expf(v0.w - m);
    v1.x = expf(v1.x - m); v1.y = expf(v1.y - m); v1.z = expf(v1.z - m); v1.w = expf(v1.w - m);
    float s = v0.x + v0.y + v0.z + v0.w + v1.x + v1.y + v1.z + v1.w;
    #pragma unroll
    for (int o = 16; o > 0; o >>= 1) s += __shfl_xor_sync(0xffffffffu, s, o);
    __syncthreads();
    if ((t & 31) == 0) red[t >> 5] = s;
    __syncthreads();
    s = red[0];
    #pragma unroll
    for (int i = 1; i < 8; i++) s += red[i];
    float inv = 1.0f / s;
    v0.x = to_tf32(v0.x * inv); v0.y = to_tf32(v0.y * inv);
    v0.z = to_tf32(v0.z * inv); v0.w = to_tf32(v0.w * inv);
    v1.x = to_tf32(v1.x * inv); v1.y = to_tf32(v1.y * inv);
    v1.z = to_tf32(v1.z * inv); v1.w = to_tf32(v1.w * inv);
    row[t] = v0; row[t + 256] = v1;
}

// ---------------- launcher ----------------
extern "C" void kernel_launch(void* const* d_in, const int* in_sizes, int n_in,
                              void* d_out, int out_size) {
    const float* x      = (const float*)d_in[0];
    const float* Wq_re  = (const float*)d_in[1];
    const float* Wq_im  = (const float*)d_in[2];
    const float* Wk_re  = (const float*)d_in[3];
    const float* Wk_im  = (const float*)d_in[4];
    const float* Wv_re  = (const float*)d_in[5];
    const float* Wv_im  = (const float*)d_in[6];
    const float* Wm_re  = (const float*)d_in[7];
    const float* Wm_im  = (const float*)d_in[8];
    const float* Wmi_re = (const float*)d_in[9];
    const float* Wmi_im = (const float*)d_in[10];
    const float* Wo_re  = (const float*)d_in[11];
    const float* Wo_im  = (const float*)d_in[12];
    float* out = (float*)d_out;

    float *xn, *fv_re, *fv_im, *qre, *qim, *kre, *kim;
    float *Vre, *Vim, *S, *Om_re, *Om_im, *oh_re, *oh_im;
    float *WkM_re, *WkM_im, *M_re, *M_im, *M_imn;
    float *rWq_re, *rWq_im, *rWk_re, *rWk_im, *rWv_re, *rWv_im;
    float *rWm_re, *rWm_im, *rWm_imn, *rWo_re, *rWo_im, *rWo_imn;
    float *rWmi_re, *rWmi_im, *rWmi_imn;
    cudaGetSymbolAddress((void**)&xn,    g_xn);
    cudaGetSymbolAddress((void**)&fv_re, g_fv_re);
    cudaGetSymbolAddress((void**)&fv_im, g_fv_im);
    cudaGetSymbolAddress((void**)&qre,   g_qre);
    cudaGetSymbolAddress((void**)&qim,   g_qim);
    cudaGetSymbolAddress((void**)&kre,   g_kre);
    cudaGetSymbolAddress((void**)&kim,   g_kim);
    cudaGetSymbolAddress((void**)&Vre,   g_Vre);
    cudaGetSymbolAddress((void**)&Vim,   g_Vim);
    cudaGetSymbolAddress((void**)&S,     g_S);
    cudaGetSymbolAddress((void**)&Om_re, g_Om_re);
    cudaGetSymbolAddress((void**)&Om_im, g_Om_im);
    cudaGetSymbolAddress((void**)&oh_re, g_oh_re);
    cudaGetSymbolAddress((void**)&oh_im, g_oh_im);
    cudaGetSymbolAddress((void**)&WkM_re, g_WkM_re);
    cudaGetSymbolAddress((void**)&WkM_im, g_WkM_im);
    cudaGetSymbolAddress((void**)&M_re,  g_M_re);
    cudaGetSymbolAddress((void**)&M_im,  g_M_im);
    cudaGetSymbolAddress((void**)&M_imn, g_M_imn);
    cudaGetSymbolAddress((void**)&rWq_re, g_rWq_re);
    cudaGetSymbolAddress((void**)&rWq_im, g_rWq_im);
    cudaGetSymbolAddress((void**)&rWk_re, g_rWk_re);
    cudaGetSymbolAddress((void**)&rWk_im, g_rWk_im);
    cudaGetSymbolAddress((void**)&rWv_re, g_rWv_re);
    cudaGetSymbolAddress((void**)&rWv_im, g_rWv_im);
    cudaGetSymbolAddress((void**)&rWm_re, g_rWm_re);
    cudaGetSymbolAddress((void**)&rWm_im, g_rWm_im);
    cudaGetSymbolAddress((void**)&rWm_imn, g_rWm_imn);
    cudaGetSymbolAddress((void**)&rWo_re, g_rWo_re);
    cudaGetSymbolAddress((void**)&rWo_im, g_rWo_im);
    cudaGetSymbolAddress((void**)&rWo_imn, g_rWo_imn);
    cudaGetSymbolAddress((void**)&rWmi_re, g_rWmi_re);
    cudaGetSymbolAddress((void**)&rWmi_im, g_rWmi_im);
    cudaGetSymbolAddress((void**)&rWmi_imn, g_rWmi_imn);

    const int SM_T1  = STAGES * ASZ * 4 * 2;                  // TRANSB=1, BN=128
    const int SM_T0  = STAGES * ASZ * 4 + STAGES * 16*136*4;  // NN, BN=128
    const int SM_T64 = STAGES * ASZ * 4 + STAGES * 16*72*4;   // NN, BN=64
    cudaFuncSetAttribute(gemm_tf32<0,1,1,128>, cudaFuncAttributeMaxDynamicSharedMemorySize, SM_T0);
    cudaFuncSetAttribute(gemm_tf32<0,0,1,128>, cudaFuncAttributeMaxDynamicSharedMemorySize, SM_T0);
    cudaFuncSetAttribute(gemm_tf32<1,1,0,128>, cudaFuncAttributeMaxDynamicSharedMemorySize, SM_T1);
    cudaFuncSetAttribute(gemm_tf32<0,1,0,128>, cudaFuncAttributeMaxDynamicSharedMemorySize, SM_T0);
    cudaFuncSetAttribute(gemm_tf32<0,1,1,64>,  cudaFuncAttributeMaxDynamicSharedMemorySize, SM_T64);

    // --- prep: tf32-round weights (+ negated Wm_im / Wo_im / Wmi_im) ---
    {
        PrepBatch pb{};
        const float* srcs[NPREP] = {Wq_re, Wq_im, Wk_re, Wk_im, Wv_re, Wv_im,
                                    Wm_re, Wm_im, Wo_re, Wo_im, Wmi_re, Wmi_im};
        float* dsts[NPREP] = {rWq_re, rWq_im, rWk_re, rWk_im, rWv_re, rWv_im,
                              rWm_re, rWm_im, rWo_re, rWo_im, rWmi_re, rWmi_im};
        float* negs[NPREP] = {nullptr, nullptr, nullptr, nullptr, nullptr, nullptr,
                              nullptr, rWm_imn, nullptr, rWo_imn, nullptr, rWmi_imn};
        int ns[NPREP] = {HID*HID, HID*HID, HID*HID, HID*HID, HID*HID, HID*HID,
                         HDIM*MAN, HDIM*MAN, HID*HID, HID*HID, MAN*HDIM, MAN*HDIM};
        for (int i = 0; i < NPREP; i++) {
            pb.src[i] = srcs[i]; pb.dst[i] = dsts[i]; pb.neg[i] = negs[i]; pb.n[i] = ns[i];
        }
        prep_kernel<<<dim3(32, NPREP), 256>>>(pb);
    }

    // --- M = Wm Wm^H  [64,64] ---
    m_kernel<<<HDIM, HDIM>>>(Wm_re, Wm_im, M_re, M_im, M_imn);

    norm_kernel<<<NROWS, 128>>>(x, xn);

    dim3 tb(128);

    // --- fused V+manifold weights only: Wvm = Wv_head @ Wm (complex), z=16 ---
    {
        GemmBatch gb{};
        int z = 0;
        for (int h = 0; h < HEADS; h++) {
            gb.A1[z] = rWv_re + h * HDIM; gb.B1[z] = rWm_re;
            gb.A2[z] = rWv_im + h * HDIM; gb.B2[z] = rWm_imn;
            gb.C[z] = fv_re + h * MAN; z++;
            gb.A1[z] = rWv_re + h * HDIM; gb.B1[z] = rWm_im;
            gb.A2[z] = rWv_im + h * HDIM; gb.B2[z] = rWm_re;
            gb.C[z] = fv_im + h * MAN; z++;
        }
        gemm_tf32<0,1,1,128><<<dim3(MAN/128, HID/128, 16), tb, SM_T0>>>(gb, HDIM, HID, MAN, DM2, 1, 1.f);
    }

    // --- WkM_h = Wk_h @ M (complex), [512,64] per head, z=16, BN=64 ---
    {
        GemmBatch gb{};
        for (int h = 0; h < HEADS; h++) {
            int z0 = 2 * h;
            gb.A1[z0] = rWk_re + h * HDIM; gb.B1[z0] = M_re;
            gb.A2[z0] = rWk_im + h * HDIM; gb.B2[z0] = M_imn;
            gb.C[z0]  = WkM_re + h * HDIM;
            gb.A1[z0+1] = rWk_re + h * HDIM; gb.B1[z0+1] = M_im;
            gb.A2[z0+1] = rWk_im + h * HDIM; gb.B2[z0+1] = M_re;
            gb.C[z0+1]  = WkM_im + h * HDIM;
        }
        gemm_tf32<0,1,1,64><<<dim3(1, HID/128, 16), tb, SM_T64>>>(gb, HDIM, HID, HDIM, HID, 1, 1.f);
    }

    // --- q'/kM projections: z=4, [4096,512] @ [512,512] ---
    {
        GemmBatch gb{};
        const float* Bp[4] = {rWq_re, rWq_im, WkM_re, WkM_im};
        float* Cp[4] = {qre, qim, kre, kim};
        for (int i = 0; i < 4; i++) { gb.A1[i] = xn; gb.B1[i] = Bp[i]; gb.C[i] = Cp[i]; }
        gemm_tf32<0,0,1,128><<<dim3(HID/128, NROWS/128, 4), tb, SM_T0>>>(gb, HID, HID, HID, HID, 1, 1.f);
    }

    // --- V projection: [4096,512] @ [512,2048], z=2 ---
    {
        GemmBatch gb{};
        gb.A1[0] = xn; gb.B1[0] = fv_re; gb.C[0] = Vre;
        gb.A1[1] = xn; gb.B1[1] = fv_im; gb.C[1] = Vim;
        gemm_tf32<0,0,1,128><<<dim3(DM2/128, NROWS/128, 2), tb, SM_T0>>>(gb, HID, HID, DM2, DM2, 1, 1.f);
    }

    // --- scores: S_h = SCALE * (q're kM_re^T + q'im kM_im^T), K=64 x2, z=16 ---
    {
        GemmBatch gb{};
        for (int z = 0; z < BH; z++) {
            int b = z >> 3, h = z & 7;
            size_t off = (size_t)b * SEQ * HID + (size_t)h * HDIM;
            gb.A1[z] = qre + off; gb.B1[z] = kre + off;
            gb.A2[z] = qim + off; gb.B2[z] = kim + off;
            gb.C[z] = S + (size_t)z * SEQ * SEQ;
        }
        gemm_tf32<1,1,0,128><<<dim3(SEQ/128, SEQ/128, BH), tb, SM_T1>>>(gb, HDIM, HID, HID, SEQ, 1, SCALE);
    }

    softmax_kernel<<<dim3(SEQ, BH), 256>>>(S);

    // --- PV: Om_re = P Vre, Om_im = P Vim, z=32 (rounded: feeds wmi gemm) ---
    {
        GemmBatch gb{};
        for (int z = 0; z < BH; z++) {
            int b = z >> 3, h = z & 7;
            size_t off = (size_t)b * SEQ * DM2 + (size_t)h * MAN;
            gb.A1[z]      = S + (size_t)z * SEQ * SEQ;
            gb.B1[z]      = Vre + off;
            gb.C[z]       = Om_re + off;
            gb.A1[z + BH] = S + (size_t)z * SEQ * SEQ;
            gb.B1[z + BH] = Vim + off;
            gb.C[z + BH]  = Om_im + off;
        }
        gemm_tf32<0,0,1,128><<<dim3(MAN/128, SEQ/128, 2*BH), tb, SM_T0>>>(gb, SEQ, SEQ, DM2, DM2, 1, 1.f);
    }

    // --- Wmi back-projection + head merge as tensor-core gemm: z=16 (8 heads x {re,im}) ---
    {
        GemmBatch gb{};
        for (int h = 0; h < HEADS; h++) {
            int z0 = 2 * h;
            gb.A1[z0] = Om_re + (size_t)h * MAN; gb.B1[z0] = rWmi_re;
            gb.A2[z0] = Om_im + (size_t)h * MAN; gb.B2[z0] = rWmi_imn;
            gb.C[z0]  = oh_re + (size_t)h * HDIM;
            gb.A1[z0+1] = Om_re + (size_t)h * MAN; gb.B1[z0+1] = rWmi_im;
            gb.A2[z0+1] = Om_im + (size_t)h * MAN; gb.B2[z0+1] = rWmi_re;
            gb.C[z0+1]  = oh_im + (size_t)h * HDIM;
        }
        gemm_tf32<0,1,1,64><<<dim3(1, NROWS/128, 16), tb, SM_T64>>>(gb, MAN, DM2, HDIM, HID, 1, 1.f);
    }

    // --- output projection: complex Wo, interleaved [.,512,2], z=2 ---
    {
        GemmBatch gb{};
        gb.A1[0] = oh_re; gb.B1[0] = rWo_re; gb.A2[0] = oh_im; gb.B2[0] = rWo_imn;
        gb.C[0] = out;
        gb.A1[1] = oh_re; gb.B1[1] = rWo_im; gb.A2[1] = oh_im; gb.B2[1] = rWo_re;
        gb.C[1] = out + 1;
        gemm_tf32<0,1,0,128><<<dim3(HID/128, NROWS/128, 2), tb, SM_T0>>>(gb, HID, HID, HID, 2*HID, 2, 1.f);
    }
}

// round 17
// speedup vs baseline: 3.8271x; 1.1049x over previous
#include <cuda_runtime.h>
#include <cuda_bf16.h>
#include <cstdint>

#define BATCH 2
#define SEQ   2048
#define HID   512
#define HEADS 8
#define HDIM  64
#define MAN   256
#define DM2   2048           // HEADS*MAN
#define NROWS (BATCH*SEQ)    // 4096
#define BH    (BATCH*HEADS)  // 16
#define SCALE 0.125f         // 64^-0.5

#define AROW 20              // padded smem row (floats): conflict-free ldmatrix
#define STAGES 4
#define ASZ (128*AROW)       // floats per A stage

// ---------------- scratch (device globals; no allocations) ----------------
__device__ float g_xn[NROWS * HID];
__device__ float g_fv_re[HID * DM2];
__device__ float g_fv_im[HID * DM2];
__device__ float g_qre[NROWS * HID];    // xn @ Wq_re   (heads in 64-col blocks)
__device__ float g_qim[NROWS * HID];
__device__ float g_kre[NROWS * HID];    // xn @ (Wk M)_re
__device__ float g_kim[NROWS * HID];
__device__ float g_S[(size_t)BH * SEQ * SEQ];           // 268 MB
__device__ float g_T[(size_t)BH * SEQ * HID];           // P @ xn, 67 MB
__device__ float g_oh_re[NROWS * HID];
__device__ float g_oh_im[NROWS * HID];
__device__ float g_WkM_re[HID * HID];   // Wk_h @ M, heads in 64-col blocks
__device__ float g_WkM_im[HID * HID];
__device__ float g_E_re[HID * HID];     // Wvm_h @ Wmi, heads in 64-col blocks
__device__ float g_E_im[HID * HID];
__device__ float g_M_re[HDIM * HDIM];
__device__ float g_M_im[HDIM * HDIM];
__device__ float g_M_imn[HDIM * HDIM];
// pre-rounded (tf32) weight copies
__device__ float g_rWq_re[HID * HID];
__device__ float g_rWq_im[HID * HID];
__device__ float g_rWk_re[HID * HID];
__device__ float g_rWk_im[HID * HID];
__device__ float g_rWv_re[HID * HID];
__device__ float g_rWv_im[HID * HID];
__device__ float g_rWm_re[HDIM * MAN];
__device__ float g_rWm_im[HDIM * MAN];
__device__ float g_rWm_imn[HDIM * MAN];
__device__ float g_rWo_re[HID * HID];
__device__ float g_rWo_im[HID * HID];
__device__ float g_rWo_imn[HID * HID];
__device__ float g_rWmi_re[MAN * HDIM];
__device__ float g_rWmi_im[MAN * HDIM];
__device__ float g_rWmi_imn[MAN * HDIM];

#define MAXB 48
struct GemmBatch {
    const float* A1[MAXB];
    const float* B1[MAXB];
    const float* A2[MAXB];
    const float* B2[MAXB];
    float*       C[MAXB];
};
#define NPREP 12
struct PrepBatch {
    const float* src[NPREP];
    float* dst[NPREP];
    float* neg[NPREP];
    int n[NPREP];
};

// ---------------- helpers ----------------
__device__ __forceinline__ float to_tf32(float x) {
    asm("cvt.rna.tf32.f32 %0, %1;" : "=f"(x) : "f"(x));
    return x;
}
__device__ __forceinline__ void mma_tf32(float c[4], const uint32_t a[4], const uint32_t b[2]) {
    asm volatile(
        "mma.sync.aligned.m16n8k8.row.col.f32.tf32.tf32.f32 "
        "{%0,%1,%2,%3},{%4,%5,%6,%7},{%8,%9},{%0,%1,%2,%3};"
        : "+f"(c[0]), "+f"(c[1]), "+f"(c[2]), "+f"(c[3])
        : "r"(a[0]), "r"(a[1]), "r"(a[2]), "r"(a[3]), "r"(b[0]), "r"(b[1]));
}
__device__ __forceinline__ void ldsm_x4(uint32_t r[4], uint32_t addr) {
    asm volatile("ldmatrix.sync.aligned.m8n8.x4.shared.b16 {%0,%1,%2,%3}, [%4];"
        : "=r"(r[0]), "=r"(r[1]), "=r"(r[2]), "=r"(r[3]) : "r"(addr));
}
__device__ __forceinline__ void cp_async16(uint32_t dst, const float* src) {
    asm volatile("cp.async.cg.shared.global [%0], [%1], 16;" :: "r"(dst), "l"(src));
}
__device__ __forceinline__ void cp_commit() {
    asm volatile("cp.async.commit_group;");
}
template<int N>
__device__ __forceinline__ void cp_wait() {
    asm volatile("cp.async.wait_group %0;" :: "n"(N));
}

// ---------------- prep: tf32-round (and negate) weight inputs ----------------
__global__ void prep_kernel(PrepBatch pb) {
    int e = blockIdx.y;
    const float* s = pb.src[e];
    float* d = pb.dst[e];
    float* dn = pb.neg[e];
    int n = pb.n[e];
    for (int i = blockIdx.x * blockDim.x + threadIdx.x; i < n; i += gridDim.x * blockDim.x) {
        float v = to_tf32(s[i]);
        d[i] = v;
        if (dn) dn[i] = -v;
    }
}

// ---------------- M = Wm Wm^H  [64,64] complex Hermitian, tf32-rounded ----------------
__global__ void m_kernel(const float* __restrict__ Wm_re, const float* __restrict__ Wm_im,
                         float* __restrict__ M_re, float* __restrict__ M_im,
                         float* __restrict__ M_imn) {
    int i = blockIdx.x;        // 64
    int j = threadIdx.x;       // 64
    float sre = 0.f, sim = 0.f;
    for (int m = 0; m < MAN; m++) {
        float ar = Wm_re[i * MAN + m], ai = Wm_im[i * MAN + m];
        float br = Wm_re[j * MAN + m], bi = Wm_im[j * MAN + m];
        sre += ar * br + ai * bi;
        sim += ai * br - ar * bi;
    }
    sre = to_tf32(sre); sim = to_tf32(sim);
    M_re[i * HDIM + j] = sre;
    M_im[i * HDIM + j] = sim;
    M_imn[i * HDIM + j] = -sim;
}

// ---------------- row L2-normalize (tf32-rounded output) ----------------
__global__ void norm_kernel(const float* __restrict__ x, float* __restrict__ xn) {
    int row = blockIdx.x;
    int t = threadIdx.x;
    const float4* xr = (const float4*)(x + (size_t)row * HID);
    float4 v = xr[t];
    float ss = v.x*v.x + v.y*v.y + v.z*v.z + v.w*v.w;
    #pragma unroll
    for (int o = 16; o > 0; o >>= 1) ss += __shfl_xor_sync(0xffffffffu, ss, o);
    __shared__ float ws[4];
    if ((t & 31) == 0) ws[t >> 5] = ss;
    __syncthreads();
    float tot = ws[0] + ws[1] + ws[2] + ws[3];
    float inv = 1.0f / sqrtf(tot);
    v.x = to_tf32(v.x * inv); v.y = to_tf32(v.y * inv);
    v.z = to_tf32(v.z * inv); v.w = to_tf32(v.w * inv);
    ((float4*)(xn + (size_t)row * HID))[t] = v;
}

// ---------------- tf32 tensor-core GEMM (cp.async 4-stage pipeline) ----------------
// 128xBN CTA tile, BK=16, 4 warps (2x2), 64x(BN/2) per warp.
// Inputs MUST be pre-rounded to tf32.  TWO=1: C = sign*(A1@B1 + A2@B2).
// ROUNDC=1: round C writes to tf32 (for tensors feeding later gemms).
template<int TRANSB, int TWO, int ROUNDC, int BN>
__global__ __launch_bounds__(128)
void gemm_tf32(GemmBatch gb, int K, int lda, int ldb, int ldc, int cstride, float sign) {
    constexpr int NI = BN / 16;                 // 8-wide n-frags per warp
    constexpr int BROW = (BN == 128) ? 136 : 72;
    constexpr int BSZ = TRANSB ? (BN * AROW) : (16 * BROW);
    constexpr int BITER = BN / 32;              // cp.async iters for B

    extern __shared__ char dynsmem[];
    float* As = (float*)dynsmem;
    float* Bs = (float*)(dynsmem + STAGES * ASZ * 4);

    const int tid = threadIdx.x;
    const int bz = blockIdx.z;
    const float* A1 = gb.A1[bz];
    const float* B1 = gb.B1[bz];
    const float* A2 = TWO ? gb.A2[bz] : nullptr;
    const float* B2 = TWO ? gb.B2[bz] : nullptr;
    float* C = gb.C[bz];

    const int row0 = blockIdx.y * 128;
    const int col0 = blockIdx.x * BN;
    const int warp = tid >> 5, lane = tid & 31;
    const int wm = (warp & 1) * 64;
    const int wn = (warp >> 1) * (BN / 2);
    const int g = lane >> 2, tig = lane & 3;

    const uint32_t As_u32 = (uint32_t)__cvta_generic_to_shared(As);
    const uint32_t Bs_u32 = (uint32_t)__cvta_generic_to_shared(Bs);
    const int arow = (lane & 7) + ((lane >> 3) & 1) * 8;
    const int akoff = (lane >> 4) * 4;

    float c[4][NI][4] = {};
    const int nk = TWO ? 2 * K : K;

    auto issue_stage = [&](int kt, int sbuf) {
        if (kt < nk) {
            int p = TWO && (kt >= K);
            const float* Ap = p ? A2 : A1;
            const float* Bp = p ? B2 : B1;
            int kk = kt - (p ? K : 0);
            uint32_t ab = As_u32 + (uint32_t)(sbuf * ASZ * 4);
            uint32_t bb = Bs_u32 + (uint32_t)(sbuf * BSZ * 4);
            #pragma unroll
            for (int i = 0; i < 4; i++) {
                int idx = tid + i * 128;
                int r = idx >> 2, kq = (idx & 3) * 4;
                cp_async16(ab + (uint32_t)((r * AROW + kq) * 4),
                           Ap + (size_t)(row0 + r) * lda + kk + kq);
            }
            if (TRANSB) {
                #pragma unroll
                for (int i = 0; i < BITER; i++) {
                    int idx = tid + i * 128;
                    int n = idx >> 2, kq = (idx & 3) * 4;
                    cp_async16(bb + (uint32_t)((n * AROW + kq) * 4),
                               Bp + (size_t)(col0 + n) * ldb + kk + kq);
                }
            } else {
                #pragma unroll
                for (int i = 0; i < BITER; i++) {
                    int idx = tid + i * 128;
                    int r = idx / (BN / 4), nq = (idx % (BN / 4)) * 4;
                    cp_async16(bb + (uint32_t)((r * BROW + nq) * 4),
                               Bp + (size_t)(kk + r) * ldb + col0 + nq);
                }
            }
        }
        cp_commit();
    };

    issue_stage(0, 0);
    issue_stage(16, 1);
    issue_stage(32, 2);

    for (int kt = 0; kt < nk; kt += 16) {
        const int s = (kt >> 4) & 3;
        cp_wait<2>();
        __syncthreads();
        issue_stage(kt + 48, (s + 3) & 3);

        #pragma unroll
        for (int kc = 0; kc < 2; kc++) {
            uint32_t a[4][4], b[NI][2];
            #pragma unroll
            for (int mi = 0; mi < 4; mi++) {
                uint32_t addr = As_u32 +
                    (uint32_t)(((s * ASZ) + (wm + mi * 16 + arow) * AROW + kc * 8 + akoff) * 4);
                ldsm_x4(a[mi], addr);
            }
            if (TRANSB) {
                #pragma unroll
                for (int nj = 0; nj < NI / 2; nj++) {
                    uint32_t r4[4];
                    uint32_t addr = Bs_u32 +
                        (uint32_t)(((s * BSZ) + (wn + nj * 16 + arow) * AROW + kc * 8 + akoff) * 4);
                    ldsm_x4(r4, addr);
                    b[2*nj][0]   = r4[0]; b[2*nj][1]   = r4[2];
                    b[2*nj+1][0] = r4[1]; b[2*nj+1][1] = r4[3];
                }
            } else {
                const int kb = kc * 8;
                #pragma unroll
                for (int ni = 0; ni < NI; ni++) {
                    int n = wn + ni * 8 + g;
                    b[ni][0] = __float_as_uint(Bs[s * BSZ + (kb + tig) * BROW + n]);
                    b[ni][1] = __float_as_uint(Bs[s * BSZ + (kb + tig + 4) * BROW + n]);
                }
            }
            #pragma unroll
            for (int mi = 0; mi < 4; mi++)
                #pragma unroll
                for (int ni = 0; ni < NI; ni++)
                    mma_tf32(c[mi][ni], a[mi], b[ni]);
        }
    }

    if (cstride == 1) {
        #pragma unroll
        for (int mi = 0; mi < 4; mi++) {
            int m0 = row0 + wm + mi * 16 + g;
            #pragma unroll
            for (int ni = 0; ni < NI; ni++) {
                int n0 = col0 + wn + ni * 8 + tig * 2;
                #pragma unroll
                for (int half = 0; half < 2; half++) {
                    int m = m0 + half * 8;
                    float vx = sign * c[mi][ni][half * 2];
                    float vy = sign * c[mi][ni][half * 2 + 1];
                    if (ROUNDC) { vx = to_tf32(vx); vy = to_tf32(vy); }
                    *(float2*)(C + (size_t)m * ldc + n0) = make_float2(vx, vy);
                }
            }
        }
    } else {
        #pragma unroll
        for (int mi = 0; mi < 4; mi++) {
            int m0 = row0 + wm + mi * 16 + g;
            #pragma unroll
            for (int ni = 0; ni < NI; ni++) {
                int n0 = col0 + wn + ni * 8 + tig * 2;
                #pragma unroll
                for (int jj = 0; jj < 4; jj++) {
                    int m = m0 + (jj >> 1) * 8;
                    int n = n0 + (jj & 1);
                    float v = sign * c[mi][ni][jj];
                    if (ROUNDC) v = to_tf32(v);
                    C[(size_t)m * ldc + (size_t)n * cstride] = v;
                }
            }
        }
    }
}

// ---------------- row softmax (scores pre-scaled), tf32-rounded output ----------------
__global__ void softmax_kernel(float* __restrict__ S) {
    size_t base = ((size_t)blockIdx.y * SEQ + blockIdx.x) * SEQ;
    float4* row = (float4*)(S + base);
    int t = threadIdx.x;
    float4 v0 = row[t], v1 = row[t + 256];
    float m = fmaxf(fmaxf(fmaxf(v0.x, v0.y), fmaxf(v0.z, v0.w)),
                    fmaxf(fmaxf(v1.x, v1.y), fmaxf(v1.z, v1.w)));
    #pragma unroll
    for (int o = 16; o > 0; o >>= 1) m = fmaxf(m, __shfl_xor_sync(0xffffffffu, m, o));
    __shared__ float red[8];
    if ((t & 31) == 0) red[t >> 5] = m;
    __syncthreads();
    m = red[0];
    #pragma unroll
    for (int i = 1; i < 8; i++) m = fmaxf(m, red[i]);

    v0.x = expf(v0.x - m); v0.y = expf(v0.y - m); v0.z = expf(v0.z - m); v0.w = expf(v0.w - m);
    v1.x = expf(v1.x - m); v1.y = expf(v1.y - m); v1.z = expf(v1.z - m); v1.w = expf(v1.w - m);
    float s = v0.x + v0.y + v0.z + v0.w + v1.x + v1.y + v1.z + v1.w;
    #pragma unroll
    for (int o = 16; o > 0; o >>= 1) s += __shfl_xor_sync(0xffffffffu, s, o);
    __syncthreads();
    if ((t & 31) == 0) red[t >> 5] = s;
    __syncthreads();
    s = red[0];
    #pragma unroll
    for (int i = 1; i < 8; i++) s += red[i];
    float inv = 1.0f / s;
    v0.x = to_tf32(v0.x * inv); v0.y = to_tf32(v0.y * inv);
    v0.z = to_tf32(v0.z * inv); v0.w = to_tf32(v0.w * inv);
    v1.x = to_tf32(v1.x * inv); v1.y = to_tf32(v1.y * inv);
    v1.z = to_tf32(v1.z * inv); v1.w = to_tf32(v1.w * inv);
    row[t] = v0; row[t + 256] = v1;
}

// ---------------- launcher ----------------
extern "C" void kernel_launch(void* const* d_in, const int* in_sizes, int n_in,
                              void* d_out, int out_size) {
    const float* x      = (const float*)d_in[0];
    const float* Wq_re  = (const float*)d_in[1];
    const float* Wq_im  = (const float*)d_in[2];
    const float* Wk_re  = (const float*)d_in[3];
    const float* Wk_im  = (const float*)d_in[4];
    const float* Wv_re  = (const float*)d_in[5];
    const float* Wv_im  = (const float*)d_in[6];
    const float* Wm_re  = (const float*)d_in[7];
    const float* Wm_im  = (const float*)d_in[8];
    const float* Wmi_re = (const float*)d_in[9];
    const float* Wmi_im = (const float*)d_in[10];
    const float* Wo_re  = (const float*)d_in[11];
    const float* Wo_im  = (const float*)d_in[12];
    float* out = (float*)d_out;

    float *xn, *fv_re, *fv_im, *qre, *qim, *kre, *kim;
    float *S, *T, *oh_re, *oh_im;
    float *WkM_re, *WkM_im, *E_re, *E_im, *M_re, *M_im, *M_imn;
    float *rWq_re, *rWq_im, *rWk_re, *rWk_im, *rWv_re, *rWv_im;
    float *rWm_re, *rWm_im, *rWm_imn, *rWo_re, *rWo_im, *rWo_imn;
    float *rWmi_re, *rWmi_im, *rWmi_imn;
    cudaGetSymbolAddress((void**)&xn,    g_xn);
    cudaGetSymbolAddress((void**)&fv_re, g_fv_re);
    cudaGetSymbolAddress((void**)&fv_im, g_fv_im);
    cudaGetSymbolAddress((void**)&qre,   g_qre);
    cudaGetSymbolAddress((void**)&qim,   g_qim);
    cudaGetSymbolAddress((void**)&kre,   g_kre);
    cudaGetSymbolAddress((void**)&kim,   g_kim);
    cudaGetSymbolAddress((void**)&S,     g_S);
    cudaGetSymbolAddress((void**)&T,     g_T);
    cudaGetSymbolAddress((void**)&oh_re, g_oh_re);
    cudaGetSymbolAddress((void**)&oh_im, g_oh_im);
    cudaGetSymbolAddress((void**)&WkM_re, g_WkM_re);
    cudaGetSymbolAddress((void**)&WkM_im, g_WkM_im);
    cudaGetSymbolAddress((void**)&E_re,  g_E_re);
    cudaGetSymbolAddress((void**)&E_im,  g_E_im);
    cudaGetSymbolAddress((void**)&M_re,  g_M_re);
    cudaGetSymbolAddress((void**)&M_im,  g_M_im);
    cudaGetSymbolAddress((void**)&M_imn, g_M_imn);
    cudaGetSymbolAddress((void**)&rWq_re, g_rWq_re);
    cudaGetSymbolAddress((void**)&rWq_im, g_rWq_im);
    cudaGetSymbolAddress((void**)&rWk_re, g_rWk_re);
    cudaGetSymbolAddress((void**)&rWk_im, g_rWk_im);
    cudaGetSymbolAddress((void**)&rWv_re, g_rWv_re);
    cudaGetSymbolAddress((void**)&rWv_im, g_rWv_im);
    cudaGetSymbolAddress((void**)&rWm_re, g_rWm_re);
    cudaGetSymbolAddress((void**)&rWm_im, g_rWm_im);
    cudaGetSymbolAddress((void**)&rWm_imn, g_rWm_imn);
    cudaGetSymbolAddress((void**)&rWo_re, g_rWo_re);
    cudaGetSymbolAddress((void**)&rWo_im, g_rWo_im);
    cudaGetSymbolAddress((void**)&rWo_imn, g_rWo_imn);
    cudaGetSymbolAddress((void**)&rWmi_re, g_rWmi_re);
    cudaGetSymbolAddress((void**)&rWmi_im, g_rWmi_im);
    cudaGetSymbolAddress((void**)&rWmi_imn, g_rWmi_imn);

    const int SM_T1  = STAGES * ASZ * 4 * 2;                  // TRANSB=1, BN=128
    const int SM_T0  = STAGES * ASZ * 4 + STAGES * 16*136*4;  // NN, BN=128
    const int SM_T64 = STAGES * ASZ * 4 + STAGES * 16*72*4;   // NN, BN=64
    cudaFuncSetAttribute(gemm_tf32<0,1,1,128>, cudaFuncAttributeMaxDynamicSharedMemorySize, SM_T0);
    cudaFuncSetAttribute(gemm_tf32<0,0,1,128>, cudaFuncAttributeMaxDynamicSharedMemorySize, SM_T0);
    cudaFuncSetAttribute(gemm_tf32<1,1,0,128>, cudaFuncAttributeMaxDynamicSharedMemorySize, SM_T1);
    cudaFuncSetAttribute(gemm_tf32<0,1,0,128>, cudaFuncAttributeMaxDynamicSharedMemorySize, SM_T0);
    cudaFuncSetAttribute(gemm_tf32<0,1,1,64>,  cudaFuncAttributeMaxDynamicSharedMemorySize, SM_T64);
    cudaFuncSetAttribute(gemm_tf32<0,0,1,64>,  cudaFuncAttributeMaxDynamicSharedMemorySize, SM_T64);

    // --- prep: tf32-round weights (+ negated Wm_im / Wo_im / Wmi_im) ---
    {
        PrepBatch pb{};
        const float* srcs[NPREP] = {Wq_re, Wq_im, Wk_re, Wk_im, Wv_re, Wv_im,
                                    Wm_re, Wm_im, Wo_re, Wo_im, Wmi_re, Wmi_im};
        float* dsts[NPREP] = {rWq_re, rWq_im, rWk_re, rWk_im, rWv_re, rWv_im,
                              rWm_re, rWm_im, rWo_re, rWo_im, rWmi_re, rWmi_im};
        float* negs[NPREP] = {nullptr, nullptr, nullptr, nullptr, nullptr, nullptr,
                              nullptr, rWm_imn, nullptr, rWo_imn, nullptr, rWmi_imn};
        int ns[NPREP] = {HID*HID, HID*HID, HID*HID, HID*HID, HID*HID, HID*HID,
                         HDIM*MAN, HDIM*MAN, HID*HID, HID*HID, MAN*HDIM, MAN*HDIM};
        for (int i = 0; i < NPREP; i++) {
            pb.src[i] = srcs[i]; pb.dst[i] = dsts[i]; pb.neg[i] = negs[i]; pb.n[i] = ns[i];
        }
        prep_kernel<<<dim3(32, NPREP), 256>>>(pb);
    }

    // --- M = Wm Wm^H  [64,64] ---
    m_kernel<<<HDIM, HDIM>>>(Wm_re, Wm_im, M_re, M_im, M_imn);

    norm_kernel<<<NROWS, 128>>>(x, xn);

    dim3 tb(128);

    // --- fused V+manifold weights: Wvm = Wv_head @ Wm (complex), z=16 ---
    {
        GemmBatch gb{};
        int z = 0;
        for (int h = 0; h < HEADS; h++) {
            gb.A1[z] = rWv_re + h * HDIM; gb.B1[z] = rWm_re;
            gb.A2[z] = rWv_im + h * HDIM; gb.B2[z] = rWm_imn;
            gb.C[z] = fv_re + h * MAN; z++;
            gb.A1[z] = rWv_re + h * HDIM; gb.B1[z] = rWm_im;
            gb.A2[z] = rWv_im + h * HDIM; gb.B2[z] = rWm_re;
            gb.C[z] = fv_im + h * MAN; z++;
        }
        gemm_tf32<0,1,1,128><<<dim3(MAN/128, HID/128, 16), tb, SM_T0>>>(gb, HDIM, HID, MAN, DM2, 1, 1.f);
    }

    // --- WkM_h = Wk_h @ M (complex), [512,64] per head, z=16, BN=64 ---
    {
        GemmBatch gb{};
        for (int h = 0; h < HEADS; h++) {
            int z0 = 2 * h;
            gb.A1[z0] = rWk_re + h * HDIM; gb.B1[z0] = M_re;
            gb.A2[z0] = rWk_im + h * HDIM; gb.B2[z0] = M_imn;
            gb.C[z0]  = WkM_re + h * HDIM;
            gb.A1[z0+1] = rWk_re + h * HDIM; gb.B1[z0+1] = M_im;
            gb.A2[z0+1] = rWk_im + h * HDIM; gb.B2[z0+1] = M_re;
            gb.C[z0+1]  = WkM_im + h * HDIM;
        }
        gemm_tf32<0,1,1,64><<<dim3(1, HID/128, 16), tb, SM_T64>>>(gb, HDIM, HID, HDIM, HID, 1, 1.f);
    }

    // --- E_h = Wvm_h @ Wmi (complex), [512,64] per head, z=32, BN=64 ---
    {
        GemmBatch gb{};
        for (int h = 0; h < HEADS; h++) {
            int z0 = 2 * h;
            gb.A1[z0] = fv_re + h * MAN; gb.B1[z0] = rWmi_re;
            gb.A2[z0] = fv_im + h * MAN; gb.B2[z0] = rWmi_imn;
            gb.C[z0]  = E_re + h * HDIM;
            gb.A1[z0+1] = fv_re + h * MAN; gb.B1[z0+1] = rWmi_im;
            gb.A2[z0+1] = fv_im + h * MAN; gb.B2[z0+1] = rWmi_re;
            gb.C[z0+1]  = E_im + h * HDIM;
        }
        gemm_tf32<0,1,1,64><<<dim3(1, HID/128, 16), tb, SM_T64>>>(gb, MAN, DM2, HDIM, HID, 1, 1.f);
    }

    // --- q'/kM projections: z=4, [4096,512] @ [512,512] ---
    {
        GemmBatch gb{};
        const float* Bp[4] = {rWq_re, rWq_im, WkM_re, WkM_im};
        float* Cp[4] = {qre, qim, kre, kim};
        for (int i = 0; i < 4; i++) { gb.A1[i] = xn; gb.B1[i] = Bp[i]; gb.C[i] = Cp[i]; }
        gemm_tf32<0,0,1,128><<<dim3(HID/128, NROWS/128, 4), tb, SM_T0>>>(gb, HID, HID, HID, HID, 1, 1.f);
    }

    // --- scores: S_h = SCALE * (q're kM_re^T + q'im kM_im^T), K=64 x2, z=16 ---
    {
        GemmBatch gb{};
        for (int z = 0; z < BH; z++) {
            int b = z >> 3, h = z & 7;
            size_t off = (size_t)b * SEQ * HID + (size_t)h * HDIM;
            gb.A1[z] = qre + off; gb.B1[z] = kre + off;
            gb.A2[z] = qim + off; gb.B2[z] = kim + off;
            gb.C[z] = S + (size_t)z * SEQ * SEQ;
        }
        gemm_tf32<1,1,0,128><<<dim3(SEQ/128, SEQ/128, BH), tb, SM_T1>>>(gb, HDIM, HID, HID, SEQ, 1, SCALE);
    }

    softmax_kernel<<<dim3(SEQ, BH), 256>>>(S);

    // --- T = P @ xn : [2048,2048]@[2048,512] per bh, z=16 (rounded: feeds oh gemm) ---
    {
        GemmBatch gb{};
        for (int z = 0; z < BH; z++) {
            int b = z >> 3;
            gb.A1[z] = S + (size_t)z * SEQ * SEQ;
            gb.B1[z] = xn + (size_t)b * SEQ * HID;
            gb.C[z]  = T + (size_t)z * SEQ * HID;
        }
        gemm_tf32<0,0,1,128><<<dim3(HID/128, SEQ/128, BH), tb, SM_T0>>>(gb, SEQ, SEQ, HID, HID, 1, 1.f);
    }

    // --- oh: oh_re[.,h] = T_bh @ E_re_h, oh_im = T_bh @ E_im_h, z=32, BN=64 ---
    {
        GemmBatch gb{};
        for (int z = 0; z < BH; z++) {
            int b = z >> 3, h = z & 7;
            gb.A1[2*z]   = T + (size_t)z * SEQ * HID;
            gb.B1[2*z]   = E_re + h * HDIM;
            gb.C[2*z]    = oh_re + (size_t)b * SEQ * HID + h * HDIM;
            gb.A1[2*z+1] = T + (size_t)z * SEQ * HID;
            gb.B1[2*z+1] = E_im + h * HDIM;
            gb.C[2*z+1]  = oh_im + (size_t)b * SEQ * HID + h * HDIM;
        }
        gemm_tf32<0,0,1,64><<<dim3(1, SEQ/128, 32), tb, SM_T64>>>(gb, HID, HID, HID, HID, 1, 1.f);
    }

    // --- output projection: complex Wo, interleaved [.,512,2], z=2 ---
    {
        GemmBatch gb{};
        gb.A1[0] = oh_re; gb.B1[0] = rWo_re; gb.A2[0] = oh_im; gb.B2[0] = rWo_imn;
        gb.C[0] = out;
        gb.A1[1] = oh_re; gb.B1[1] = rWo_im; gb.A2[1] = oh_im; gb.B2[1] = rWo_re;
        gb.C[1] = out + 1;
        gemm_tf32<0,1,0,128><<<dim3(HID/128, NROWS/128, 2), tb, SM_T0>>>(gb, HID, HID, HID, 2*HID, 2, 1.f);
    }
}